// round 11
// baseline (speedup 1.0000x reference)
#include <cuda_runtime.h>
#include <cuda_bf16.h>
#include <cstdint>
#include <cmath>

#define LPN 4096
#define LHN 4096
#define DN  300
#define HN  512
#define DP  320          // DN padded to 32
#define D2P 608          // 2*DN padded to 32
#define NROWS_PAD 384    // DN padded for B-operand rows
#define M2  8192         // batched p+h rows

// ---------------- scratch (static device globals) ---------------------------
__device__ float g_emb2[M2 * DN];
__device__ float g_eik [LPN];
__device__ float g_ekj [LHN];
__device__ float g_part [64 * 4096];
__device__ float g_part2[64 * 4096];
__device__ float g_split[8 * LPN * DN];

__device__ __nv_bfloat16 g_emb2s_h[M2 * DP],  g_emb2s_l[M2 * DP];
__device__ __nv_bfloat16 g_ths_h [M2 * HN],   g_ths_l [M2 * HN];
__device__ __nv_bfloat16 g_fps_h [LPN * HN],  g_fps_l [LPN * HN];
__device__ __nv_bfloat16 g_fhTs_h[LHN * HN],  g_fhTs_l[LHN * HN];
__device__ __nv_bfloat16 g_Es_h [(long)LPN * LHN], g_Es_l [(long)LPN * LHN];
__device__ __nv_bfloat16 g_ETs_h[(long)LPN * LHN], g_ETs_l[(long)LPN * LHN];
__device__ __nv_bfloat16 g_hTs_h[NROWS_PAD * LHN], g_hTs_l[NROWS_PAD * LHN];
__device__ __nv_bfloat16 g_pTs_h[NROWS_PAD * LPN], g_pTs_l[NROWS_PAD * LPN];
__device__ __nv_bfloat16 g_xs_h [M2 * D2P],   g_xs_l [M2 * D2P];
__device__ __nv_bfloat16 g_Wa1s_h[HN * DP],   g_Wa1s_l[HN * DP];
__device__ __nv_bfloat16 g_Wa2s_h[HN * HN],   g_Wa2s_l[HN * HN];
__device__ __nv_bfloat16 g_Wc1s_h[HN * D2P],  g_Wc1s_l[HN * D2P];
__device__ __nv_bfloat16 g_Wc2s_h[HN * HN],   g_Wc2s_l[HN * HN];

// ---------------- PTX helpers ------------------------------------------------
__device__ __forceinline__ uint32_t smem_u32(const void* p) {
    uint32_t a;
    asm("{ .reg .u64 t; cvta.to.shared.u64 t, %1; cvt.u32.u64 %0, t; }" : "=r"(a) : "l"(p));
    return a;
}
__device__ __forceinline__ void ldsm4(uint32_t& r0, uint32_t& r1, uint32_t& r2,
                                      uint32_t& r3, uint32_t addr) {
    asm volatile("ldmatrix.sync.aligned.m8n8.x4.shared.b16 {%0,%1,%2,%3}, [%4];"
                 : "=r"(r0), "=r"(r1), "=r"(r2), "=r"(r3) : "r"(addr));
}
__device__ __forceinline__ void mma16816(float* c, const uint32_t* a,
                                         const uint32_t b0, const uint32_t b1) {
    asm volatile(
        "mma.sync.aligned.m16n8k16.row.col.f32.bf16.bf16.f32 "
        "{%0,%1,%2,%3}, {%4,%5,%6,%7}, {%8,%9}, {%0,%1,%2,%3};"
        : "+f"(c[0]), "+f"(c[1]), "+f"(c[2]), "+f"(c[3])
        : "r"(a[0]), "r"(a[1]), "r"(a[2]), "r"(a[3]), "r"(b0), "r"(b1));
}
__device__ __forceinline__ void cvt_split(float x, __nv_bfloat16& hi, __nv_bfloat16& lo) {
    hi = __float2bfloat16(x);
    lo = __float2bfloat16(x - __bfloat162float(hi));
}
__device__ __forceinline__ void cp16(uint32_t dst, const void* src) {
    asm volatile("cp.async.cg.shared.global [%0], [%1], 16;"
                 :: "r"(dst), "l"(__cvta_generic_to_global(src)));
}
__device__ __forceinline__ void cp_commit() {
    asm volatile("cp.async.commit_group;");
}
template <int NN> __device__ __forceinline__ void cp_wait() {
    asm volatile("cp.async.wait_group %0;" :: "n"(NN));
}

#define STAGE_BYTES 30720
#define NSTAGES 3

// ---------------- bf16x3 mma.sync SGEMM, 128x64 tile, 3-stage pipeline -------
// smem/stage: Ah 10240 | Al 10240 | Bh 5120 | Bl 5120 = 30720; 3 stages.
// ONE __syncthreads per chunk: with 3 stages, the stage written for chunk i+2
// was last read in chunk i-1, and the barrier at chunk i proves completion.
__global__ __launch_bounds__(256, 2)
void bgemm(const __nv_bfloat16* __restrict__ Agh, const __nv_bfloat16* __restrict__ Agl, long ldA,
           const __nv_bfloat16* __restrict__ Bgh, const __nv_bfloat16* __restrict__ Bgl, long ldB,
           const __nv_bfloat16* __restrict__ A2gh, const __nv_bfloat16* __restrict__ A2gl,
           const __nv_bfloat16* __restrict__ B2gh, const __nv_bfloat16* __restrict__ B2gl,
           int zSecond,
           const float* __restrict__ bias,
           float* __restrict__ C, long ldc, long sliceStride,
           __nv_bfloat16* __restrict__ Chi, __nv_bfloat16* __restrict__ Clo, long ldS,
           __nv_bfloat16* __restrict__ Th, __nv_bfloat16* __restrict__ Tl, long ldT,
           float* __restrict__ rowpart, float* __restrict__ colpart,
           int reshapeRow,
           int M, int N, int K, int kPerSlice, int relu) {
    extern __shared__ __align__(16) char smraw[];
    const int tid = threadIdx.x, lane = tid & 31, wid = tid >> 5;
    const int wm = wid >> 1, wn = wid & 1;          // 4 x 2 warps, warp tile 32x32
    const int m0 = blockIdx.y * 128, n0 = blockIdx.x * 64;
    const int zz = blockIdx.z;
    if (A2gh && zz >= zSecond) { Agh = A2gh; Agl = A2gl; Bgh = B2gh; Bgl = B2gl; }
    const int kbeg = (zz % zSecond) * kPerSlice;
    const int kend = min(K, kbeg + kPerSlice);
    const int nch = (kend - kbeg) >> 5;
    C += (long)zz * sliceStride;

    const uint32_t sb = smem_u32(smraw);

    float acc[2][4][4];
    #pragma unroll
    for (int i = 0; i < 2; i++)
        #pragma unroll
        for (int j = 0; j < 4; j++)
            #pragma unroll
            for (int e = 0; e < 4; e++) acc[i][j][e] = 0.f;

    const int lrow = (((lane >> 3) & 1) << 3) + (lane & 7);
    const int lcol = (lane >> 4) << 4;

    auto load_stage = [&](int st, int k0) {
        uint32_t sbase = sb + st * STAGE_BYTES;
        #pragma unroll
        for (int i = 0; i < 2; i++) {
            int c = tid + i * 256;          // 0..511 -> A rows
            int r = c >> 2, kq = c & 3;
            uint32_t dso = (uint32_t)(r * 80 + kq * 16);
            long ao = (long)(m0 + r) * ldA + k0 + kq * 8;
            cp16(sbase + dso,         Agh + ao);
            cp16(sbase + 10240 + dso, Agl + ao);
        }
        {
            int r = tid >> 2, kq = tid & 3; // 0..255 -> B rows (64)
            uint32_t dso = (uint32_t)(r * 80 + kq * 16);
            long bo = (long)(n0 + r) * ldB + k0 + kq * 8;
            cp16(sbase + 20480 + dso, Bgh + bo);
            cp16(sbase + 25600 + dso, Bgl + bo);
        }
    };

    // prologue: fill NSTAGES-1 stages
    load_stage(0, kbeg);
    cp_commit();
    if (nch > 1) { load_stage(1, kbeg + 32); cp_commit(); }

    int stage = 0;
    for (int i = 0; i < nch; i++) {
        if (i + 2 < nch) cp_wait<1>(); else cp_wait<0>();
        __syncthreads();                       // single barrier per chunk
        if (i + 2 < nch) {
            load_stage((stage + 2) % NSTAGES, kbeg + (i + 2) * 32);
            cp_commit();
        }

        const uint32_t aAh = sb + stage * STAGE_BYTES;
        const uint32_t aAl = aAh + 10240;
        const uint32_t aBh = aAh + 20480;
        const uint32_t aBl = aAh + 25600;

        #pragma unroll
        for (int s = 0; s < 2; s++) {
            const int sbyte = s * 32;
            uint32_t ah[2][4], al[2][4], bh[2][4];
            #pragma unroll
            for (int mf = 0; mf < 2; mf++) {
                int row = wm * 32 + mf * 16 + lrow;
                ldsm4(ah[mf][0], ah[mf][1], ah[mf][2], ah[mf][3],
                      aAh + row * 80 + lcol + sbyte);
                ldsm4(al[mf][0], al[mf][1], al[mf][2], al[mf][3],
                      aAl + row * 80 + lcol + sbyte);
            }
            #pragma unroll
            for (int nf = 0; nf < 2; nf++) {
                int row = wn * 32 + nf * 16 + lrow;
                ldsm4(bh[nf][0], bh[nf][1], bh[nf][2], bh[nf][3],
                      aBh + row * 80 + lcol + sbyte);
            }
            #pragma unroll
            for (int nf = 0; nf < 2; nf++)
                #pragma unroll
                for (int j = 0; j < 2; j++)
                    #pragma unroll
                    for (int mf = 0; mf < 2; mf++)
                        mma16816(acc[mf][nf * 2 + j], ah[mf], bh[nf][j], bh[nf][j + 2]);
            #pragma unroll
            for (int nf = 0; nf < 2; nf++)
                #pragma unroll
                for (int j = 0; j < 2; j++)
                    #pragma unroll
                    for (int mf = 0; mf < 2; mf++)
                        mma16816(acc[mf][nf * 2 + j], al[mf], bh[nf][j], bh[nf][j + 2]);
            #pragma unroll
            for (int nf = 0; nf < 2; nf++) {
                int row = wn * 32 + nf * 16 + lrow;
                uint32_t bl[4];
                ldsm4(bl[0], bl[1], bl[2], bl[3], aBl + row * 80 + lcol + sbyte);
                #pragma unroll
                for (int j = 0; j < 2; j++)
                    #pragma unroll
                    for (int mf = 0; mf < 2; mf++)
                        mma16816(acc[mf][nf * 2 + j], ah[mf], bl[j], bl[j + 2]);
            }
        }
        stage = (stage + 1) % NSTAGES;
    }
    __syncthreads();   // protect smem reuse in staging epilogue

    // ---- epilogue: bias/relu in-place ----
    const int tg = lane >> 2;
    const int tn = (lane & 3) << 1;
    if (bias || relu) {
        #pragma unroll
        for (int mf = 0; mf < 2; mf++)
            #pragma unroll
            for (int nfj = 0; nfj < 4; nfj++) {
                int n = n0 + (wn * 32 + nfj * 8 + tn);
                #pragma unroll
                for (int h2 = 0; h2 < 2; h2++) {
                    float vx = acc[mf][nfj][h2 * 2 + 0];
                    float vy = acc[mf][nfj][h2 * 2 + 1];
                    if (bias && n < N) { vx += bias[n]; vy += bias[n + 1]; }
                    if (relu) { vx = fmaxf(vx, 0.f); vy = fmaxf(vy, 0.f); }
                    acc[mf][nfj][h2 * 2 + 0] = vx;
                    acc[mf][nfj][h2 * 2 + 1] = vy;
                }
            }
    }

    const bool rsh = (reshapeRow >= 0);
    const bool isH = rsh && (m0 >= reshapeRow);

    if (C || (Chi && !isH)) {
        #pragma unroll
        for (int mf = 0; mf < 2; mf++) {
            #pragma unroll
            for (int h2 = 0; h2 < 2; h2++) {
                int m = m0 + wm * 32 + mf * 16 + h2 * 8 + tg;
                #pragma unroll
                for (int nfj = 0; nfj < 4; nfj++) {
                    int n = n0 + wn * 32 + nfj * 8 + tn;
                    if (n >= N) continue;
                    float2 v;
                    v.x = acc[mf][nfj][h2 * 2 + 0];
                    v.y = acc[mf][nfj][h2 * 2 + 1];
                    if (C) *(float2*)(C + (long)m * ldc + n) = v;
                    if (Chi && !isH) {
                        __nv_bfloat16 h0, l0, h1, l1;
                        cvt_split(v.x, h0, l0);
                        cvt_split(v.y, h1, l1);
                        long o = (long)m * ldS + n;
                        Chi[o] = h0; Chi[o + 1] = h1;
                        Clo[o] = l0; Clo[o + 1] = l1;
                    }
                }
            }
        }
    }

    const bool doStage = (Th && (!rsh || isH)) || rowpart || colpart;
    if (doStage) {
        float* ts = (float*)smraw;             // [64][129]
        #pragma unroll
        for (int mf = 0; mf < 2; mf++) {
            #pragma unroll
            for (int h2 = 0; h2 < 2; h2++) {
                int ml = wm * 32 + mf * 16 + h2 * 8 + tg;
                #pragma unroll
                for (int nfj = 0; nfj < 4; nfj++) {
                    int nl = wn * 32 + nfj * 8 + tn;
                    ts[(nl + 0) * 129 + ml] = acc[mf][nfj][h2 * 2 + 0];
                    ts[(nl + 1) * 129 + ml] = acc[mf][nfj][h2 * 2 + 1];
                }
            }
        }
        __syncthreads();
        if (tid < 128 && rowpart) {
            float s = 0.f;
            #pragma unroll 8
            for (int n = 0; n < 64; n++) s += ts[n * 129 + tid];
            rowpart[(long)blockIdx.x * M + m0 + tid] = s;
        }
        if (tid < 64 && colpart) {
            float s2 = 0.f;
            #pragma unroll 8
            for (int m = 0; m < 128; m++) s2 += ts[tid * 129 + m];
            colpart[(long)blockIdx.y * N + n0 + tid] = s2;
        }
        if (Th && (!rsh || isH)) {
            if (rsh) {
                long kb = (long)(m0 - reshapeRow) >> 3;
                for (int idx = tid; idx < 512; idx += 256) {
                    int r8 = idx >> 6, nl = idx & 63;
                    long j = (long)r8 * HN + n0 + nl;
                    __align__(16) __nv_bfloat16 hb[16], lb[16];
                    #pragma unroll
                    for (int q = 0; q < 16; q++) {
                        __nv_bfloat16 hi, lo;
                        cvt_split(ts[nl * 129 + r8 + 8 * q], hi, lo);
                        hb[q] = hi; lb[q] = lo;
                    }
                    long o = j * ldT + kb;
                    *(uint4*)(Th + o)     = *(uint4*)(hb);
                    *(uint4*)(Th + o + 8) = *(uint4*)(hb + 8);
                    *(uint4*)(Tl + o)     = *(uint4*)(lb);
                    *(uint4*)(Tl + o + 8) = *(uint4*)(lb + 8);
                }
            } else {
                for (int idx = tid; idx < 8192; idx += 256) {
                    int n = idx >> 7, m = idx & 127;
                    __nv_bfloat16 hi, lo;
                    cvt_split(ts[n * 129 + m], hi, lo);
                    long o = (long)(n0 + n) * ldT + m0 + m;
                    Th[o] = hi; Tl[o] = lo;
                }
            }
        }
    }
}

static const int BGEMM_SMEM = NSTAGES * STAGE_BYTES;

// ---------------- all 4 weight splits in ONE kernel ---------------------------
__global__ void split_weights_kernel(const float* __restrict__ Wa1, const float* __restrict__ Wa2,
                                     const float* __restrict__ Wc1, const float* __restrict__ Wc2,
                                     __nv_bfloat16* __restrict__ a1h, __nv_bfloat16* __restrict__ a1l,
                                     __nv_bfloat16* __restrict__ a2h, __nv_bfloat16* __restrict__ a2l,
                                     __nv_bfloat16* __restrict__ c1h, __nv_bfloat16* __restrict__ c1l,
                                     __nv_bfloat16* __restrict__ c2h, __nv_bfloat16* __restrict__ c2l) {
    const long s1 = (long)HN * DP, s2 = (long)HN * HN, s3 = (long)HN * D2P, s4 = (long)HN * HN;
    long i = (long)blockIdx.x * blockDim.x + threadIdx.x;
    const float* src; __nv_bfloat16 *dh, *dl; int K, Kpad; long li;
    if (i < s1)                { src = Wa1; dh = a1h; dl = a1l; K = DN;     Kpad = DP;  li = i; }
    else if (i < s1 + s2)      { src = Wa2; dh = a2h; dl = a2l; K = HN;     Kpad = HN;  li = i - s1; }
    else if (i < s1 + s2 + s3) { src = Wc1; dh = c1h; dl = c1l; K = 2 * DN; Kpad = D2P; li = i - s1 - s2; }
    else if (i < s1 + s2 + s3 + s4) { src = Wc2; dh = c2h; dl = c2l; K = HN; Kpad = HN; li = i - s1 - s2 - s3; }
    else return;
    int m = (int)(li / Kpad), k = (int)(li % Kpad);
    float v = (k < K) ? src[(long)m * K + k] : 0.f;
    __nv_bfloat16 hi, lo;
    cvt_split(v, hi, lo);
    dh[li] = hi; dl[li] = lo;
}

// ---------------- fused gather + fp32 + split-pad + xs fill -------------------
__global__ void gather_split_kernel(const float* __restrict__ emb,
                                    const int* __restrict__ p_idx,
                                    const int* __restrict__ h_idx,
                                    float* __restrict__ emb2,
                                    __nv_bfloat16* __restrict__ e_h,
                                    __nv_bfloat16* __restrict__ e_l,
                                    __nv_bfloat16* __restrict__ x_h,
                                    __nv_bfloat16* __restrict__ x_l) {
    int r = blockIdx.x;
    long src = (r < LPN) ? p_idx[r] : h_idx[r - LPN];
    const float* s = emb + src * (long)DN;
    for (int c = threadIdx.x; c < DP; c += blockDim.x) {
        float v = (c < DN) ? s[c] : 0.f;
        __nv_bfloat16 hi, lo;
        cvt_split(v, hi, lo);
        long eo = (long)r * DP + c;
        e_h[eo] = hi; e_l[eo] = lo;
        if (c < DN) {
            emb2[(long)r * DN + c] = v;
            long xo = (long)r * D2P + c;
            x_h[xo] = hi; x_l[xo] = lo;
        }
    }
    for (int c = 2 * DN + threadIdx.x; c < D2P; c += blockDim.x) {
        long xo = (long)r * D2P + c;
        x_h[xo] = __float2bfloat16(0.f);
        x_l[xo] = __float2bfloat16(0.f);
    }
}

// ---------------- transpose + split (dual-source via blockIdx.z) --------------
__global__ void transpose_split2_kernel(const float* __restrict__ srcA,
                                        __nv_bfloat16* __restrict__ dhA, __nv_bfloat16* __restrict__ dlA,
                                        const float* __restrict__ srcB,
                                        __nv_bfloat16* __restrict__ dhB, __nv_bfloat16* __restrict__ dlB,
                                        int R, int C, int dR) {
    const float* src = blockIdx.z ? srcB : srcA;
    __nv_bfloat16* dh = blockIdx.z ? dhB : dhA;
    __nv_bfloat16* dl = blockIdx.z ? dlB : dlA;
    __shared__ float tile[32][33];
    int c0 = blockIdx.x * 32, r0 = blockIdx.y * 32;
    int x = threadIdx.x, y = threadIdx.y;
    #pragma unroll
    for (int i = y; i < 32; i += 8) {
        int r = r0 + i, c = c0 + x;
        tile[i][x] = (r < R && c < C) ? src[(long)r * C + c] : 0.f;
    }
    __syncthreads();
    #pragma unroll
    for (int i = y; i < 32; i += 8) {
        int dr = c0 + i, dc = r0 + x;
        if (dr < dR && dc < R) {
            __nv_bfloat16 hi, lo;
            cvt_split(tile[x][i], hi, lo);
            dh[(long)dr * R + dc] = hi;
            dl[(long)dr * R + dc] = lo;
        }
    }
}

// ---------------- split-K reduce + rowdiv + fused concat, dual via grid.y -----
__global__ void splitk_concat2_kernel(const float* __restrict__ partA, const float* __restrict__ rdA,
                                      float* __restrict__ CA,
                                      const float* __restrict__ partB, const float* __restrict__ rdB,
                                      float* __restrict__ CB,
                                      __nv_bfloat16* __restrict__ xh, __nv_bfloat16* __restrict__ xl,
                                      int M, int N, int S) {
    const float* part = blockIdx.y ? partB : partA;
    const float* rowdiv = blockIdx.y ? rdB : rdA;
    float* C = blockIdx.y ? CB : CA;
    long xRowOff = blockIdx.y ? (long)M : 0;
    long i = (long)blockIdx.x * blockDim.x + threadIdx.x;
    long total = (long)M * N;
    if (i >= total) return;
    int m = (int)(i / N), n = (int)(i % N);
    float s = 0.f;
    for (int p = 0; p < S; p++) s += part[(long)p * total + i];
    float v = s / rowdiv[m];
    C[(long)m * N + n] = v;
    __nv_bfloat16 hi, lo;
    cvt_split(v, hi, lo);
    long o = (xRowOff + m) * (long)D2P + DN + n;
    xh[o] = hi; xl[o] = lo;
}

// ---------------- dual column reduce (independent P per source) ---------------
__global__ void colsum_reduce2_kernel(const float* __restrict__ partA, float* __restrict__ outA, int PA,
                                      const float* __restrict__ partB, float* __restrict__ outB, int PB,
                                      int C) {
    const float* part = blockIdx.y ? partB : partA;
    float* out = blockIdx.y ? outB : outA;
    int P = blockIdx.y ? PB : PA;
    int c = blockIdx.x * blockDim.x + threadIdx.x;
    if (c >= C) return;
    float s = 0.f;
    for (int p = 0; p < P; p++) s += part[(long)p * C + c];
    out[c] = s;
}

// ---------------- final MLP head + softmax -------------------------------------
__global__ void head_kernel(const float* __restrict__ v,
                            const float* __restrict__ Wg1, const float* __restrict__ bg1,
                            const float* __restrict__ Wg2, const float* __restrict__ bg2,
                            const float* __restrict__ Wg3, const float* __restrict__ bg3,
                            float* __restrict__ y) {
    __shared__ float sv[2 * HN];
    __shared__ float y1[HN];
    __shared__ float y2[HN];
    __shared__ float logit[3];
    int t = threadIdx.x;
    sv[t] = v[t];
    sv[t + HN] = v[t + HN];
    __syncthreads();
    {
        float acc = bg1[t];
        const float* w = Wg1 + (long)t * (2 * HN);
        for (int k = 0; k < 2 * HN; k++) acc += sv[k] * w[k];
        y1[t] = fmaxf(acc, 0.f);
    }
    __syncthreads();
    {
        float acc = bg2[t];
        const float* w = Wg2 + (long)t * HN;
        for (int k = 0; k < HN; k++) acc += y1[k] * w[k];
        y2[t] = fmaxf(acc, 0.f);
    }
    __syncthreads();
    if (t < 3) {
        float a = bg3[t];
        const float* w = Wg3 + (long)t * HN;
        for (int k = 0; k < HN; k++) a += y2[k] * w[k];
        logit[t] = a;
    }
    __syncthreads();
    if (t == 0) {
        float m = fmaxf(logit[0], fmaxf(logit[1], logit[2]));
        float e0 = expf(logit[0] - m), e1 = expf(logit[1] - m), e2 = expf(logit[2] - m);
        float s = e0 + e1 + e2;
        y[0] = e0 / s; y[1] = e1 / s; y[2] = e2 / s;
    }
}

// ---------------- host dispatch -----------------------------------------------
struct BArgs {
    const __nv_bfloat16 *Ah, *Al; long ldA;
    const __nv_bfloat16 *Bh, *Bl; long ldB;
    const __nv_bfloat16 *A2h = nullptr, *A2l = nullptr, *B2h = nullptr, *B2l = nullptr;
    const float* bias = nullptr;
    float* C = nullptr; long ldc = 0; long sliceStride = 0;
    __nv_bfloat16 *Chi = nullptr, *Clo = nullptr; long ldS = 0;
    __nv_bfloat16 *Th = nullptr, *Tl = nullptr; long ldT = 0;
    float *rowpart = nullptr, *colpart = nullptr;
    int reshapeRow = -1;
    int M, N, K, splits = 1, zTotal = 0, relu = 0;
};

static void launch_bgemm(const BArgs& a) {
    cudaFuncSetAttribute(bgemm, cudaFuncAttributeMaxDynamicSharedMemorySize, BGEMM_SMEM);
    int kps = (a.K + a.splits - 1) / a.splits;
    kps = ((kps + 31) / 32) * 32;
    int zt = a.zTotal ? a.zTotal : a.splits;
    dim3 grid((a.N + 63) / 64, a.M / 128, zt);
    bgemm<<<grid, 256, BGEMM_SMEM>>>(a.Ah, a.Al, a.ldA, a.Bh, a.Bl, a.ldB,
                                     a.A2h, a.A2l, a.B2h, a.B2l, a.splits,
                                     a.bias, a.C, a.ldc, a.sliceStride,
                                     a.Chi, a.Clo, a.ldS, a.Th, a.Tl, a.ldT,
                                     a.rowpart, a.colpart, a.reshapeRow,
                                     a.M, a.N, a.K, kps, a.relu);
}

#define GETSYM(var, sym) cudaGetSymbolAddress((void**)&var, sym)

extern "C" void kernel_launch(void* const* d_in, const int* in_sizes, int n_in,
                              void* d_out, int out_size) {
    const int*   p_idx = (const int*)  d_in[0];
    const int*   h_idx = (const int*)  d_in[1];
    const float* emb   = (const float*)d_in[2];
    const float* W_a1  = (const float*)d_in[3];
    const float* b_a1  = (const float*)d_in[4];
    const float* W_a2  = (const float*)d_in[5];
    const float* b_a2  = (const float*)d_in[6];
    const float* W_c1  = (const float*)d_in[7];
    const float* b_c1  = (const float*)d_in[8];
    const float* W_c2  = (const float*)d_in[9];
    const float* b_c2  = (const float*)d_in[10];
    const float* W_g1  = (const float*)d_in[11];
    const float* b_g1  = (const float*)d_in[12];
    const float* W_g2  = (const float*)d_in[13];
    const float* b_g2  = (const float*)d_in[14];
    const float* W_g3  = (const float*)d_in[15];
    const float* b_g3  = (const float*)d_in[16];

    float* out = (float*)d_out;
    const long E_OFF    = 0;
    const long BETA_OFF = (long)LPN * LHN;
    const long ALPHA_OFF= BETA_OFF + (long)LPN * DN;
    const long V1_OFF   = ALPHA_OFF + (long)LHN * DN;
    const long V2_OFF   = V1_OFF + HN;
    const long Y_OFF    = V2_OFF + HN;

    float *emb2, *eik, *ekj, *part, *part2, *split;
    GETSYM(emb2, g_emb2);
    GETSYM(eik, g_eik); GETSYM(ekj, g_ekj);
    GETSYM(part, g_part); GETSYM(part2, g_part2); GETSYM(split, g_split);

    __nv_bfloat16 *emb2s_h, *emb2s_l, *ths_h, *ths_l, *fps_h, *fps_l;
    __nv_bfloat16 *fhTs_h, *fhTs_l, *Es_h, *Es_l, *ETs_h, *ETs_l;
    __nv_bfloat16 *hTs_h, *hTs_l, *pTs_h, *pTs_l, *xs_h, *xs_l;
    __nv_bfloat16 *Wa1s_h, *Wa1s_l, *Wa2s_h, *Wa2s_l, *Wc1s_h, *Wc1s_l, *Wc2s_h, *Wc2s_l;
    GETSYM(emb2s_h, g_emb2s_h); GETSYM(emb2s_l, g_emb2s_l);
    GETSYM(ths_h, g_ths_h);     GETSYM(ths_l, g_ths_l);
    GETSYM(fps_h, g_fps_h);     GETSYM(fps_l, g_fps_l);
    GETSYM(fhTs_h, g_fhTs_h);   GETSYM(fhTs_l, g_fhTs_l);
    GETSYM(Es_h, g_Es_h);       GETSYM(Es_l, g_Es_l);
    GETSYM(ETs_h, g_ETs_h);     GETSYM(ETs_l, g_ETs_l);
    GETSYM(hTs_h, g_hTs_h);     GETSYM(hTs_l, g_hTs_l);
    GETSYM(pTs_h, g_pTs_h);     GETSYM(pTs_l, g_pTs_l);
    GETSYM(xs_h, g_xs_h);       GETSYM(xs_l, g_xs_l);
    GETSYM(Wa1s_h, g_Wa1s_h);   GETSYM(Wa1s_l, g_Wa1s_l);
    GETSYM(Wa2s_h, g_Wa2s_h);   GETSYM(Wa2s_l, g_Wa2s_l);
    GETSYM(Wc1s_h, g_Wc1s_h);   GETSYM(Wc1s_l, g_Wc1s_l);
    GETSYM(Wc2s_h, g_Wc2s_h);   GETSYM(Wc2s_l, g_Wc2s_l);

    // 0) all weight splits
    {
        long total = (long)HN * (DP + HN + D2P + HN);
        split_weights_kernel<<<(int)((total + 255) / 256), 256>>>(
            W_a1, W_a2, W_c1, W_c2,
            Wa1s_h, Wa1s_l, Wa2s_h, Wa2s_l, Wc1s_h, Wc1s_l, Wc2s_h, Wc2s_l);
    }

    // 1) fused gather + splits + xs fill
    gather_split_kernel<<<M2, 128>>>(emb, p_idx, h_idx, emb2,
                                     emb2s_h, emb2s_l, xs_h, xs_l);

    // 2) attend1 (batched p+h)
    {
        BArgs a{emb2s_h, emb2s_l, DP, Wa1s_h, Wa1s_l, DP};
        a.bias = b_a1; a.Chi = ths_h; a.Clo = ths_l; a.ldS = HN;
        a.M = M2; a.N = HN; a.K = DP; a.relu = 1;
        launch_bgemm(a);
    }
    // 3) attend2 with fused reshape-transpose
    {
        BArgs a{ths_h, ths_l, HN, Wa2s_h, Wa2s_l, HN};
        a.bias = b_a2;
        a.Chi = fps_h; a.Clo = fps_l; a.ldS = HN;
        a.Th = fhTs_h; a.Tl = fhTs_l; a.ldT = HN;
        a.reshapeRow = LPN;
        a.M = M2; a.N = HN; a.K = HN; a.relu = 1;
        launch_bgemm(a);
    }

    // 4) E GEMM with fused split + transposed split + row/col partials
    {
        BArgs a{fps_h, fps_l, HN, fhTs_h, fhTs_l, HN};
        a.C = out + E_OFF; a.ldc = LHN;
        a.Chi = Es_h; a.Clo = Es_l; a.ldS = LHN;
        a.Th = ETs_h; a.Tl = ETs_l; a.ldT = LHN;
        a.rowpart = part; a.colpart = part2;
        a.M = LPN; a.N = LHN; a.K = HN;
        launch_bgemm(a);
    }
    {
        dim3 g((LPN + 255) / 256, 2);
        colsum_reduce2_kernel<<<g, 256>>>(part, eik, 64, part2, ekj, 32, LPN);
    }

    // 5) embedding transposes for beta/alpha B-operands
    {
        dim3 b(32, 8);
        dim3 g((NROWS_PAD + 31) / 32, (LPN + 31) / 32, 2);
        transpose_split2_kernel<<<g, b>>>(emb2, pTs_h, pTs_l,
                                          emb2 + (long)LPN * DN, hTs_h, hTs_l,
                                          LPN, DN, NROWS_PAD);
    }

    // 6) beta & alpha in ONE launch, split-K x4 each
    {
        BArgs a{Es_h, Es_l, LHN, hTs_h, hTs_l, LHN};
        a.A2h = ETs_h; a.A2l = ETs_l; a.B2h = pTs_h; a.B2l = pTs_l;
        a.C = split; a.ldc = DN; a.sliceStride = (long)LPN * DN;
        a.M = LPN; a.N = DN; a.K = LHN; a.splits = 4; a.zTotal = 8;
        launch_bgemm(a);
    }
    {
        dim3 g((int)(((long)LPN * DN + 255) / 256), 2);
        splitk_concat2_kernel<<<g, 256>>>(split, eik, out + BETA_OFF,
                                          split + 4 * (long)LPN * DN, ekj, out + ALPHA_OFF,
                                          xs_h, xs_l, LPN, DN, 4);
    }

    // 7) comp (batched), colsums fused into comp2
    {
        BArgs a{xs_h, xs_l, D2P, Wc1s_h, Wc1s_l, D2P};
        a.bias = b_c1; a.Chi = ths_h; a.Clo = ths_l; a.ldS = HN;
        a.M = M2; a.N = HN; a.K = D2P; a.relu = 1;
        launch_bgemm(a);
    }
    {
        BArgs a{ths_h, ths_l, HN, Wc2s_h, Wc2s_l, HN};
        a.bias = b_c2; a.colpart = part;
        a.M = M2; a.N = HN; a.K = HN; a.relu = 1;
        launch_bgemm(a);
    }
    {
        dim3 g((HN + 255) / 256, 2);
        colsum_reduce2_kernel<<<g, 256>>>(part, out + V1_OFF, 32,
                                          part + 32 * HN, out + V2_OFF, 32, HN);
    }

    // 8) head
    head_kernel<<<1, HN>>>(out + V1_OFF, W_g1, b_g1, W_g2, b_g2, W_g3, b_g3, out + Y_OFF);

    (void)in_sizes; (void)n_in; (void)out_size;
}

// round 12
// speedup vs baseline: 1.1115x; 1.1115x over previous
#include <cuda_runtime.h>
#include <cuda_bf16.h>
#include <cstdint>
#include <cmath>

#define LPN 4096
#define LHN 4096
#define DN  300
#define HN  512
#define DP  320          // DN padded to 32
#define D2P 608          // 2*DN padded to 32
#define NROWS_PAD 384    // DN padded for B-operand rows
#define M2  8192         // batched p+h rows

// ---------------- scratch (static device globals) ---------------------------
__device__ float g_emb2[M2 * DN];
__device__ float g_eik [LPN];
__device__ float g_ekj [LHN];
__device__ float g_part [64 * 4096];
__device__ float g_part2[64 * 4096];
__device__ float g_split[8 * LPN * DN];

__device__ __nv_bfloat16 g_emb2s_h[M2 * DP],  g_emb2s_l[M2 * DP];
__device__ __nv_bfloat16 g_ths_h [M2 * HN],   g_ths_l [M2 * HN];
__device__ __nv_bfloat16 g_fps_h [LPN * HN],  g_fps_l [LPN * HN];
__device__ __nv_bfloat16 g_fhTs_h[LHN * HN],  g_fhTs_l[LHN * HN];
__device__ __nv_bfloat16 g_Es_h [(long)LPN * LHN], g_Es_l [(long)LPN * LHN];
__device__ __nv_bfloat16 g_ETs_h[(long)LPN * LHN], g_ETs_l[(long)LPN * LHN];
__device__ __nv_bfloat16 g_hTs_h[NROWS_PAD * LHN], g_hTs_l[NROWS_PAD * LHN];
__device__ __nv_bfloat16 g_pTs_h[NROWS_PAD * LPN], g_pTs_l[NROWS_PAD * LPN];
__device__ __nv_bfloat16 g_xs_h [M2 * D2P],   g_xs_l [M2 * D2P];
__device__ __nv_bfloat16 g_Wa1s_h[HN * DP],   g_Wa1s_l[HN * DP];
__device__ __nv_bfloat16 g_Wa2s_h[HN * HN],   g_Wa2s_l[HN * HN];
__device__ __nv_bfloat16 g_Wc1s_h[HN * D2P],  g_Wc1s_l[HN * D2P];
__device__ __nv_bfloat16 g_Wc2s_h[HN * HN],   g_Wc2s_l[HN * HN];

// ---------------- PTX helpers ------------------------------------------------
__device__ __forceinline__ uint32_t smem_u32(const void* p) {
    uint32_t a;
    asm("{ .reg .u64 t; cvta.to.shared.u64 t, %1; cvt.u32.u64 %0, t; }" : "=r"(a) : "l"(p));
    return a;
}
__device__ __forceinline__ void ldsm4(uint32_t& r0, uint32_t& r1, uint32_t& r2,
                                      uint32_t& r3, uint32_t addr) {
    asm volatile("ldmatrix.sync.aligned.m8n8.x4.shared.b16 {%0,%1,%2,%3}, [%4];"
                 : "=r"(r0), "=r"(r1), "=r"(r2), "=r"(r3) : "r"(addr));
}
__device__ __forceinline__ void mma16816(float* c, const uint32_t* a,
                                         const uint32_t b0, const uint32_t b1) {
    asm volatile(
        "mma.sync.aligned.m16n8k16.row.col.f32.bf16.bf16.f32 "
        "{%0,%1,%2,%3}, {%4,%5,%6,%7}, {%8,%9}, {%0,%1,%2,%3};"
        : "+f"(c[0]), "+f"(c[1]), "+f"(c[2]), "+f"(c[3])
        : "r"(a[0]), "r"(a[1]), "r"(a[2]), "r"(a[3]), "r"(b0), "r"(b1));
}
__device__ __forceinline__ void cvt_split(float x, __nv_bfloat16& hi, __nv_bfloat16& lo) {
    hi = __float2bfloat16(x);
    lo = __float2bfloat16(x - __bfloat162float(hi));
}
__device__ __forceinline__ uint32_t pack_bf2(__nv_bfloat16 a, __nv_bfloat16 b) {
    return (uint32_t)__bfloat16_as_ushort(a) | ((uint32_t)__bfloat16_as_ushort(b) << 16);
}
__device__ __forceinline__ void cp16(uint32_t dst, const void* src) {
    asm volatile("cp.async.cg.shared.global [%0], [%1], 16;"
                 :: "r"(dst), "l"(__cvta_generic_to_global(src)));
}
__device__ __forceinline__ void cp_commit() {
    asm volatile("cp.async.commit_group;");
}
template <int NN> __device__ __forceinline__ void cp_wait() {
    asm volatile("cp.async.wait_group %0;" :: "n"(NN));
}

#define STAGE_BYTES 30720

// ---------------- bf16x3 mma.sync SGEMM, 128x64 tile, 2-stage, 1 bar/chunk ---
// smem/stage: Ah 10240 | Al 10240 | Bh 5120 | Bl 5120 = 30720; 2 stages.
// Single barrier per chunk: the load for chunk i+1 targets stage (i-1)&1,
// fully read before all warps reached the barrier at the top of chunk i.
__global__ __launch_bounds__(256, 3)
void bgemm(const __nv_bfloat16* __restrict__ Agh, const __nv_bfloat16* __restrict__ Agl, long ldA,
           const __nv_bfloat16* __restrict__ Bgh, const __nv_bfloat16* __restrict__ Bgl, long ldB,
           const __nv_bfloat16* __restrict__ A2gh, const __nv_bfloat16* __restrict__ A2gl,
           const __nv_bfloat16* __restrict__ B2gh, const __nv_bfloat16* __restrict__ B2gl,
           int zSecond,
           const float* __restrict__ bias,
           float* __restrict__ C, long ldc, long sliceStride,
           __nv_bfloat16* __restrict__ Chi, __nv_bfloat16* __restrict__ Clo, long ldS,
           __nv_bfloat16* __restrict__ Th, __nv_bfloat16* __restrict__ Tl, long ldT,
           float* __restrict__ rowpart, float* __restrict__ colpart,
           int reshapeRow,
           int M, int N, int K, int kPerSlice, int relu) {
    extern __shared__ __align__(16) char smraw[];
    const int tid = threadIdx.x, lane = tid & 31, wid = tid >> 5;
    const int wm = wid >> 1, wn = wid & 1;          // 4 x 2 warps, warp tile 32x32
    const int m0 = blockIdx.y * 128, n0 = blockIdx.x * 64;
    const int zz = blockIdx.z;
    if (A2gh && zz >= zSecond) { Agh = A2gh; Agl = A2gl; Bgh = B2gh; Bgl = B2gl; }
    const int kbeg = (zz % zSecond) * kPerSlice;
    const int kend = min(K, kbeg + kPerSlice);
    const int nch = (kend - kbeg) >> 5;
    C += (long)zz * sliceStride;

    const uint32_t sb = smem_u32(smraw);

    float acc[2][4][4];
    #pragma unroll
    for (int i = 0; i < 2; i++)
        #pragma unroll
        for (int j = 0; j < 4; j++)
            #pragma unroll
            for (int e = 0; e < 4; e++) acc[i][j][e] = 0.f;

    const int lrow = (((lane >> 3) & 1) << 3) + (lane & 7);
    const int lcol = (lane >> 4) << 4;

    auto load_stage = [&](int st, int k0) {
        uint32_t sbase = sb + st * STAGE_BYTES;
        #pragma unroll
        for (int i = 0; i < 2; i++) {
            int c = tid + i * 256;          // 0..511 -> A rows
            int r = c >> 2, kq = c & 3;
            uint32_t dso = (uint32_t)(r * 80 + kq * 16);
            long ao = (long)(m0 + r) * ldA + k0 + kq * 8;
            cp16(sbase + dso,         Agh + ao);
            cp16(sbase + 10240 + dso, Agl + ao);
        }
        {
            int r = tid >> 2, kq = tid & 3; // 0..255 -> B rows (64)
            uint32_t dso = (uint32_t)(r * 80 + kq * 16);
            long bo = (long)(n0 + r) * ldB + k0 + kq * 8;
            cp16(sbase + 20480 + dso, Bgh + bo);
            cp16(sbase + 25600 + dso, Bgl + bo);
        }
    };

    load_stage(0, kbeg);
    cp_commit();

    int stage = 0;
    for (int i = 0; i < nch; i++) {
        cp_wait<0>();
        __syncthreads();                       // single barrier per chunk
        if (i + 1 < nch) {
            load_stage(stage ^ 1, kbeg + (i + 1) * 32);
            cp_commit();
        }

        const uint32_t aAh = sb + stage * STAGE_BYTES;
        const uint32_t aAl = aAh + 10240;
        const uint32_t aBh = aAh + 20480;
        const uint32_t aBl = aAh + 25600;

        #pragma unroll
        for (int s = 0; s < 2; s++) {
            const int sbyte = s * 32;
            uint32_t ah[2][4], al[2][4], bh[2][4];
            #pragma unroll
            for (int mf = 0; mf < 2; mf++) {
                int row = wm * 32 + mf * 16 + lrow;
                ldsm4(ah[mf][0], ah[mf][1], ah[mf][2], ah[mf][3],
                      aAh + row * 80 + lcol + sbyte);
                ldsm4(al[mf][0], al[mf][1], al[mf][2], al[mf][3],
                      aAl + row * 80 + lcol + sbyte);
            }
            #pragma unroll
            for (int nf = 0; nf < 2; nf++) {
                int row = wn * 32 + nf * 16 + lrow;
                ldsm4(bh[nf][0], bh[nf][1], bh[nf][2], bh[nf][3],
                      aBh + row * 80 + lcol + sbyte);
            }
            #pragma unroll
            for (int nf = 0; nf < 2; nf++)
                #pragma unroll
                for (int j = 0; j < 2; j++)
                    #pragma unroll
                    for (int mf = 0; mf < 2; mf++)
                        mma16816(acc[mf][nf * 2 + j], ah[mf], bh[nf][j], bh[nf][j + 2]);
            #pragma unroll
            for (int nf = 0; nf < 2; nf++)
                #pragma unroll
                for (int j = 0; j < 2; j++)
                    #pragma unroll
                    for (int mf = 0; mf < 2; mf++)
                        mma16816(acc[mf][nf * 2 + j], al[mf], bh[nf][j], bh[nf][j + 2]);
            #pragma unroll
            for (int nf = 0; nf < 2; nf++) {
                int row = wn * 32 + nf * 16 + lrow;
                uint32_t bl[4];
                ldsm4(bl[0], bl[1], bl[2], bl[3], aBl + row * 80 + lcol + sbyte);
                #pragma unroll
                for (int j = 0; j < 2; j++)
                    #pragma unroll
                    for (int mf = 0; mf < 2; mf++)
                        mma16816(acc[mf][nf * 2 + j], ah[mf], bl[j], bl[j + 2]);
            }
        }
        stage ^= 1;
    }
    __syncthreads();   // protect smem reuse in staging epilogue

    // ---- epilogue: bias/relu in-place ----
    const int tg = lane >> 2;
    const int tn = (lane & 3) << 1;
    if (bias || relu) {
        #pragma unroll
        for (int mf = 0; mf < 2; mf++)
            #pragma unroll
            for (int nfj = 0; nfj < 4; nfj++) {
                int n = n0 + (wn * 32 + nfj * 8 + tn);
                #pragma unroll
                for (int h2 = 0; h2 < 2; h2++) {
                    float vx = acc[mf][nfj][h2 * 2 + 0];
                    float vy = acc[mf][nfj][h2 * 2 + 1];
                    if (bias && n < N) { vx += bias[n]; vy += bias[n + 1]; }
                    if (relu) { vx = fmaxf(vx, 0.f); vy = fmaxf(vy, 0.f); }
                    acc[mf][nfj][h2 * 2 + 0] = vx;
                    acc[mf][nfj][h2 * 2 + 1] = vy;
                }
            }
    }

    const bool rsh = (reshapeRow >= 0);
    const bool isH = rsh && (m0 >= reshapeRow);

    if (C || (Chi && !isH)) {
        #pragma unroll
        for (int mf = 0; mf < 2; mf++) {
            #pragma unroll
            for (int h2 = 0; h2 < 2; h2++) {
                int m = m0 + wm * 32 + mf * 16 + h2 * 8 + tg;
                #pragma unroll
                for (int nfj = 0; nfj < 4; nfj++) {
                    int n = n0 + wn * 32 + nfj * 8 + tn;
                    if (n >= N) continue;
                    float2 v;
                    v.x = acc[mf][nfj][h2 * 2 + 0];
                    v.y = acc[mf][nfj][h2 * 2 + 1];
                    if (C) *(float2*)(C + (long)m * ldc + n) = v;
                    if (Chi && !isH) {
                        __nv_bfloat16 h0, l0, h1, l1;
                        cvt_split(v.x, h0, l0);
                        cvt_split(v.y, h1, l1);
                        long o = (long)m * ldS + n;
                        *(uint32_t*)(Chi + o) = pack_bf2(h0, h1);
                        *(uint32_t*)(Clo + o) = pack_bf2(l0, l1);
                    }
                }
            }
        }
    }

    const bool doStage = (Th && (!rsh || isH)) || rowpart || colpart;
    if (doStage) {
        float* ts = (float*)smraw;             // [64][129]
        #pragma unroll
        for (int mf = 0; mf < 2; mf++) {
            #pragma unroll
            for (int h2 = 0; h2 < 2; h2++) {
                int ml = wm * 32 + mf * 16 + h2 * 8 + tg;
                #pragma unroll
                for (int nfj = 0; nfj < 4; nfj++) {
                    int nl = wn * 32 + nfj * 8 + tn;
                    ts[(nl + 0) * 129 + ml] = acc[mf][nfj][h2 * 2 + 0];
                    ts[(nl + 1) * 129 + ml] = acc[mf][nfj][h2 * 2 + 1];
                }
            }
        }
        __syncthreads();
        if (tid < 128 && rowpart) {
            float s = 0.f;
            #pragma unroll 8
            for (int n = 0; n < 64; n++) s += ts[n * 129 + tid];
            rowpart[(long)blockIdx.x * M + m0 + tid] = s;
        }
        if (tid < 64 && colpart) {
            float s2 = 0.f;
            #pragma unroll 8
            for (int m = 0; m < 128; m++) s2 += ts[tid * 129 + m];
            colpart[(long)blockIdx.y * N + n0 + tid] = s2;
        }
        if (Th && (!rsh || isH)) {
            if (rsh) {
                long kb = (long)(m0 - reshapeRow) >> 3;
                for (int idx = tid; idx < 512; idx += 256) {
                    int r8 = idx >> 6, nl = idx & 63;
                    long j = (long)r8 * HN + n0 + nl;
                    __align__(16) __nv_bfloat16 hb[16], lb[16];
                    #pragma unroll
                    for (int q = 0; q < 16; q++) {
                        __nv_bfloat16 hi, lo;
                        cvt_split(ts[nl * 129 + r8 + 8 * q], hi, lo);
                        hb[q] = hi; lb[q] = lo;
                    }
                    long o = j * ldT + kb;
                    *(uint4*)(Th + o)     = *(uint4*)(hb);
                    *(uint4*)(Th + o + 8) = *(uint4*)(hb + 8);
                    *(uint4*)(Tl + o)     = *(uint4*)(lb);
                    *(uint4*)(Tl + o + 8) = *(uint4*)(lb + 8);
                }
            } else {
                for (int idx = tid; idx < 4096; idx += 256) {
                    int n = idx >> 6, m2 = (idx & 63) << 1;
                    __nv_bfloat16 h0, l0, h1, l1;
                    cvt_split(ts[n * 129 + m2], h0, l0);
                    cvt_split(ts[n * 129 + m2 + 1], h1, l1);
                    long o = (long)(n0 + n) * ldT + m0 + m2;
                    *(uint32_t*)(Th + o) = pack_bf2(h0, h1);
                    *(uint32_t*)(Tl + o) = pack_bf2(l0, l1);
                }
            }
        }
    }
}

static const int BGEMM_SMEM = 2 * STAGE_BYTES;

// ---------------- all 4 weight splits in ONE kernel ---------------------------
__global__ void split_weights_kernel(const float* __restrict__ Wa1, const float* __restrict__ Wa2,
                                     const float* __restrict__ Wc1, const float* __restrict__ Wc2,
                                     __nv_bfloat16* __restrict__ a1h, __nv_bfloat16* __restrict__ a1l,
                                     __nv_bfloat16* __restrict__ a2h, __nv_bfloat16* __restrict__ a2l,
                                     __nv_bfloat16* __restrict__ c1h, __nv_bfloat16* __restrict__ c1l,
                                     __nv_bfloat16* __restrict__ c2h, __nv_bfloat16* __restrict__ c2l) {
    const long s1 = (long)HN * DP, s2 = (long)HN * HN, s3 = (long)HN * D2P, s4 = (long)HN * HN;
    long i = (long)blockIdx.x * blockDim.x + threadIdx.x;
    const float* src; __nv_bfloat16 *dh, *dl; int K, Kpad; long li;
    if (i < s1)                { src = Wa1; dh = a1h; dl = a1l; K = DN;     Kpad = DP;  li = i; }
    else if (i < s1 + s2)      { src = Wa2; dh = a2h; dl = a2l; K = HN;     Kpad = HN;  li = i - s1; }
    else if (i < s1 + s2 + s3) { src = Wc1; dh = c1h; dl = c1l; K = 2 * DN; Kpad = D2P; li = i - s1 - s2; }
    else if (i < s1 + s2 + s3 + s4) { src = Wc2; dh = c2h; dl = c2l; K = HN; Kpad = HN; li = i - s1 - s2 - s3; }
    else return;
    int m = (int)(li / Kpad), k = (int)(li % Kpad);
    float v = (k < K) ? src[(long)m * K + k] : 0.f;
    __nv_bfloat16 hi, lo;
    cvt_split(v, hi, lo);
    dh[li] = hi; dl[li] = lo;
}

// ---------------- fused gather + fp32 + split-pad + xs fill -------------------
__global__ void gather_split_kernel(const float* __restrict__ emb,
                                    const int* __restrict__ p_idx,
                                    const int* __restrict__ h_idx,
                                    float* __restrict__ emb2,
                                    __nv_bfloat16* __restrict__ e_h,
                                    __nv_bfloat16* __restrict__ e_l,
                                    __nv_bfloat16* __restrict__ x_h,
                                    __nv_bfloat16* __restrict__ x_l) {
    int r = blockIdx.x;
    long src = (r < LPN) ? p_idx[r] : h_idx[r - LPN];
    const float* s = emb + src * (long)DN;
    for (int c = threadIdx.x; c < DP; c += blockDim.x) {
        float v = (c < DN) ? s[c] : 0.f;
        __nv_bfloat16 hi, lo;
        cvt_split(v, hi, lo);
        long eo = (long)r * DP + c;
        e_h[eo] = hi; e_l[eo] = lo;
        if (c < DN) {
            emb2[(long)r * DN + c] = v;
            long xo = (long)r * D2P + c;
            x_h[xo] = hi; x_l[xo] = lo;
        }
    }
    for (int c = 2 * DN + threadIdx.x; c < D2P; c += blockDim.x) {
        long xo = (long)r * D2P + c;
        x_h[xo] = __float2bfloat16(0.f);
        x_l[xo] = __float2bfloat16(0.f);
    }
}

// ---------------- transpose + split (dual-source via blockIdx.z) --------------
__global__ void transpose_split2_kernel(const float* __restrict__ srcA,
                                        __nv_bfloat16* __restrict__ dhA, __nv_bfloat16* __restrict__ dlA,
                                        const float* __restrict__ srcB,
                                        __nv_bfloat16* __restrict__ dhB, __nv_bfloat16* __restrict__ dlB,
                                        int R, int C, int dR) {
    const float* src = blockIdx.z ? srcB : srcA;
    __nv_bfloat16* dh = blockIdx.z ? dhB : dhA;
    __nv_bfloat16* dl = blockIdx.z ? dlB : dlA;
    __shared__ float tile[32][33];
    int c0 = blockIdx.x * 32, r0 = blockIdx.y * 32;
    int x = threadIdx.x, y = threadIdx.y;
    #pragma unroll
    for (int i = y; i < 32; i += 8) {
        int r = r0 + i, c = c0 + x;
        tile[i][x] = (r < R && c < C) ? src[(long)r * C + c] : 0.f;
    }
    __syncthreads();
    #pragma unroll
    for (int i = y; i < 32; i += 8) {
        int dr = c0 + i, dc = r0 + x;
        if (dr < dR && dc < R) {
            __nv_bfloat16 hi, lo;
            cvt_split(tile[x][i], hi, lo);
            dh[(long)dr * R + dc] = hi;
            dl[(long)dr * R + dc] = lo;
        }
    }
}

// ---------------- split-K reduce + rowdiv + fused concat, dual via grid.y -----
__global__ void splitk_concat2_kernel(const float* __restrict__ partA, const float* __restrict__ rdA,
                                      float* __restrict__ CA,
                                      const float* __restrict__ partB, const float* __restrict__ rdB,
                                      float* __restrict__ CB,
                                      __nv_bfloat16* __restrict__ xh, __nv_bfloat16* __restrict__ xl,
                                      int M, int N, int S) {
    const float* part = blockIdx.y ? partB : partA;
    const float* rowdiv = blockIdx.y ? rdB : rdA;
    float* C = blockIdx.y ? CB : CA;
    long xRowOff = blockIdx.y ? (long)M : 0;
    long i = (long)blockIdx.x * blockDim.x + threadIdx.x;
    long total = (long)M * N;
    if (i >= total) return;
    int m = (int)(i / N), n = (int)(i % N);
    float s = 0.f;
    for (int p = 0; p < S; p++) s += part[(long)p * total + i];
    float v = s / rowdiv[m];
    C[(long)m * N + n] = v;
    __nv_bfloat16 hi, lo;
    cvt_split(v, hi, lo);
    long o = (xRowOff + m) * (long)D2P + DN + n;
    xh[o] = hi; xl[o] = lo;
}

// ---------------- dual column reduce (independent P per source) ---------------
__global__ void colsum_reduce2_kernel(const float* __restrict__ partA, float* __restrict__ outA, int PA,
                                      const float* __restrict__ partB, float* __restrict__ outB, int PB,
                                      int C) {
    const float* part = blockIdx.y ? partB : partA;
    float* out = blockIdx.y ? outB : outA;
    int P = blockIdx.y ? PB : PA;
    int c = blockIdx.x * blockDim.x + threadIdx.x;
    if (c >= C) return;
    float s = 0.f;
    for (int p = 0; p < P; p++) s += part[(long)p * C + c];
    out[c] = s;
}

// ---------------- final MLP head + softmax -------------------------------------
__global__ void head_kernel(const float* __restrict__ v,
                            const float* __restrict__ Wg1, const float* __restrict__ bg1,
                            const float* __restrict__ Wg2, const float* __restrict__ bg2,
                            const float* __restrict__ Wg3, const float* __restrict__ bg3,
                            float* __restrict__ y) {
    __shared__ float sv[2 * HN];
    __shared__ float y1[HN];
    __shared__ float y2[HN];
    __shared__ float logit[3];
    int t = threadIdx.x;
    sv[t] = v[t];
    sv[t + HN] = v[t + HN];
    __syncthreads();
    {
        float acc = bg1[t];
        const float* w = Wg1 + (long)t * (2 * HN);
        for (int k = 0; k < 2 * HN; k++) acc += sv[k] * w[k];
        y1[t] = fmaxf(acc, 0.f);
    }
    __syncthreads();
    {
        float acc = bg2[t];
        const float* w = Wg2 + (long)t * HN;
        for (int k = 0; k < HN; k++) acc += y1[k] * w[k];
        y2[t] = fmaxf(acc, 0.f);
    }
    __syncthreads();
    if (t < 3) {
        float a = bg3[t];
        const float* w = Wg3 + (long)t * HN;
        for (int k = 0; k < HN; k++) a += y2[k] * w[k];
        logit[t] = a;
    }
    __syncthreads();
    if (t == 0) {
        float m = fmaxf(logit[0], fmaxf(logit[1], logit[2]));
        float e0 = expf(logit[0] - m), e1 = expf(logit[1] - m), e2 = expf(logit[2] - m);
        float s = e0 + e1 + e2;
        y[0] = e0 / s; y[1] = e1 / s; y[2] = e2 / s;
    }
}

// ---------------- host dispatch -----------------------------------------------
struct BArgs {
    const __nv_bfloat16 *Ah, *Al; long ldA;
    const __nv_bfloat16 *Bh, *Bl; long ldB;
    const __nv_bfloat16 *A2h = nullptr, *A2l = nullptr, *B2h = nullptr, *B2l = nullptr;
    const float* bias = nullptr;
    float* C = nullptr; long ldc = 0; long sliceStride = 0;
    __nv_bfloat16 *Chi = nullptr, *Clo = nullptr; long ldS = 0;
    __nv_bfloat16 *Th = nullptr, *Tl = nullptr; long ldT = 0;
    float *rowpart = nullptr, *colpart = nullptr;
    int reshapeRow = -1;
    int M, N, K, splits = 1, zTotal = 0, relu = 0;
};

static void launch_bgemm(const BArgs& a) {
    cudaFuncSetAttribute(bgemm, cudaFuncAttributeMaxDynamicSharedMemorySize, BGEMM_SMEM);
    int kps = (a.K + a.splits - 1) / a.splits;
    kps = ((kps + 31) / 32) * 32;
    int zt = a.zTotal ? a.zTotal : a.splits;
    dim3 grid((a.N + 63) / 64, a.M / 128, zt);
    bgemm<<<grid, 256, BGEMM_SMEM>>>(a.Ah, a.Al, a.ldA, a.Bh, a.Bl, a.ldB,
                                     a.A2h, a.A2l, a.B2h, a.B2l, a.splits,
                                     a.bias, a.C, a.ldc, a.sliceStride,
                                     a.Chi, a.Clo, a.ldS, a.Th, a.Tl, a.ldT,
                                     a.rowpart, a.colpart, a.reshapeRow,
                                     a.M, a.N, a.K, kps, a.relu);
}

#define GETSYM(var, sym) cudaGetSymbolAddress((void**)&var, sym)

extern "C" void kernel_launch(void* const* d_in, const int* in_sizes, int n_in,
                              void* d_out, int out_size) {
    const int*   p_idx = (const int*)  d_in[0];
    const int*   h_idx = (const int*)  d_in[1];
    const float* emb   = (const float*)d_in[2];
    const float* W_a1  = (const float*)d_in[3];
    const float* b_a1  = (const float*)d_in[4];
    const float* W_a2  = (const float*)d_in[5];
    const float* b_a2  = (const float*)d_in[6];
    const float* W_c1  = (const float*)d_in[7];
    const float* b_c1  = (const float*)d_in[8];
    const float* W_c2  = (const float*)d_in[9];
    const float* b_c2  = (const float*)d_in[10];
    const float* W_g1  = (const float*)d_in[11];
    const float* b_g1  = (const float*)d_in[12];
    const float* W_g2  = (const float*)d_in[13];
    const float* b_g2  = (const float*)d_in[14];
    const float* W_g3  = (const float*)d_in[15];
    const float* b_g3  = (const float*)d_in[16];

    float* out = (float*)d_out;
    const long E_OFF    = 0;
    const long BETA_OFF = (long)LPN * LHN;
    const long ALPHA_OFF= BETA_OFF + (long)LPN * DN;
    const long V1_OFF   = ALPHA_OFF + (long)LHN * DN;
    const long V2_OFF   = V1_OFF + HN;
    const long Y_OFF    = V2_OFF + HN;

    float *emb2, *eik, *ekj, *part, *part2, *split;
    GETSYM(emb2, g_emb2);
    GETSYM(eik, g_eik); GETSYM(ekj, g_ekj);
    GETSYM(part, g_part); GETSYM(part2, g_part2); GETSYM(split, g_split);

    __nv_bfloat16 *emb2s_h, *emb2s_l, *ths_h, *ths_l, *fps_h, *fps_l;
    __nv_bfloat16 *fhTs_h, *fhTs_l, *Es_h, *Es_l, *ETs_h, *ETs_l;
    __nv_bfloat16 *hTs_h, *hTs_l, *pTs_h, *pTs_l, *xs_h, *xs_l;
    __nv_bfloat16 *Wa1s_h, *Wa1s_l, *Wa2s_h, *Wa2s_l, *Wc1s_h, *Wc1s_l, *Wc2s_h, *Wc2s_l;
    GETSYM(emb2s_h, g_emb2s_h); GETSYM(emb2s_l, g_emb2s_l);
    GETSYM(ths_h, g_ths_h);     GETSYM(ths_l, g_ths_l);
    GETSYM(fps_h, g_fps_h);     GETSYM(fps_l, g_fps_l);
    GETSYM(fhTs_h, g_fhTs_h);   GETSYM(fhTs_l, g_fhTs_l);
    GETSYM(Es_h, g_Es_h);       GETSYM(Es_l, g_Es_l);
    GETSYM(ETs_h, g_ETs_h);     GETSYM(ETs_l, g_ETs_l);
    GETSYM(hTs_h, g_hTs_h);     GETSYM(hTs_l, g_hTs_l);
    GETSYM(pTs_h, g_pTs_h);     GETSYM(pTs_l, g_pTs_l);
    GETSYM(xs_h, g_xs_h);       GETSYM(xs_l, g_xs_l);
    GETSYM(Wa1s_h, g_Wa1s_h);   GETSYM(Wa1s_l, g_Wa1s_l);
    GETSYM(Wa2s_h, g_Wa2s_h);   GETSYM(Wa2s_l, g_Wa2s_l);
    GETSYM(Wc1s_h, g_Wc1s_h);   GETSYM(Wc1s_l, g_Wc1s_l);
    GETSYM(Wc2s_h, g_Wc2s_h);   GETSYM(Wc2s_l, g_Wc2s_l);

    // 0) all weight splits
    {
        long total = (long)HN * (DP + HN + D2P + HN);
        split_weights_kernel<<<(int)((total + 255) / 256), 256>>>(
            W_a1, W_a2, W_c1, W_c2,
            Wa1s_h, Wa1s_l, Wa2s_h, Wa2s_l, Wc1s_h, Wc1s_l, Wc2s_h, Wc2s_l);
    }

    // 1) fused gather + splits + xs fill
    gather_split_kernel<<<M2, 128>>>(emb, p_idx, h_idx, emb2,
                                     emb2s_h, emb2s_l, xs_h, xs_l);

    // 2) attend1 (batched p+h)
    {
        BArgs a{emb2s_h, emb2s_l, DP, Wa1s_h, Wa1s_l, DP};
        a.bias = b_a1; a.Chi = ths_h; a.Clo = ths_l; a.ldS = HN;
        a.M = M2; a.N = HN; a.K = DP; a.relu = 1;
        launch_bgemm(a);
    }
    // 3) attend2 with fused reshape-transpose
    {
        BArgs a{ths_h, ths_l, HN, Wa2s_h, Wa2s_l, HN};
        a.bias = b_a2;
        a.Chi = fps_h; a.Clo = fps_l; a.ldS = HN;
        a.Th = fhTs_h; a.Tl = fhTs_l; a.ldT = HN;
        a.reshapeRow = LPN;
        a.M = M2; a.N = HN; a.K = HN; a.relu = 1;
        launch_bgemm(a);
    }

    // 4) E GEMM with fused split + transposed split + row/col partials
    {
        BArgs a{fps_h, fps_l, HN, fhTs_h, fhTs_l, HN};
        a.C = out + E_OFF; a.ldc = LHN;
        a.Chi = Es_h; a.Clo = Es_l; a.ldS = LHN;
        a.Th = ETs_h; a.Tl = ETs_l; a.ldT = LHN;
        a.rowpart = part; a.colpart = part2;
        a.M = LPN; a.N = LHN; a.K = HN;
        launch_bgemm(a);
    }
    {
        dim3 g((LPN + 255) / 256, 2);
        colsum_reduce2_kernel<<<g, 256>>>(part, eik, 64, part2, ekj, 32, LPN);
    }

    // 5) embedding transposes for beta/alpha B-operands
    {
        dim3 b(32, 8);
        dim3 g((NROWS_PAD + 31) / 32, (LPN + 31) / 32, 2);
        transpose_split2_kernel<<<g, b>>>(emb2, pTs_h, pTs_l,
                                          emb2 + (long)LPN * DN, hTs_h, hTs_l,
                                          LPN, DN, NROWS_PAD);
    }

    // 6) beta & alpha in ONE launch, split-K x4 each
    {
        BArgs a{Es_h, Es_l, LHN, hTs_h, hTs_l, LHN};
        a.A2h = ETs_h; a.A2l = ETs_l; a.B2h = pTs_h; a.B2l = pTs_l;
        a.C = split; a.ldc = DN; a.sliceStride = (long)LPN * DN;
        a.M = LPN; a.N = DN; a.K = LHN; a.splits = 4; a.zTotal = 8;
        launch_bgemm(a);
    }
    {
        dim3 g((int)(((long)LPN * DN + 255) / 256), 2);
        splitk_concat2_kernel<<<g, 256>>>(split, eik, out + BETA_OFF,
                                          split + 4 * (long)LPN * DN, ekj, out + ALPHA_OFF,
                                          xs_h, xs_l, LPN, DN, 4);
    }

    // 7) comp (batched), colsums fused into comp2
    {
        BArgs a{xs_h, xs_l, D2P, Wc1s_h, Wc1s_l, D2P};
        a.bias = b_c1; a.Chi = ths_h; a.Clo = ths_l; a.ldS = HN;
        a.M = M2; a.N = HN; a.K = D2P; a.relu = 1;
        launch_bgemm(a);
    }
    {
        BArgs a{ths_h, ths_l, HN, Wc2s_h, Wc2s_l, HN};
        a.bias = b_c2; a.colpart = part;
        a.M = M2; a.N = HN; a.K = HN; a.relu = 1;
        launch_bgemm(a);
    }
    {
        dim3 g((HN + 255) / 256, 2);
        colsum_reduce2_kernel<<<g, 256>>>(part, out + V1_OFF, 32,
                                          part + 32 * HN, out + V2_OFF, 32, HN);
    }

    // 8) head
    head_kernel<<<1, HN>>>(out + V1_OFF, W_g1, b_g1, W_g2, b_g2, W_g3, b_g3, out + Y_OFF);

    (void)in_sizes; (void)n_in; (void)out_size;
}

// round 13
// speedup vs baseline: 1.2844x; 1.1555x over previous
#include <cuda_runtime.h>
#include <cuda_bf16.h>
#include <cstdint>
#include <cmath>

#define LPN 4096
#define LHN 4096
#define DN  300
#define HN  512
#define DP  320
#define D2P 608
#define NROWS_PAD 384
#define M2  8192
#define WROWS 384          // padded rows of W1T/W2T
#define WELEMS (WROWS * HN)

// ---------------- scratch ----------------------------------------------------
__device__ float g_emb2[M2 * DN];
__device__ float g_eik [LPN];
__device__ float g_ekj [LHN];
__device__ float g_part [64 * 4096];
__device__ float g_part2[64 * 4096];
__device__ float g_split[16 * WELEMS + 2 * LPN * DN];   // W slices + beta/alpha raw

__device__ __nv_bfloat16 g_emb2s_h[M2 * DP],  g_emb2s_l[M2 * DP];
__device__ __nv_bfloat16 g_ths_h [M2 * HN],   g_ths_l [M2 * HN];
__device__ __nv_bfloat16 g_fs_h  [M2 * HN],   g_fs_l  [M2 * HN];   // attend2 out (fp|fh)
__device__ __nv_bfloat16 g_fpTs_h[HN * LPN],  g_fpTs_l[HN * LPN];  // fp^T
__device__ __nv_bfloat16 g_fhTs_h[LHN * HN],  g_fhTs_l[LHN * HN];  // reshape-transpose
__device__ __nv_bfloat16 g_hTs_h[NROWS_PAD * LHN], g_hTs_l[NROWS_PAD * LHN];
__device__ __nv_bfloat16 g_pTs_h[NROWS_PAD * LPN], g_pTs_l[NROWS_PAD * LPN];
__device__ __nv_bfloat16 g_W1Ts_h[WELEMS], g_W1Ts_l[WELEMS];
__device__ __nv_bfloat16 g_W2Ts_h[WELEMS], g_W2Ts_l[WELEMS];
__device__ __nv_bfloat16 g_xs_h [M2 * D2P],   g_xs_l [M2 * D2P];
__device__ __nv_bfloat16 g_Wa1s_h[HN * DP],   g_Wa1s_l[HN * DP];
__device__ __nv_bfloat16 g_Wa2s_h[HN * HN],   g_Wa2s_l[HN * HN];
__device__ __nv_bfloat16 g_Wc1s_h[HN * D2P],  g_Wc1s_l[HN * D2P];
__device__ __nv_bfloat16 g_Wc2s_h[HN * HN],   g_Wc2s_l[HN * HN];

// ---------------- PTX helpers ------------------------------------------------
__device__ __forceinline__ uint32_t smem_u32(const void* p) {
    uint32_t a;
    asm("{ .reg .u64 t; cvta.to.shared.u64 t, %1; cvt.u32.u64 %0, t; }" : "=r"(a) : "l"(p));
    return a;
}
__device__ __forceinline__ void ldsm4(uint32_t& r0, uint32_t& r1, uint32_t& r2,
                                      uint32_t& r3, uint32_t addr) {
    asm volatile("ldmatrix.sync.aligned.m8n8.x4.shared.b16 {%0,%1,%2,%3}, [%4];"
                 : "=r"(r0), "=r"(r1), "=r"(r2), "=r"(r3) : "r"(addr));
}
__device__ __forceinline__ void mma16816(float* c, const uint32_t* a,
                                         const uint32_t b0, const uint32_t b1) {
    asm volatile(
        "mma.sync.aligned.m16n8k16.row.col.f32.bf16.bf16.f32 "
        "{%0,%1,%2,%3}, {%4,%5,%6,%7}, {%8,%9}, {%0,%1,%2,%3};"
        : "+f"(c[0]), "+f"(c[1]), "+f"(c[2]), "+f"(c[3])
        : "r"(a[0]), "r"(a[1]), "r"(a[2]), "r"(a[3]), "r"(b0), "r"(b1));
}
__device__ __forceinline__ void cvt_split(float x, __nv_bfloat16& hi, __nv_bfloat16& lo) {
    hi = __float2bfloat16(x);
    lo = __float2bfloat16(x - __bfloat162float(hi));
}
__device__ __forceinline__ uint32_t pack_bf2(__nv_bfloat16 a, __nv_bfloat16 b) {
    return (uint32_t)__bfloat16_as_ushort(a) | ((uint32_t)__bfloat16_as_ushort(b) << 16);
}
__device__ __forceinline__ void cp16(uint32_t dst, const void* src) {
    asm volatile("cp.async.cg.shared.global [%0], [%1], 16;"
                 :: "r"(dst), "l"(__cvta_generic_to_global(src)));
}
__device__ __forceinline__ void cp_commit() {
    asm volatile("cp.async.commit_group;");
}
template <int NN> __device__ __forceinline__ void cp_wait() {
    asm volatile("cp.async.wait_group %0;" :: "n"(NN));
}

#define STAGE_BYTES 30720

// ---------------- bf16x3 mma.sync SGEMM, 128x64 tile, 2-stage, 1 bar/chunk ---
__global__ __launch_bounds__(256, 3)
void bgemm(const __nv_bfloat16* __restrict__ Agh, const __nv_bfloat16* __restrict__ Agl, long ldA,
           const __nv_bfloat16* __restrict__ Bgh, const __nv_bfloat16* __restrict__ Bgl, long ldB,
           const __nv_bfloat16* __restrict__ A2gh, const __nv_bfloat16* __restrict__ A2gl,
           const __nv_bfloat16* __restrict__ B2gh, const __nv_bfloat16* __restrict__ B2gl,
           int zSecond,
           const float* __restrict__ bias,
           float* __restrict__ C, long ldc, long sliceStride,
           __nv_bfloat16* __restrict__ Chi, __nv_bfloat16* __restrict__ Clo, long ldS,
           __nv_bfloat16* __restrict__ Th, __nv_bfloat16* __restrict__ Tl, long ldT,
           __nv_bfloat16* __restrict__ Tph, __nv_bfloat16* __restrict__ Tpl, long ldTp,
           float* __restrict__ rowpart, float* __restrict__ colpart,
           int reshapeRow,
           int M, int N, int K, int kPerSlice, int relu) {
    extern __shared__ __align__(16) char smraw[];
    const int tid = threadIdx.x, lane = tid & 31, wid = tid >> 5;
    const int wm = wid >> 1, wn = wid & 1;
    const int m0 = blockIdx.y * 128, n0 = blockIdx.x * 64;
    const int zz = blockIdx.z;
    if (A2gh && zz >= zSecond) { Agh = A2gh; Agl = A2gl; Bgh = B2gh; Bgl = B2gl; }
    const int kbeg = (zz % zSecond) * kPerSlice;
    const int kend = min(K, kbeg + kPerSlice);
    const int nch = (kend - kbeg) >> 5;
    C += (long)zz * sliceStride;

    const uint32_t sb = smem_u32(smraw);

    float acc[2][4][4];
    #pragma unroll
    for (int i = 0; i < 2; i++)
        #pragma unroll
        for (int j = 0; j < 4; j++)
            #pragma unroll
            for (int e = 0; e < 4; e++) acc[i][j][e] = 0.f;

    const int lrow = (((lane >> 3) & 1) << 3) + (lane & 7);
    const int lcol = (lane >> 4) << 4;

    auto load_stage = [&](int st, int k0) {
        uint32_t sbase = sb + st * STAGE_BYTES;
        #pragma unroll
        for (int i = 0; i < 2; i++) {
            int c = tid + i * 256;
            int r = c >> 2, kq = c & 3;
            uint32_t dso = (uint32_t)(r * 80 + kq * 16);
            long ao = (long)(m0 + r) * ldA + k0 + kq * 8;
            cp16(sbase + dso,         Agh + ao);
            cp16(sbase + 10240 + dso, Agl + ao);
        }
        {
            int r = tid >> 2, kq = tid & 3;
            uint32_t dso = (uint32_t)(r * 80 + kq * 16);
            long bo = (long)(n0 + r) * ldB + k0 + kq * 8;
            cp16(sbase + 20480 + dso, Bgh + bo);
            cp16(sbase + 25600 + dso, Bgl + bo);
        }
    };

    load_stage(0, kbeg);
    cp_commit();

    int stage = 0;
    for (int i = 0; i < nch; i++) {
        cp_wait<0>();
        __syncthreads();
        if (i + 1 < nch) {
            load_stage(stage ^ 1, kbeg + (i + 1) * 32);
            cp_commit();
        }

        const uint32_t aAh = sb + stage * STAGE_BYTES;
        const uint32_t aAl = aAh + 10240;
        const uint32_t aBh = aAh + 20480;
        const uint32_t aBl = aAh + 25600;

        #pragma unroll
        for (int s = 0; s < 2; s++) {
            const int sbyte = s * 32;
            uint32_t ah[2][4], al[2][4], bh[2][4];
            #pragma unroll
            for (int mf = 0; mf < 2; mf++) {
                int row = wm * 32 + mf * 16 + lrow;
                ldsm4(ah[mf][0], ah[mf][1], ah[mf][2], ah[mf][3],
                      aAh + row * 80 + lcol + sbyte);
                ldsm4(al[mf][0], al[mf][1], al[mf][2], al[mf][3],
                      aAl + row * 80 + lcol + sbyte);
            }
            #pragma unroll
            for (int nf = 0; nf < 2; nf++) {
                int row = wn * 32 + nf * 16 + lrow;
                ldsm4(bh[nf][0], bh[nf][1], bh[nf][2], bh[nf][3],
                      aBh + row * 80 + lcol + sbyte);
            }
            #pragma unroll
            for (int nf = 0; nf < 2; nf++)
                #pragma unroll
                for (int j = 0; j < 2; j++)
                    #pragma unroll
                    for (int mf = 0; mf < 2; mf++)
                        mma16816(acc[mf][nf * 2 + j], ah[mf], bh[nf][j], bh[nf][j + 2]);
            #pragma unroll
            for (int nf = 0; nf < 2; nf++)
                #pragma unroll
                for (int j = 0; j < 2; j++)
                    #pragma unroll
                    for (int mf = 0; mf < 2; mf++)
                        mma16816(acc[mf][nf * 2 + j], al[mf], bh[nf][j], bh[nf][j + 2]);
            #pragma unroll
            for (int nf = 0; nf < 2; nf++) {
                int row = wn * 32 + nf * 16 + lrow;
                uint32_t bl[4];
                ldsm4(bl[0], bl[1], bl[2], bl[3], aBl + row * 80 + lcol + sbyte);
                #pragma unroll
                for (int j = 0; j < 2; j++)
                    #pragma unroll
                    for (int mf = 0; mf < 2; mf++)
                        mma16816(acc[mf][nf * 2 + j], ah[mf], bl[j], bl[j + 2]);
            }
        }
        stage ^= 1;
    }
    __syncthreads();

    // ---- bias/relu in-place ----
    const int tg = lane >> 2;
    const int tn = (lane & 3) << 1;
    if (bias || relu) {
        #pragma unroll
        for (int mf = 0; mf < 2; mf++)
            #pragma unroll
            for (int nfj = 0; nfj < 4; nfj++) {
                int n = n0 + (wn * 32 + nfj * 8 + tn);
                #pragma unroll
                for (int h2 = 0; h2 < 2; h2++) {
                    float vx = acc[mf][nfj][h2 * 2 + 0];
                    float vy = acc[mf][nfj][h2 * 2 + 1];
                    if (bias && n < N) { vx += bias[n]; vy += bias[n + 1]; }
                    if (relu) { vx = fmaxf(vx, 0.f); vy = fmaxf(vy, 0.f); }
                    acc[mf][nfj][h2 * 2 + 0] = vx;
                    acc[mf][nfj][h2 * 2 + 1] = vy;
                }
            }
    }

    const bool rsh = (reshapeRow >= 0);
    const bool isH = rsh && (m0 >= reshapeRow);

    if (C || Chi) {
        __nv_bfloat16* ChiZ = Chi ? Chi + (long)zz * 0 : nullptr; // Chi not sliced
        #pragma unroll
        for (int mf = 0; mf < 2; mf++) {
            #pragma unroll
            for (int h2 = 0; h2 < 2; h2++) {
                int m = m0 + wm * 32 + mf * 16 + h2 * 8 + tg;
                #pragma unroll
                for (int nfj = 0; nfj < 4; nfj++) {
                    int n = n0 + wn * 32 + nfj * 8 + tn;
                    if (n >= N) continue;
                    float2 v;
                    v.x = acc[mf][nfj][h2 * 2 + 0];
                    v.y = acc[mf][nfj][h2 * 2 + 1];
                    if (C) *(float2*)(C + (long)m * ldc + n) = v;
                    if (ChiZ) {
                        __nv_bfloat16 h0, l0, h1, l1;
                        cvt_split(v.x, h0, l0);
                        cvt_split(v.y, h1, l1);
                        long o = (long)m * ldS + n;
                        *(uint32_t*)(Chi + o) = pack_bf2(h0, h1);
                        *(uint32_t*)(Clo + o) = pack_bf2(l0, l1);
                    }
                }
            }
        }
    }

    const bool doResh = Th && rsh && isH;
    const bool doReg  = Tph && rsh && !isH;
    if (doResh || doReg || rowpart || colpart) {
        float* ts = (float*)smraw;             // [64][129]
        #pragma unroll
        for (int mf = 0; mf < 2; mf++) {
            #pragma unroll
            for (int h2 = 0; h2 < 2; h2++) {
                int ml = wm * 32 + mf * 16 + h2 * 8 + tg;
                #pragma unroll
                for (int nfj = 0; nfj < 4; nfj++) {
                    int nl = wn * 32 + nfj * 8 + tn;
                    ts[(nl + 0) * 129 + ml] = acc[mf][nfj][h2 * 2 + 0];
                    ts[(nl + 1) * 129 + ml] = acc[mf][nfj][h2 * 2 + 1];
                }
            }
        }
        __syncthreads();
        if (tid < 128 && rowpart) {
            float s = 0.f;
            #pragma unroll 8
            for (int n = 0; n < 64; n++) s += ts[n * 129 + tid];
            rowpart[(long)blockIdx.x * M + m0 + tid] = s;
        }
        if (tid < 64 && colpart) {
            float s2 = 0.f;
            #pragma unroll 8
            for (int m = 0; m < 128; m++) s2 += ts[tid * 129 + m];
            colpart[(long)blockIdx.y * N + n0 + tid] = s2;
        }
        if (doResh) {
            long kb = (long)(m0 - reshapeRow) >> 3;
            for (int idx = tid; idx < 512; idx += 256) {
                int r8 = idx >> 6, nl = idx & 63;
                long j = (long)r8 * HN + n0 + nl;
                __align__(16) __nv_bfloat16 hb[16], lb[16];
                #pragma unroll
                for (int q = 0; q < 16; q++) {
                    __nv_bfloat16 hi, lo;
                    cvt_split(ts[nl * 129 + r8 + 8 * q], hi, lo);
                    hb[q] = hi; lb[q] = lo;
                }
                long o = j * ldT + kb;
                *(uint4*)(Th + o)     = *(uint4*)(hb);
                *(uint4*)(Th + o + 8) = *(uint4*)(hb + 8);
                *(uint4*)(Tl + o)     = *(uint4*)(lb);
                *(uint4*)(Tl + o + 8) = *(uint4*)(lb + 8);
            }
        }
        if (doReg) {
            for (int idx = tid; idx < 4096; idx += 256) {
                int n = idx >> 6, m2 = (idx & 63) << 1;
                __nv_bfloat16 h0, l0, h1, l1;
                cvt_split(ts[n * 129 + m2], h0, l0);
                cvt_split(ts[n * 129 + m2 + 1], h1, l1);
                long o = (long)(n0 + n) * ldTp + m0 + m2;
                *(uint32_t*)(Tph + o) = pack_bf2(h0, h1);
                *(uint32_t*)(Tpl + o) = pack_bf2(l0, l1);
            }
        }
    }
}

static const int BGEMM_SMEM = 2 * STAGE_BYTES;

// ---------------- weight splits -----------------------------------------------
__global__ void split_weights_kernel(const float* __restrict__ Wa1, const float* __restrict__ Wa2,
                                     const float* __restrict__ Wc1, const float* __restrict__ Wc2,
                                     __nv_bfloat16* __restrict__ a1h, __nv_bfloat16* __restrict__ a1l,
                                     __nv_bfloat16* __restrict__ a2h, __nv_bfloat16* __restrict__ a2l,
                                     __nv_bfloat16* __restrict__ c1h, __nv_bfloat16* __restrict__ c1l,
                                     __nv_bfloat16* __restrict__ c2h, __nv_bfloat16* __restrict__ c2l) {
    const long s1 = (long)HN * DP, s2 = (long)HN * HN, s3 = (long)HN * D2P, s4 = (long)HN * HN;
    long i = (long)blockIdx.x * blockDim.x + threadIdx.x;
    const float* src; __nv_bfloat16 *dh, *dl; int K, Kpad; long li;
    if (i < s1)                { src = Wa1; dh = a1h; dl = a1l; K = DN;     Kpad = DP;  li = i; }
    else if (i < s1 + s2)      { src = Wa2; dh = a2h; dl = a2l; K = HN;     Kpad = HN;  li = i - s1; }
    else if (i < s1 + s2 + s3) { src = Wc1; dh = c1h; dl = c1l; K = 2 * DN; Kpad = D2P; li = i - s1 - s2; }
    else if (i < s1 + s2 + s3 + s4) { src = Wc2; dh = c2h; dl = c2l; K = HN; Kpad = HN; li = i - s1 - s2 - s3; }
    else return;
    int m = (int)(li / Kpad), k = (int)(li % Kpad);
    float v = (k < K) ? src[(long)m * K + k] : 0.f;
    __nv_bfloat16 hi, lo;
    cvt_split(v, hi, lo);
    dh[li] = hi; dl[li] = lo;
}

// ---------------- fused gather + split-pad + xs fill ---------------------------
__global__ void gather_split_kernel(const float* __restrict__ emb,
                                    const int* __restrict__ p_idx,
                                    const int* __restrict__ h_idx,
                                    float* __restrict__ emb2,
                                    __nv_bfloat16* __restrict__ e_h,
                                    __nv_bfloat16* __restrict__ e_l,
                                    __nv_bfloat16* __restrict__ x_h,
                                    __nv_bfloat16* __restrict__ x_l) {
    int r = blockIdx.x;
    long src = (r < LPN) ? p_idx[r] : h_idx[r - LPN];
    const float* s = emb + src * (long)DN;
    for (int c = threadIdx.x; c < DP; c += blockDim.x) {
        float v = (c < DN) ? s[c] : 0.f;
        __nv_bfloat16 hi, lo;
        cvt_split(v, hi, lo);
        long eo = (long)r * DP + c;
        e_h[eo] = hi; e_l[eo] = lo;
        if (c < DN) {
            emb2[(long)r * DN + c] = v;
            long xo = (long)r * D2P + c;
            x_h[xo] = hi; x_l[xo] = lo;
        }
    }
    for (int c = 2 * DN + threadIdx.x; c < D2P; c += blockDim.x) {
        long xo = (long)r * D2P + c;
        x_h[xo] = __float2bfloat16(0.f);
        x_l[xo] = __float2bfloat16(0.f);
    }
}

// ---------------- transpose + split (dual-source) ------------------------------
__global__ void transpose_split2_kernel(const float* __restrict__ srcA,
                                        __nv_bfloat16* __restrict__ dhA, __nv_bfloat16* __restrict__ dlA,
                                        const float* __restrict__ srcB,
                                        __nv_bfloat16* __restrict__ dhB, __nv_bfloat16* __restrict__ dlB,
                                        int R, int C, int dR) {
    const float* src = blockIdx.z ? srcB : srcA;
    __nv_bfloat16* dh = blockIdx.z ? dhB : dhA;
    __nv_bfloat16* dl = blockIdx.z ? dlB : dlA;
    __shared__ float tile[32][33];
    int c0 = blockIdx.x * 32, r0 = blockIdx.y * 32;
    int x = threadIdx.x, y = threadIdx.y;
    #pragma unroll
    for (int i = y; i < 32; i += 8) {
        int r = r0 + i, c = c0 + x;
        tile[i][x] = (r < R && c < C) ? src[(long)r * C + c] : 0.f;
    }
    __syncthreads();
    #pragma unroll
    for (int i = y; i < 32; i += 8) {
        int dr = c0 + i, dc = r0 + x;
        if (dr < dR && dc < R) {
            __nv_bfloat16 hi, lo;
            cvt_split(tile[x][i], hi, lo);
            dh[(long)dr * R + dc] = hi;
            dl[(long)dr * R + dc] = lo;
        }
    }
}

// ---------------- W slice reduce + split ----------------------------------------
__global__ void wreduce_kernel(const float* __restrict__ slices,
                               __nv_bfloat16* __restrict__ w1h, __nv_bfloat16* __restrict__ w1l,
                               __nv_bfloat16* __restrict__ w2h, __nv_bfloat16* __restrict__ w2l) {
    int i = blockIdx.x * blockDim.x + threadIdx.x;
    if (i >= WELEMS) return;
    int which = blockIdx.y;
    const float* base = slices + (long)which * 8 * WELEMS + i;
    float s = 0.f;
    #pragma unroll
    for (int p = 0; p < 8; p++) s += base[(long)p * WELEMS];
    __nv_bfloat16 hi, lo;
    cvt_split(s, hi, lo);
    if (which) { w2h[i] = hi; w2l[i] = lo; }
    else       { w1h[i] = hi; w1l[i] = lo; }
}

// ---------------- reduce + rowdiv + fused concat (dual) -------------------------
__global__ void splitk_concat2_kernel(const float* __restrict__ partA, const float* __restrict__ rdA,
                                      float* __restrict__ CA,
                                      const float* __restrict__ partB, const float* __restrict__ rdB,
                                      float* __restrict__ CB,
                                      __nv_bfloat16* __restrict__ xh, __nv_bfloat16* __restrict__ xl,
                                      int M, int N, int S) {
    const float* part = blockIdx.y ? partB : partA;
    const float* rowdiv = blockIdx.y ? rdB : rdA;
    float* C = blockIdx.y ? CB : CA;
    long xRowOff = blockIdx.y ? (long)M : 0;
    long i = (long)blockIdx.x * blockDim.x + threadIdx.x;
    long total = (long)M * N;
    if (i >= total) return;
    int m = (int)(i / N), n = (int)(i % N);
    float s = 0.f;
    for (int p = 0; p < S; p++) s += part[(long)p * total + i];
    float v = s / rowdiv[m];
    C[(long)m * N + n] = v;
    __nv_bfloat16 hi, lo;
    cvt_split(v, hi, lo);
    long o = (xRowOff + m) * (long)D2P + DN + n;
    xh[o] = hi; xl[o] = lo;
}

// ---------------- dual column reduce --------------------------------------------
__global__ void colsum_reduce2_kernel(const float* __restrict__ partA, float* __restrict__ outA, int PA,
                                      const float* __restrict__ partB, float* __restrict__ outB, int PB,
                                      int C) {
    const float* part = blockIdx.y ? partB : partA;
    float* out = blockIdx.y ? outB : outA;
    int P = blockIdx.y ? PB : PA;
    int c = blockIdx.x * blockDim.x + threadIdx.x;
    if (c >= C) return;
    float s = 0.f;
    for (int p = 0; p < P; p++) s += part[(long)p * C + c];
    out[c] = s;
}

// ---------------- final head -----------------------------------------------------
__global__ void head_kernel(const float* __restrict__ v,
                            const float* __restrict__ Wg1, const float* __restrict__ bg1,
                            const float* __restrict__ Wg2, const float* __restrict__ bg2,
                            const float* __restrict__ Wg3, const float* __restrict__ bg3,
                            float* __restrict__ y) {
    __shared__ float sv[2 * HN];
    __shared__ float y1[HN];
    __shared__ float y2[HN];
    __shared__ float logit[3];
    int t = threadIdx.x;
    sv[t] = v[t];
    sv[t + HN] = v[t + HN];
    __syncthreads();
    {
        float acc = bg1[t];
        const float* w = Wg1 + (long)t * (2 * HN);
        for (int k = 0; k < 2 * HN; k++) acc += sv[k] * w[k];
        y1[t] = fmaxf(acc, 0.f);
    }
    __syncthreads();
    {
        float acc = bg2[t];
        const float* w = Wg2 + (long)t * HN;
        for (int k = 0; k < HN; k++) acc += y1[k] * w[k];
        y2[t] = fmaxf(acc, 0.f);
    }
    __syncthreads();
    if (t < 3) {
        float a = bg3[t];
        const float* w = Wg3 + (long)t * HN;
        for (int k = 0; k < HN; k++) a += y2[k] * w[k];
        logit[t] = a;
    }
    __syncthreads();
    if (t == 0) {
        float m = fmaxf(logit[0], fmaxf(logit[1], logit[2]));
        float e0 = expf(logit[0] - m), e1 = expf(logit[1] - m), e2 = expf(logit[2] - m);
        float s = e0 + e1 + e2;
        y[0] = e0 / s; y[1] = e1 / s; y[2] = e2 / s;
    }
}

// ---------------- host dispatch ---------------------------------------------------
struct BArgs {
    const __nv_bfloat16 *Ah, *Al; long ldA;
    const __nv_bfloat16 *Bh, *Bl; long ldB;
    const __nv_bfloat16 *A2h = nullptr, *A2l = nullptr, *B2h = nullptr, *B2l = nullptr;
    const float* bias = nullptr;
    float* C = nullptr; long ldc = 0; long sliceStride = 0;
    __nv_bfloat16 *Chi = nullptr, *Clo = nullptr; long ldS = 0;
    __nv_bfloat16 *Th = nullptr, *Tl = nullptr; long ldT = 0;
    __nv_bfloat16 *Tph = nullptr, *Tpl = nullptr; long ldTp = 0;
    float *rowpart = nullptr, *colpart = nullptr;
    int reshapeRow = -1;
    int M, N, K, splits = 1, zTotal = 0, relu = 0;
};

static void launch_bgemm(const BArgs& a) {
    cudaFuncSetAttribute(bgemm, cudaFuncAttributeMaxDynamicSharedMemorySize, BGEMM_SMEM);
    int kps = (a.K + a.splits - 1) / a.splits;
    kps = ((kps + 31) / 32) * 32;
    int zt = a.zTotal ? a.zTotal : a.splits;
    dim3 grid((a.N + 63) / 64, a.M / 128, zt);
    bgemm<<<grid, 256, BGEMM_SMEM>>>(a.Ah, a.Al, a.ldA, a.Bh, a.Bl, a.ldB,
                                     a.A2h, a.A2l, a.B2h, a.B2l, a.splits,
                                     a.bias, a.C, a.ldc, a.sliceStride,
                                     a.Chi, a.Clo, a.ldS,
                                     a.Th, a.Tl, a.ldT,
                                     a.Tph, a.Tpl, a.ldTp,
                                     a.rowpart, a.colpart, a.reshapeRow,
                                     a.M, a.N, a.K, kps, a.relu);
}

#define GETSYM(var, sym) cudaGetSymbolAddress((void**)&var, sym)

extern "C" void kernel_launch(void* const* d_in, const int* in_sizes, int n_in,
                              void* d_out, int out_size) {
    const int*   p_idx = (const int*)  d_in[0];
    const int*   h_idx = (const int*)  d_in[1];
    const float* emb   = (const float*)d_in[2];
    const float* W_a1  = (const float*)d_in[3];
    const float* b_a1  = (const float*)d_in[4];
    const float* W_a2  = (const float*)d_in[5];
    const float* b_a2  = (const float*)d_in[6];
    const float* W_c1  = (const float*)d_in[7];
    const float* b_c1  = (const float*)d_in[8];
    const float* W_c2  = (const float*)d_in[9];
    const float* b_c2  = (const float*)d_in[10];
    const float* W_g1  = (const float*)d_in[11];
    const float* b_g1  = (const float*)d_in[12];
    const float* W_g2  = (const float*)d_in[13];
    const float* b_g2  = (const float*)d_in[14];
    const float* W_g3  = (const float*)d_in[15];
    const float* b_g3  = (const float*)d_in[16];

    float* out = (float*)d_out;
    const long E_OFF    = 0;
    const long BETA_OFF = (long)LPN * LHN;
    const long ALPHA_OFF= BETA_OFF + (long)LPN * DN;
    const long V1_OFF   = ALPHA_OFF + (long)LHN * DN;
    const long V2_OFF   = V1_OFF + HN;
    const long Y_OFF    = V2_OFF + HN;

    float *emb2, *eik, *ekj, *part, *part2, *split;
    GETSYM(emb2, g_emb2);
    GETSYM(eik, g_eik); GETSYM(ekj, g_ekj);
    GETSYM(part, g_part); GETSYM(part2, g_part2); GETSYM(split, g_split);

    __nv_bfloat16 *emb2s_h, *emb2s_l, *ths_h, *ths_l, *fs_h, *fs_l;
    __nv_bfloat16 *fpTs_h, *fpTs_l, *fhTs_h, *fhTs_l;
    __nv_bfloat16 *hTs_h, *hTs_l, *pTs_h, *pTs_l;
    __nv_bfloat16 *W1Ts_h, *W1Ts_l, *W2Ts_h, *W2Ts_l, *xs_h, *xs_l;
    __nv_bfloat16 *Wa1s_h, *Wa1s_l, *Wa2s_h, *Wa2s_l, *Wc1s_h, *Wc1s_l, *Wc2s_h, *Wc2s_l;
    GETSYM(emb2s_h, g_emb2s_h); GETSYM(emb2s_l, g_emb2s_l);
    GETSYM(ths_h, g_ths_h);     GETSYM(ths_l, g_ths_l);
    GETSYM(fs_h, g_fs_h);       GETSYM(fs_l, g_fs_l);
    GETSYM(fpTs_h, g_fpTs_h);   GETSYM(fpTs_l, g_fpTs_l);
    GETSYM(fhTs_h, g_fhTs_h);   GETSYM(fhTs_l, g_fhTs_l);
    GETSYM(hTs_h, g_hTs_h);     GETSYM(hTs_l, g_hTs_l);
    GETSYM(pTs_h, g_pTs_h);     GETSYM(pTs_l, g_pTs_l);
    GETSYM(W1Ts_h, g_W1Ts_h);   GETSYM(W1Ts_l, g_W1Ts_l);
    GETSYM(W2Ts_h, g_W2Ts_h);   GETSYM(W2Ts_l, g_W2Ts_l);
    GETSYM(xs_h, g_xs_h);       GETSYM(xs_l, g_xs_l);
    GETSYM(Wa1s_h, g_Wa1s_h);   GETSYM(Wa1s_l, g_Wa1s_l);
    GETSYM(Wa2s_h, g_Wa2s_h);   GETSYM(Wa2s_l, g_Wa2s_l);
    GETSYM(Wc1s_h, g_Wc1s_h);   GETSYM(Wc1s_l, g_Wc1s_l);
    GETSYM(Wc2s_h, g_Wc2s_h);   GETSYM(Wc2s_l, g_Wc2s_l);

    // 0) weight splits
    {
        long total = (long)HN * (DP + HN + D2P + HN);
        split_weights_kernel<<<(int)((total + 255) / 256), 256>>>(
            W_a1, W_a2, W_c1, W_c2,
            Wa1s_h, Wa1s_l, Wa2s_h, Wa2s_l, Wc1s_h, Wc1s_l, Wc2s_h, Wc2s_l);
    }

    // 1) gather + splits + xs fill
    gather_split_kernel<<<M2, 128>>>(emb, p_idx, h_idx, emb2,
                                     emb2s_h, emb2s_l, xs_h, xs_l);

    // 2) attend1
    {
        BArgs a{emb2s_h, emb2s_l, DP, Wa1s_h, Wa1s_l, DP};
        a.bias = b_a1; a.Chi = ths_h; a.Clo = ths_l; a.ldS = HN;
        a.M = M2; a.N = HN; a.K = DP; a.relu = 1;
        launch_bgemm(a);
    }
    // 3) attend2: Chi=fs (full), p-tiles -> fpTs (regular T), h-tiles -> fhTs (reshape T)
    {
        BArgs a{ths_h, ths_l, HN, Wa2s_h, Wa2s_l, HN};
        a.bias = b_a2;
        a.Chi = fs_h; a.Clo = fs_l; a.ldS = HN;
        a.Th = fhTs_h; a.Tl = fhTs_l; a.ldT = HN;
        a.Tph = fpTs_h; a.Tpl = fpTs_l; a.ldTp = LPN;
        a.reshapeRow = LPN;
        a.M = M2; a.N = HN; a.K = HN; a.relu = 1;
        launch_bgemm(a);
    }

    // 4) E = fp @ fhR : A=fs (p half), B=fhTs; fused row/col partials only
    {
        BArgs a{fs_h, fs_l, HN, fhTs_h, fhTs_l, HN};
        a.C = out + E_OFF; a.ldc = LHN;
        a.rowpart = part; a.colpart = part2;
        a.M = LPN; a.N = LHN; a.K = HN;
        launch_bgemm(a);
    }
    {
        dim3 g((LPN + 255) / 256, 2);
        colsum_reduce2_kernel<<<g, 256>>>(part, eik, 64, part2, ekj, 32, LPN);
    }

    // 5) embedding transposes (pTs, hTs)
    {
        dim3 b(32, 8);
        dim3 g((NROWS_PAD + 31) / 32, (LPN + 31) / 32, 2);
        transpose_split2_kernel<<<g, b>>>(emb2, pTs_h, pTs_l,
                                          emb2 + (long)LPN * DN, hTs_h, hTs_l,
                                          LPN, DN, NROWS_PAD);
    }

    // 6) W1T = hT @ fhR^T ; W2T = pT @ fpT^T  (dual, split-K x8, fp32 slices)
    //    z 0..7: A=hTs, B=fhs(=fs+LPN*HN viewed [512 x 4096]); z 8..15: A=pTs, B=fpTs
    {
        BArgs a{hTs_h, hTs_l, LHN, fs_h + (long)LPN * HN, fs_l + (long)LPN * HN, LHN};
        a.A2h = pTs_h; a.A2l = pTs_l; a.B2h = fpTs_h; a.B2l = fpTs_l;
        a.C = split; a.ldc = HN; a.sliceStride = WELEMS;
        a.M = WROWS; a.N = HN; a.K = LHN; a.splits = 8; a.zTotal = 16;
        launch_bgemm(a);
    }
    {
        dim3 g((WELEMS + 255) / 256, 2);
        wreduce_kernel<<<g, 256>>>(split, W1Ts_h, W1Ts_l, W2Ts_h, W2Ts_l);
    }

    // 7) beta_raw = fp @ W1 ; alpha_raw = fhT @ W2  (dual, K=512)
    float* baRaw = split + 16L * WELEMS;
    {
        BArgs a{fs_h, fs_l, HN, W1Ts_h, W1Ts_l, HN};
        a.A2h = fhTs_h; a.A2l = fhTs_l; a.B2h = W2Ts_h; a.B2l = W2Ts_l;
        a.C = baRaw; a.ldc = DN; a.sliceStride = (long)LPN * DN;
        a.M = LPN; a.N = DN; a.K = HN; a.splits = 1; a.zTotal = 2;
        launch_bgemm(a);
    }
    {
        dim3 g((int)(((long)LPN * DN + 255) / 256), 2);
        splitk_concat2_kernel<<<g, 256>>>(baRaw, eik, out + BETA_OFF,
                                          baRaw + (long)LPN * DN, ekj, out + ALPHA_OFF,
                                          xs_h, xs_l, LPN, DN, 1);
    }

    // 8) comp (batched), colsums fused into comp2
    {
        BArgs a{xs_h, xs_l, D2P, Wc1s_h, Wc1s_l, D2P};
        a.bias = b_c1; a.Chi = ths_h; a.Clo = ths_l; a.ldS = HN;
        a.M = M2; a.N = HN; a.K = D2P; a.relu = 1;
        launch_bgemm(a);
    }
    {
        BArgs a{ths_h, ths_l, HN, Wc2s_h, Wc2s_l, HN};
        a.bias = b_c2; a.colpart = part;
        a.M = M2; a.N = HN; a.K = HN; a.relu = 1;
        launch_bgemm(a);
    }
    {
        dim3 g((HN + 255) / 256, 2);
        colsum_reduce2_kernel<<<g, 256>>>(part, out + V1_OFF, 32,
                                          part + 32 * HN, out + V2_OFF, 32, HN);
    }

    // 9) head
    head_kernel<<<1, HN>>>(out + V1_OFF, W_g1, b_g1, W_g2, b_g2, W_g3, b_g3, out + Y_OFF);

    (void)in_sizes; (void)n_in; (void)out_size;
}

// round 14
// speedup vs baseline: 1.3133x; 1.0225x over previous
#include <cuda_runtime.h>
#include <cuda_bf16.h>
#include <cstdint>
#include <cmath>

#define LPN 4096
#define LHN 4096
#define DN  300
#define HN  512
#define DP  320
#define D2P 608
#define NROWS_PAD 384
#define M2  8192
#define WROWS 384
#define WELEMS (WROWS * HN)

// ---------------- scratch ----------------------------------------------------
__device__ float g_eik [LPN];
__device__ float g_ekj [LHN];
__device__ float g_part [64 * 4096];
__device__ float g_part2[64 * 4096];
__device__ float g_split[16 * WELEMS + 2 * LPN * DN];

__device__ __nv_bfloat16 g_emb2s_h[M2 * DP],  g_emb2s_l[M2 * DP];
__device__ __nv_bfloat16 g_ths_h [M2 * HN],   g_ths_l [M2 * HN];
__device__ __nv_bfloat16 g_fs_h  [M2 * HN],   g_fs_l  [M2 * HN];
__device__ __nv_bfloat16 g_fpTs_h[HN * LPN],  g_fpTs_l[HN * LPN];
__device__ __nv_bfloat16 g_fhTs_h[LHN * HN],  g_fhTs_l[LHN * HN];
__device__ __nv_bfloat16 g_hTs_h[NROWS_PAD * LHN], g_hTs_l[NROWS_PAD * LHN];
__device__ __nv_bfloat16 g_pTs_h[NROWS_PAD * LPN], g_pTs_l[NROWS_PAD * LPN];
__device__ __nv_bfloat16 g_W1Ts_h[WELEMS], g_W1Ts_l[WELEMS];
__device__ __nv_bfloat16 g_W2Ts_h[WELEMS], g_W2Ts_l[WELEMS];
__device__ __nv_bfloat16 g_xs_h [M2 * D2P],   g_xs_l [M2 * D2P];
__device__ __nv_bfloat16 g_Wa1s_h[HN * DP],   g_Wa1s_l[HN * DP];
__device__ __nv_bfloat16 g_Wa2s_h[HN * HN],   g_Wa2s_l[HN * HN];
__device__ __nv_bfloat16 g_Wc1s_h[HN * D2P],  g_Wc1s_l[HN * D2P];
__device__ __nv_bfloat16 g_Wc2s_h[HN * HN],   g_Wc2s_l[HN * HN];

// ---------------- PTX helpers ------------------------------------------------
__device__ __forceinline__ uint32_t smem_u32(const void* p) {
    uint32_t a;
    asm("{ .reg .u64 t; cvta.to.shared.u64 t, %1; cvt.u32.u64 %0, t; }" : "=r"(a) : "l"(p));
    return a;
}
__device__ __forceinline__ void ldsm4(uint32_t& r0, uint32_t& r1, uint32_t& r2,
                                      uint32_t& r3, uint32_t addr) {
    asm volatile("ldmatrix.sync.aligned.m8n8.x4.shared.b16 {%0,%1,%2,%3}, [%4];"
                 : "=r"(r0), "=r"(r1), "=r"(r2), "=r"(r3) : "r"(addr));
}
__device__ __forceinline__ void mma16816(float* c, const uint32_t* a,
                                         const uint32_t b0, const uint32_t b1) {
    asm volatile(
        "mma.sync.aligned.m16n8k16.row.col.f32.bf16.bf16.f32 "
        "{%0,%1,%2,%3}, {%4,%5,%6,%7}, {%8,%9}, {%0,%1,%2,%3};"
        : "+f"(c[0]), "+f"(c[1]), "+f"(c[2]), "+f"(c[3])
        : "r"(a[0]), "r"(a[1]), "r"(a[2]), "r"(a[3]), "r"(b0), "r"(b1));
}
__device__ __forceinline__ void cvt_split(float x, __nv_bfloat16& hi, __nv_bfloat16& lo) {
    hi = __float2bfloat16(x);
    lo = __float2bfloat16(x - __bfloat162float(hi));
}
__device__ __forceinline__ uint32_t pack_bf2(__nv_bfloat16 a, __nv_bfloat16 b) {
    return (uint32_t)__bfloat16_as_ushort(a) | ((uint32_t)__bfloat16_as_ushort(b) << 16);
}
__device__ __forceinline__ void cp16(uint32_t dst, const void* src) {
    asm volatile("cp.async.cg.shared.global [%0], [%1], 16;"
                 :: "r"(dst), "l"(__cvta_generic_to_global(src)));
}
__device__ __forceinline__ void cp_commit() {
    asm volatile("cp.async.commit_group;");
}
template <int NN> __device__ __forceinline__ void cp_wait() {
    asm volatile("cp.async.wait_group %0;" :: "n"(NN));
}

#define STAGE_BYTES 30720

// ---------------- bf16x3 mma.sync SGEMM, 128x64 tile, 2-stage, 1 bar/chunk ---
__global__ __launch_bounds__(256, 3)
void bgemm(const __nv_bfloat16* __restrict__ Agh, const __nv_bfloat16* __restrict__ Agl, long ldA,
           const __nv_bfloat16* __restrict__ Bgh, const __nv_bfloat16* __restrict__ Bgl, long ldB,
           const __nv_bfloat16* __restrict__ A2gh, const __nv_bfloat16* __restrict__ A2gl,
           const __nv_bfloat16* __restrict__ B2gh, const __nv_bfloat16* __restrict__ B2gl,
           int zSecond,
           const float* __restrict__ bias,
           float* __restrict__ C, long ldc, long sliceStride,
           __nv_bfloat16* __restrict__ Chi, __nv_bfloat16* __restrict__ Clo, long ldS,
           __nv_bfloat16* __restrict__ Th, __nv_bfloat16* __restrict__ Tl, long ldT,
           __nv_bfloat16* __restrict__ Tph, __nv_bfloat16* __restrict__ Tpl, long ldTp,
           float* __restrict__ rowpart, float* __restrict__ colpart,
           int reshapeRow,
           int M, int N, int K, int kPerSlice, int relu) {
    extern __shared__ __align__(16) char smraw[];
    const int tid = threadIdx.x, lane = tid & 31, wid = tid >> 5;
    const int wm = wid >> 1, wn = wid & 1;
    const int m0 = blockIdx.y * 128, n0 = blockIdx.x * 64;
    const int zz = blockIdx.z;
    if (A2gh && zz >= zSecond) { Agh = A2gh; Agl = A2gl; Bgh = B2gh; Bgl = B2gl; }
    const int kbeg = (zz % zSecond) * kPerSlice;
    const int kend = min(K, kbeg + kPerSlice);
    const int nch = (kend - kbeg) >> 5;
    C += (long)zz * sliceStride;

    const uint32_t sb = smem_u32(smraw);

    float acc[2][4][4];
    #pragma unroll
    for (int i = 0; i < 2; i++)
        #pragma unroll
        for (int j = 0; j < 4; j++)
            #pragma unroll
            for (int e = 0; e < 4; e++) acc[i][j][e] = 0.f;

    const int lrow = (((lane >> 3) & 1) << 3) + (lane & 7);
    const int lcol = (lane >> 4) << 4;

    auto load_stage = [&](int st, int k0) {
        uint32_t sbase = sb + st * STAGE_BYTES;
        #pragma unroll
        for (int i = 0; i < 2; i++) {
            int c = tid + i * 256;
            int r = c >> 2, kq = c & 3;
            uint32_t dso = (uint32_t)(r * 80 + kq * 16);
            long ao = (long)(m0 + r) * ldA + k0 + kq * 8;
            cp16(sbase + dso,         Agh + ao);
            cp16(sbase + 10240 + dso, Agl + ao);
        }
        {
            int r = tid >> 2, kq = tid & 3;
            uint32_t dso = (uint32_t)(r * 80 + kq * 16);
            long bo = (long)(n0 + r) * ldB + k0 + kq * 8;
            cp16(sbase + 20480 + dso, Bgh + bo);
            cp16(sbase + 25600 + dso, Bgl + bo);
        }
    };

    load_stage(0, kbeg);
    cp_commit();

    int stage = 0;
    for (int i = 0; i < nch; i++) {
        cp_wait<0>();
        __syncthreads();
        if (i + 1 < nch) {
            load_stage(stage ^ 1, kbeg + (i + 1) * 32);
            cp_commit();
        }

        const uint32_t aAh = sb + stage * STAGE_BYTES;
        const uint32_t aAl = aAh + 10240;
        const uint32_t aBh = aAh + 20480;
        const uint32_t aBl = aAh + 25600;

        #pragma unroll
        for (int s = 0; s < 2; s++) {
            const int sbyte = s * 32;
            uint32_t ah[2][4], al[2][4], bh[2][4];
            #pragma unroll
            for (int mf = 0; mf < 2; mf++) {
                int row = wm * 32 + mf * 16 + lrow;
                ldsm4(ah[mf][0], ah[mf][1], ah[mf][2], ah[mf][3],
                      aAh + row * 80 + lcol + sbyte);
                ldsm4(al[mf][0], al[mf][1], al[mf][2], al[mf][3],
                      aAl + row * 80 + lcol + sbyte);
            }
            #pragma unroll
            for (int nf = 0; nf < 2; nf++) {
                int row = wn * 32 + nf * 16 + lrow;
                ldsm4(bh[nf][0], bh[nf][1], bh[nf][2], bh[nf][3],
                      aBh + row * 80 + lcol + sbyte);
            }
            #pragma unroll
            for (int nf = 0; nf < 2; nf++)
                #pragma unroll
                for (int j = 0; j < 2; j++)
                    #pragma unroll
                    for (int mf = 0; mf < 2; mf++)
                        mma16816(acc[mf][nf * 2 + j], ah[mf], bh[nf][j], bh[nf][j + 2]);
            #pragma unroll
            for (int nf = 0; nf < 2; nf++)
                #pragma unroll
                for (int j = 0; j < 2; j++)
                    #pragma unroll
                    for (int mf = 0; mf < 2; mf++)
                        mma16816(acc[mf][nf * 2 + j], al[mf], bh[nf][j], bh[nf][j + 2]);
            #pragma unroll
            for (int nf = 0; nf < 2; nf++) {
                int row = wn * 32 + nf * 16 + lrow;
                uint32_t bl[4];
                ldsm4(bl[0], bl[1], bl[2], bl[3], aBl + row * 80 + lcol + sbyte);
                #pragma unroll
                for (int j = 0; j < 2; j++)
                    #pragma unroll
                    for (int mf = 0; mf < 2; mf++)
                        mma16816(acc[mf][nf * 2 + j], ah[mf], bl[j], bl[j + 2]);
            }
        }
        stage ^= 1;
    }
    __syncthreads();

    // ---- bias/relu in-place ----
    const int tg = lane >> 2;
    const int tn = (lane & 3) << 1;
    if (bias || relu) {
        #pragma unroll
        for (int mf = 0; mf < 2; mf++)
            #pragma unroll
            for (int nfj = 0; nfj < 4; nfj++) {
                int n = n0 + (wn * 32 + nfj * 8 + tn);
                #pragma unroll
                for (int h2 = 0; h2 < 2; h2++) {
                    float vx = acc[mf][nfj][h2 * 2 + 0];
                    float vy = acc[mf][nfj][h2 * 2 + 1];
                    if (bias && n < N) { vx += bias[n]; vy += bias[n + 1]; }
                    if (relu) { vx = fmaxf(vx, 0.f); vy = fmaxf(vy, 0.f); }
                    acc[mf][nfj][h2 * 2 + 0] = vx;
                    acc[mf][nfj][h2 * 2 + 1] = vy;
                }
            }
    }

    const bool rsh = (reshapeRow >= 0);
    const bool isH = rsh && (m0 >= reshapeRow);

    if (C || Chi) {
        #pragma unroll
        for (int mf = 0; mf < 2; mf++) {
            #pragma unroll
            for (int h2 = 0; h2 < 2; h2++) {
                int m = m0 + wm * 32 + mf * 16 + h2 * 8 + tg;
                #pragma unroll
                for (int nfj = 0; nfj < 4; nfj++) {
                    int n = n0 + wn * 32 + nfj * 8 + tn;
                    if (n >= N) continue;
                    float2 v;
                    v.x = acc[mf][nfj][h2 * 2 + 0];
                    v.y = acc[mf][nfj][h2 * 2 + 1];
                    if (C) *(float2*)(C + (long)m * ldc + n) = v;
                    if (Chi) {
                        __nv_bfloat16 h0, l0, h1, l1;
                        cvt_split(v.x, h0, l0);
                        cvt_split(v.y, h1, l1);
                        long o = (long)m * ldS + n;
                        *(uint32_t*)(Chi + o) = pack_bf2(h0, h1);
                        *(uint32_t*)(Clo + o) = pack_bf2(l0, l1);
                    }
                }
            }
        }
    }

    const bool doResh = Th && rsh && isH;
    const bool doReg  = Tph && rsh && !isH;
    if (doResh || doReg || rowpart || colpart) {
        float* ts = (float*)smraw;             // [64][129]
        #pragma unroll
        for (int mf = 0; mf < 2; mf++) {
            #pragma unroll
            for (int h2 = 0; h2 < 2; h2++) {
                int ml = wm * 32 + mf * 16 + h2 * 8 + tg;
                #pragma unroll
                for (int nfj = 0; nfj < 4; nfj++) {
                    int nl = wn * 32 + nfj * 8 + tn;
                    ts[(nl + 0) * 129 + ml] = acc[mf][nfj][h2 * 2 + 0];
                    ts[(nl + 1) * 129 + ml] = acc[mf][nfj][h2 * 2 + 1];
                }
            }
        }
        __syncthreads();
        if (tid < 128 && rowpart) {
            float s = 0.f;
            #pragma unroll 8
            for (int n = 0; n < 64; n++) s += ts[n * 129 + tid];
            rowpart[(long)blockIdx.x * M + m0 + tid] = s;
        }
        if (tid < 64 && colpart) {
            float s2 = 0.f;
            #pragma unroll 8
            for (int m = 0; m < 128; m++) s2 += ts[tid * 129 + m];
            colpart[(long)blockIdx.y * N + n0 + tid] = s2;
        }
        if (doResh) {
            long kb = (long)(m0 - reshapeRow) >> 3;
            for (int idx = tid; idx < 512; idx += 256) {
                int r8 = idx >> 6, nl = idx & 63;
                long j = (long)r8 * HN + n0 + nl;
                __align__(16) __nv_bfloat16 hb[16], lb[16];
                #pragma unroll
                for (int q = 0; q < 16; q++) {
                    __nv_bfloat16 hi, lo;
                    cvt_split(ts[nl * 129 + r8 + 8 * q], hi, lo);
                    hb[q] = hi; lb[q] = lo;
                }
                long o = j * ldT + kb;
                *(uint4*)(Th + o)     = *(uint4*)(hb);
                *(uint4*)(Th + o + 8) = *(uint4*)(hb + 8);
                *(uint4*)(Tl + o)     = *(uint4*)(lb);
                *(uint4*)(Tl + o + 8) = *(uint4*)(lb + 8);
            }
        }
        if (doReg) {
            for (int idx = tid; idx < 4096; idx += 256) {
                int n = idx >> 6, m2 = (idx & 63) << 1;
                __nv_bfloat16 h0, l0, h1, l1;
                cvt_split(ts[n * 129 + m2], h0, l0);
                cvt_split(ts[n * 129 + m2 + 1], h1, l1);
                long o = (long)(n0 + n) * ldTp + m0 + m2;
                *(uint32_t*)(Tph + o) = pack_bf2(h0, h1);
                *(uint32_t*)(Tpl + o) = pack_bf2(l0, l1);
            }
        }
    }
}

static const int BGEMM_SMEM = 2 * STAGE_BYTES;

// ---------------- weight splits -----------------------------------------------
__global__ void split_weights_kernel(const float* __restrict__ Wa1, const float* __restrict__ Wa2,
                                     const float* __restrict__ Wc1, const float* __restrict__ Wc2,
                                     __nv_bfloat16* __restrict__ a1h, __nv_bfloat16* __restrict__ a1l,
                                     __nv_bfloat16* __restrict__ a2h, __nv_bfloat16* __restrict__ a2l,
                                     __nv_bfloat16* __restrict__ c1h, __nv_bfloat16* __restrict__ c1l,
                                     __nv_bfloat16* __restrict__ c2h, __nv_bfloat16* __restrict__ c2l) {
    const long s1 = (long)HN * DP, s2 = (long)HN * HN, s3 = (long)HN * D2P, s4 = (long)HN * HN;
    long i = (long)blockIdx.x * blockDim.x + threadIdx.x;
    const float* src; __nv_bfloat16 *dh, *dl; int K, Kpad; long li;
    if (i < s1)                { src = Wa1; dh = a1h; dl = a1l; K = DN;     Kpad = DP;  li = i; }
    else if (i < s1 + s2)      { src = Wa2; dh = a2h; dl = a2l; K = HN;     Kpad = HN;  li = i - s1; }
    else if (i < s1 + s2 + s3) { src = Wc1; dh = c1h; dl = c1l; K = 2 * DN; Kpad = D2P; li = i - s1 - s2; }
    else if (i < s1 + s2 + s3 + s4) { src = Wc2; dh = c2h; dl = c2l; K = HN; Kpad = HN; li = i - s1 - s2 - s3; }
    else return;
    int m = (int)(li / Kpad), k = (int)(li % Kpad);
    float v = (k < K) ? src[(long)m * K + k] : 0.f;
    __nv_bfloat16 hi, lo;
    cvt_split(v, hi, lo);
    dh[li] = hi; dl[li] = lo;
}

// ---------------- fused gather + split-pad + xs fill ---------------------------
__global__ void gather_split_kernel(const float* __restrict__ emb,
                                    const int* __restrict__ p_idx,
                                    const int* __restrict__ h_idx,
                                    __nv_bfloat16* __restrict__ e_h,
                                    __nv_bfloat16* __restrict__ e_l,
                                    __nv_bfloat16* __restrict__ x_h,
                                    __nv_bfloat16* __restrict__ x_l) {
    int r = blockIdx.x;
    long src = (r < LPN) ? p_idx[r] : h_idx[r - LPN];
    const float* s = emb + src * (long)DN;
    for (int c = threadIdx.x; c < DP; c += blockDim.x) {
        float v = (c < DN) ? s[c] : 0.f;
        __nv_bfloat16 hi, lo;
        cvt_split(v, hi, lo);
        long eo = (long)r * DP + c;
        e_h[eo] = hi; e_l[eo] = lo;
        if (c < DN) {
            long xo = (long)r * D2P + c;
            x_h[xo] = hi; x_l[xo] = lo;
        }
    }
    for (int c = 2 * DN + threadIdx.x; c < D2P; c += blockDim.x) {
        long xo = (long)r * D2P + c;
        x_h[xo] = __float2bfloat16(0.f);
        x_l[xo] = __float2bfloat16(0.f);
    }
}

// ---------------- gathered transpose + split (reads emb via idx) ---------------
__global__ void gtranspose_split2_kernel(const float* __restrict__ emb,
                                         const int* __restrict__ p_idx,
                                         __nv_bfloat16* __restrict__ dhA, __nv_bfloat16* __restrict__ dlA,
                                         const int* __restrict__ h_idx,
                                         __nv_bfloat16* __restrict__ dhB, __nv_bfloat16* __restrict__ dlB,
                                         int R, int C, int dR) {
    const int* idx = blockIdx.z ? h_idx : p_idx;
    __nv_bfloat16* dh = blockIdx.z ? dhB : dhA;
    __nv_bfloat16* dl = blockIdx.z ? dlB : dlA;
    __shared__ float tile[32][33];
    int c0 = blockIdx.x * 32, r0 = blockIdx.y * 32;
    int x = threadIdx.x, y = threadIdx.y;
    #pragma unroll
    for (int i = y; i < 32; i += 8) {
        int r = r0 + i, c = c0 + x;
        tile[i][x] = (r < R && c < C) ? emb[(long)idx[r] * DN + c] : 0.f;
    }
    __syncthreads();
    #pragma unroll
    for (int i = y; i < 32; i += 8) {
        int dr = c0 + i, dc = r0 + x;
        if (dr < dR && dc < R) {
            __nv_bfloat16 hi, lo;
            cvt_split(tile[x][i], hi, lo);
            dh[(long)dr * R + dc] = hi;
            dl[(long)dr * R + dc] = lo;
        }
    }
}

// ---------------- W slice reduce + split ----------------------------------------
__global__ void wreduce_kernel(const float* __restrict__ slices,
                               __nv_bfloat16* __restrict__ w1h, __nv_bfloat16* __restrict__ w1l,
                               __nv_bfloat16* __restrict__ w2h, __nv_bfloat16* __restrict__ w2l) {
    int i = blockIdx.x * blockDim.x + threadIdx.x;
    if (i >= WELEMS) return;
    int which = blockIdx.y;
    const float* base = slices + (long)which * 8 * WELEMS + i;
    float s = 0.f;
    #pragma unroll
    for (int p = 0; p < 8; p++) s += base[(long)p * WELEMS];
    __nv_bfloat16 hi, lo;
    cvt_split(s, hi, lo);
    if (which) { w2h[i] = hi; w2l[i] = lo; }
    else       { w1h[i] = hi; w1l[i] = lo; }
}

// ---------------- reduce + rowdiv + fused concat (dual) -------------------------
__global__ void splitk_concat2_kernel(const float* __restrict__ partA, const float* __restrict__ rdA,
                                      float* __restrict__ CA,
                                      const float* __restrict__ partB, const float* __restrict__ rdB,
                                      float* __restrict__ CB,
                                      __nv_bfloat16* __restrict__ xh, __nv_bfloat16* __restrict__ xl,
                                      int M, int N, int S) {
    const float* part = blockIdx.y ? partB : partA;
    const float* rowdiv = blockIdx.y ? rdB : rdA;
    float* C = blockIdx.y ? CB : CA;
    long xRowOff = blockIdx.y ? (long)M : 0;
    long i = (long)blockIdx.x * blockDim.x + threadIdx.x;
    long total = (long)M * N;
    if (i >= total) return;
    int m = (int)(i / N), n = (int)(i % N);
    float s = 0.f;
    for (int p = 0; p < S; p++) s += part[(long)p * total + i];
    float v = s / rowdiv[m];
    C[(long)m * N + n] = v;
    __nv_bfloat16 hi, lo;
    cvt_split(v, hi, lo);
    long o = (xRowOff + m) * (long)D2P + DN + n;
    xh[o] = hi; xl[o] = lo;
}

// ---------------- dual column reduce --------------------------------------------
__global__ void colsum_reduce2_kernel(const float* __restrict__ partA, float* __restrict__ outA, int PA,
                                      const float* __restrict__ partB, float* __restrict__ outB, int PB,
                                      int C) {
    const float* part = blockIdx.y ? partB : partA;
    float* out = blockIdx.y ? outB : outA;
    int P = blockIdx.y ? PB : PA;
    int c = blockIdx.x * blockDim.x + threadIdx.x;
    if (c >= C) return;
    float s = 0.f;
    for (int p = 0; p < P; p++) s += part[(long)p * C + c];
    out[c] = s;
}

// ---------------- final head -----------------------------------------------------
__global__ void head_kernel(const float* __restrict__ v,
                            const float* __restrict__ Wg1, const float* __restrict__ bg1,
                            const float* __restrict__ Wg2, const float* __restrict__ bg2,
                            const float* __restrict__ Wg3, const float* __restrict__ bg3,
                            float* __restrict__ y) {
    __shared__ float sv[2 * HN];
    __shared__ float y1[HN];
    __shared__ float y2[HN];
    __shared__ float logit[3];
    int t = threadIdx.x;
    sv[t] = v[t];
    sv[t + HN] = v[t + HN];
    __syncthreads();
    {
        float acc = bg1[t];
        const float* w = Wg1 + (long)t * (2 * HN);
        for (int k = 0; k < 2 * HN; k++) acc += sv[k] * w[k];
        y1[t] = fmaxf(acc, 0.f);
    }
    __syncthreads();
    {
        float acc = bg2[t];
        const float* w = Wg2 + (long)t * HN;
        for (int k = 0; k < HN; k++) acc += y1[k] * w[k];
        y2[t] = fmaxf(acc, 0.f);
    }
    __syncthreads();
    if (t < 3) {
        float a = bg3[t];
        const float* w = Wg3 + (long)t * HN;
        for (int k = 0; k < HN; k++) a += y2[k] * w[k];
        logit[t] = a;
    }
    __syncthreads();
    if (t == 0) {
        float m = fmaxf(logit[0], fmaxf(logit[1], logit[2]));
        float e0 = expf(logit[0] - m), e1 = expf(logit[1] - m), e2 = expf(logit[2] - m);
        float s = e0 + e1 + e2;
        y[0] = e0 / s; y[1] = e1 / s; y[2] = e2 / s;
    }
}

// ---------------- host dispatch ---------------------------------------------------
struct BArgs {
    const __nv_bfloat16 *Ah, *Al; long ldA;
    const __nv_bfloat16 *Bh, *Bl; long ldB;
    const __nv_bfloat16 *A2h = nullptr, *A2l = nullptr, *B2h = nullptr, *B2l = nullptr;
    const float* bias = nullptr;
    float* C = nullptr; long ldc = 0; long sliceStride = 0;
    __nv_bfloat16 *Chi = nullptr, *Clo = nullptr; long ldS = 0;
    __nv_bfloat16 *Th = nullptr, *Tl = nullptr; long ldT = 0;
    __nv_bfloat16 *Tph = nullptr, *Tpl = nullptr; long ldTp = 0;
    float *rowpart = nullptr, *colpart = nullptr;
    int reshapeRow = -1;
    int M, N, K, splits = 1, zTotal = 0, relu = 0;
};

static void launch_bgemm(const BArgs& a, cudaStream_t st) {
    cudaFuncSetAttribute(bgemm, cudaFuncAttributeMaxDynamicSharedMemorySize, BGEMM_SMEM);
    int kps = (a.K + a.splits - 1) / a.splits;
    kps = ((kps + 31) / 32) * 32;
    int zt = a.zTotal ? a.zTotal : a.splits;
    dim3 grid((a.N + 63) / 64, a.M / 128, zt);
    bgemm<<<grid, 256, BGEMM_SMEM, st>>>(a.Ah, a.Al, a.ldA, a.Bh, a.Bl, a.ldB,
                                         a.A2h, a.A2l, a.B2h, a.B2l, a.splits,
                                         a.bias, a.C, a.ldc, a.sliceStride,
                                         a.Chi, a.Clo, a.ldS,
                                         a.Th, a.Tl, a.ldT,
                                         a.Tph, a.Tpl, a.ldTp,
                                         a.rowpart, a.colpart, a.reshapeRow,
                                         a.M, a.N, a.K, kps, a.relu);
}

#define GETSYM(var, sym) cudaGetSymbolAddress((void**)&var, sym)

extern "C" void kernel_launch(void* const* d_in, const int* in_sizes, int n_in,
                              void* d_out, int out_size) {
    // side stream + fork/join events, created once on first (non-captured) call
    static cudaStream_t s2 = nullptr;
    static cudaEvent_t evFork = nullptr, evJoin = nullptr;
    if (!s2) {
        cudaStreamCreateWithFlags(&s2, cudaStreamNonBlocking);
        cudaEventCreateWithFlags(&evFork, cudaEventDisableTiming);
        cudaEventCreateWithFlags(&evJoin, cudaEventDisableTiming);
    }

    const int*   p_idx = (const int*)  d_in[0];
    const int*   h_idx = (const int*)  d_in[1];
    const float* emb   = (const float*)d_in[2];
    const float* W_a1  = (const float*)d_in[3];
    const float* b_a1  = (const float*)d_in[4];
    const float* W_a2  = (const float*)d_in[5];
    const float* b_a2  = (const float*)d_in[6];
    const float* W_c1  = (const float*)d_in[7];
    const float* b_c1  = (const float*)d_in[8];
    const float* W_c2  = (const float*)d_in[9];
    const float* b_c2  = (const float*)d_in[10];
    const float* W_g1  = (const float*)d_in[11];
    const float* b_g1  = (const float*)d_in[12];
    const float* W_g2  = (const float*)d_in[13];
    const float* b_g2  = (const float*)d_in[14];
    const float* W_g3  = (const float*)d_in[15];
    const float* b_g3  = (const float*)d_in[16];

    float* out = (float*)d_out;
    const long E_OFF    = 0;
    const long BETA_OFF = (long)LPN * LHN;
    const long ALPHA_OFF= BETA_OFF + (long)LPN * DN;
    const long V1_OFF   = ALPHA_OFF + (long)LHN * DN;
    const long V2_OFF   = V1_OFF + HN;
    const long Y_OFF    = V2_OFF + HN;

    float *eik, *ekj, *part, *part2, *split;
    GETSYM(eik, g_eik); GETSYM(ekj, g_ekj);
    GETSYM(part, g_part); GETSYM(part2, g_part2); GETSYM(split, g_split);

    __nv_bfloat16 *emb2s_h, *emb2s_l, *ths_h, *ths_l, *fs_h, *fs_l;
    __nv_bfloat16 *fpTs_h, *fpTs_l, *fhTs_h, *fhTs_l;
    __nv_bfloat16 *hTs_h, *hTs_l, *pTs_h, *pTs_l;
    __nv_bfloat16 *W1Ts_h, *W1Ts_l, *W2Ts_h, *W2Ts_l, *xs_h, *xs_l;
    __nv_bfloat16 *Wa1s_h, *Wa1s_l, *Wa2s_h, *Wa2s_l, *Wc1s_h, *Wc1s_l, *Wc2s_h, *Wc2s_l;
    GETSYM(emb2s_h, g_emb2s_h); GETSYM(emb2s_l, g_emb2s_l);
    GETSYM(ths_h, g_ths_h);     GETSYM(ths_l, g_ths_l);
    GETSYM(fs_h, g_fs_h);       GETSYM(fs_l, g_fs_l);
    GETSYM(fpTs_h, g_fpTs_h);   GETSYM(fpTs_l, g_fpTs_l);
    GETSYM(fhTs_h, g_fhTs_h);   GETSYM(fhTs_l, g_fhTs_l);
    GETSYM(hTs_h, g_hTs_h);     GETSYM(hTs_l, g_hTs_l);
    GETSYM(pTs_h, g_pTs_h);     GETSYM(pTs_l, g_pTs_l);
    GETSYM(W1Ts_h, g_W1Ts_h);   GETSYM(W1Ts_l, g_W1Ts_l);
    GETSYM(W2Ts_h, g_W2Ts_h);   GETSYM(W2Ts_l, g_W2Ts_l);
    GETSYM(xs_h, g_xs_h);       GETSYM(xs_l, g_xs_l);
    GETSYM(Wa1s_h, g_Wa1s_h);   GETSYM(Wa1s_l, g_Wa1s_l);
    GETSYM(Wa2s_h, g_Wa2s_h);   GETSYM(Wa2s_l, g_Wa2s_l);
    GETSYM(Wc1s_h, g_Wc1s_h);   GETSYM(Wc1s_l, g_Wc1s_l);
    GETSYM(Wc2s_h, g_Wc2s_h);   GETSYM(Wc2s_l, g_Wc2s_l);

    // 0) weight splits + gather + embedding transposes (all before attend)
    {
        long total = (long)HN * (DP + HN + D2P + HN);
        split_weights_kernel<<<(int)((total + 255) / 256), 256>>>(
            W_a1, W_a2, W_c1, W_c2,
            Wa1s_h, Wa1s_l, Wa2s_h, Wa2s_l, Wc1s_h, Wc1s_l, Wc2s_h, Wc2s_l);
    }
    gather_split_kernel<<<M2, 128>>>(emb, p_idx, h_idx, emb2s_h, emb2s_l, xs_h, xs_l);
    {
        dim3 b(32, 8);
        dim3 g((NROWS_PAD + 31) / 32, (LPN + 31) / 32, 2);
        gtranspose_split2_kernel<<<g, b>>>(emb, p_idx, pTs_h, pTs_l,
                                           h_idx, hTs_h, hTs_l, LPN, DN, NROWS_PAD);
    }

    // 1) attend1
    {
        BArgs a{emb2s_h, emb2s_l, DP, Wa1s_h, Wa1s_l, DP};
        a.bias = b_a1; a.Chi = ths_h; a.Clo = ths_l; a.ldS = HN;
        a.M = M2; a.N = HN; a.K = DP; a.relu = 1;
        launch_bgemm(a, 0);
    }
    // 2) attend2: Chi=fs, h-tiles -> fhTs (reshape T), p-tiles -> fpTs (regular T)
    {
        BArgs a{ths_h, ths_l, HN, Wa2s_h, Wa2s_l, HN};
        a.bias = b_a2;
        a.Chi = fs_h; a.Clo = fs_l; a.ldS = HN;
        a.Th = fhTs_h; a.Tl = fhTs_l; a.ldT = HN;
        a.Tph = fpTs_h; a.Tpl = fpTs_l; a.ldTp = LPN;
        a.reshapeRow = LPN;
        a.M = M2; a.N = HN; a.K = HN; a.relu = 1;
        launch_bgemm(a, 0);
    }

    // ---- FORK: side stream computes W1/W2 while main computes E ----
    cudaEventRecord(evFork, 0);
    cudaStreamWaitEvent(s2, evFork, 0);

    // 3a) [s2] W1T = hT @ fhR^T ; W2T = pT @ fpT^T  (dual, split-K x8)
    {
        BArgs a{hTs_h, hTs_l, LHN, fs_h + (long)LPN * HN, fs_l + (long)LPN * HN, LHN};
        a.A2h = pTs_h; a.A2l = pTs_l; a.B2h = fpTs_h; a.B2l = fpTs_l;
        a.C = split; a.ldc = HN; a.sliceStride = WELEMS;
        a.M = WROWS; a.N = HN; a.K = LHN; a.splits = 8; a.zTotal = 16;
        launch_bgemm(a, s2);
    }
    {
        dim3 g((WELEMS + 255) / 256, 2);
        wreduce_kernel<<<g, 256, 0, s2>>>(split, W1Ts_h, W1Ts_l, W2Ts_h, W2Ts_l);
    }
    cudaEventRecord(evJoin, s2);

    // 3b) [main] E = fp @ fhR with fused row/col partials
    {
        BArgs a{fs_h, fs_l, HN, fhTs_h, fhTs_l, HN};
        a.C = out + E_OFF; a.ldc = LHN;
        a.rowpart = part; a.colpart = part2;
        a.M = LPN; a.N = LHN; a.K = HN;
        launch_bgemm(a, 0);
    }
    {
        dim3 g((LPN + 255) / 256, 2);
        colsum_reduce2_kernel<<<g, 256>>>(part, eik, 64, part2, ekj, 32, LPN);
    }

    // ---- JOIN ----
    cudaStreamWaitEvent(0, evJoin, 0);

    // 4) beta_raw = fp @ W1 ; alpha_raw = fhT @ W2  (dual, K=512)
    float* baRaw = split + 16L * WELEMS;
    {
        BArgs a{fs_h, fs_l, HN, W1Ts_h, W1Ts_l, HN};
        a.A2h = fhTs_h; a.A2l = fhTs_l; a.B2h = W2Ts_h; a.B2l = W2Ts_l;
        a.C = baRaw; a.ldc = DN; a.sliceStride = (long)LPN * DN;
        a.M = LPN; a.N = DN; a.K = HN; a.splits = 1; a.zTotal = 2;
        launch_bgemm(a, 0);
    }
    {
        dim3 g((int)(((long)LPN * DN + 255) / 256), 2);
        splitk_concat2_kernel<<<g, 256>>>(baRaw, eik, out + BETA_OFF,
                                          baRaw + (long)LPN * DN, ekj, out + ALPHA_OFF,
                                          xs_h, xs_l, LPN, DN, 1);
    }

    // 5) comp (batched), colsums fused into comp2
    {
        BArgs a{xs_h, xs_l, D2P, Wc1s_h, Wc1s_l, D2P};
        a.bias = b_c1; a.Chi = ths_h; a.Clo = ths_l; a.ldS = HN;
        a.M = M2; a.N = HN; a.K = D2P; a.relu = 1;
        launch_bgemm(a, 0);
    }
    {
        BArgs a{ths_h, ths_l, HN, Wc2s_h, Wc2s_l, HN};
        a.bias = b_c2; a.colpart = part;
        a.M = M2; a.N = HN; a.K = HN; a.relu = 1;
        launch_bgemm(a, 0);
    }
    {
        dim3 g((HN + 255) / 256, 2);
        colsum_reduce2_kernel<<<g, 256>>>(part, out + V1_OFF, 32,
                                          part + 32 * HN, out + V2_OFF, 32, HN);
    }

    // 6) head
    head_kernel<<<1, HN>>>(out + V1_OFF, W_g1, b_g1, W_g2, b_g2, W_g3, b_g3, out + Y_OFF);

    (void)in_sizes; (void)n_in; (void)out_size;
}

// round 15
// speedup vs baseline: 1.3223x; 1.0068x over previous
#include <cuda_runtime.h>
#include <cuda_bf16.h>
#include <cstdint>
#include <cmath>

#define LPN 4096
#define LHN 4096
#define DN  300
#define HN  512
#define DP  320
#define XK  320          // per-half K width for comp1
#define NROWS_PAD 384
#define M2  8192
#define WROWS 384
#define WELEMS (WROWS * HN)

// ---------------- scratch ----------------------------------------------------
__device__ float g_eik [LPN];
__device__ float g_ekj [LHN];
__device__ float g_part [64 * 4096];
__device__ float g_part2[64 * 4096];
__device__ float g_split[16 * WELEMS + 2 * LPN * DN];
__device__ float g_csl  [(long)M2 * HN];             // comp1 emb-half partial (fp32)

__device__ __nv_bfloat16 g_emb2s_h[M2 * DP],  g_emb2s_l[M2 * DP];
__device__ __nv_bfloat16 g_xb_h  [M2 * XK],   g_xb_l  [M2 * XK];   // beta|alpha half
__device__ __nv_bfloat16 g_ths_h [M2 * HN],   g_ths_l [M2 * HN];
__device__ __nv_bfloat16 g_fs_h  [M2 * HN],   g_fs_l  [M2 * HN];
__device__ __nv_bfloat16 g_fpTs_h[HN * LPN],  g_fpTs_l[HN * LPN];
__device__ __nv_bfloat16 g_fhTs_h[LHN * HN],  g_fhTs_l[LHN * HN];
__device__ __nv_bfloat16 g_hTs_h[NROWS_PAD * LHN], g_hTs_l[NROWS_PAD * LHN];
__device__ __nv_bfloat16 g_pTs_h[NROWS_PAD * LPN], g_pTs_l[NROWS_PAD * LPN];
__device__ __nv_bfloat16 g_W1Ts_h[WELEMS], g_W1Ts_l[WELEMS];
__device__ __nv_bfloat16 g_W2Ts_h[WELEMS], g_W2Ts_l[WELEMS];
__device__ __nv_bfloat16 g_Wa1s_h[HN * DP],   g_Wa1s_l[HN * DP];
__device__ __nv_bfloat16 g_Wa2s_h[HN * HN],   g_Wa2s_l[HN * HN];
__device__ __nv_bfloat16 g_Wc1a_h[HN * XK],   g_Wc1a_l[HN * XK];   // cols 0..299
__device__ __nv_bfloat16 g_Wc1b_h[HN * XK],   g_Wc1b_l[HN * XK];   // cols 300..599
__device__ __nv_bfloat16 g_Wc2s_h[HN * HN],   g_Wc2s_l[HN * HN];

// ---------------- PTX helpers ------------------------------------------------
__device__ __forceinline__ uint32_t smem_u32(const void* p) {
    uint32_t a;
    asm("{ .reg .u64 t; cvta.to.shared.u64 t, %1; cvt.u32.u64 %0, t; }" : "=r"(a) : "l"(p));
    return a;
}
__device__ __forceinline__ void ldsm4(uint32_t& r0, uint32_t& r1, uint32_t& r2,
                                      uint32_t& r3, uint32_t addr) {
    asm volatile("ldmatrix.sync.aligned.m8n8.x4.shared.b16 {%0,%1,%2,%3}, [%4];"
                 : "=r"(r0), "=r"(r1), "=r"(r2), "=r"(r3) : "r"(addr));
}
__device__ __forceinline__ void mma16816(float* c, const uint32_t* a,
                                         const uint32_t b0, const uint32_t b1) {
    asm volatile(
        "mma.sync.aligned.m16n8k16.row.col.f32.bf16.bf16.f32 "
        "{%0,%1,%2,%3}, {%4,%5,%6,%7}, {%8,%9}, {%0,%1,%2,%3};"
        : "+f"(c[0]), "+f"(c[1]), "+f"(c[2]), "+f"(c[3])
        : "r"(a[0]), "r"(a[1]), "r"(a[2]), "r"(a[3]), "r"(b0), "r"(b1));
}
__device__ __forceinline__ void cvt_split(float x, __nv_bfloat16& hi, __nv_bfloat16& lo) {
    hi = __float2bfloat16(x);
    lo = __float2bfloat16(x - __bfloat162float(hi));
}
__device__ __forceinline__ uint32_t pack_bf2(__nv_bfloat16 a, __nv_bfloat16 b) {
    return (uint32_t)__bfloat16_as_ushort(a) | ((uint32_t)__bfloat16_as_ushort(b) << 16);
}
__device__ __forceinline__ void cp16(uint32_t dst, const void* src) {
    asm volatile("cp.async.cg.shared.global [%0], [%1], 16;"
                 :: "r"(dst), "l"(__cvta_generic_to_global(src)));
}
__device__ __forceinline__ void cp_commit() {
    asm volatile("cp.async.commit_group;");
}
template <int NN> __device__ __forceinline__ void cp_wait() {
    asm volatile("cp.async.wait_group %0;" :: "n"(NN));
}

#define STAGE_BYTES 30720

// ---------------- bf16x3 mma.sync SGEMM, 128x64 tile, 2-stage, 1 bar/chunk ---
__global__ __launch_bounds__(256, 3)
void bgemm(const __nv_bfloat16* __restrict__ Agh, const __nv_bfloat16* __restrict__ Agl, long ldA,
           const __nv_bfloat16* __restrict__ Bgh, const __nv_bfloat16* __restrict__ Bgl, long ldB,
           const __nv_bfloat16* __restrict__ A2gh, const __nv_bfloat16* __restrict__ A2gl,
           const __nv_bfloat16* __restrict__ B2gh, const __nv_bfloat16* __restrict__ B2gl,
           int zSecond,
           const float* __restrict__ bias,
           const float* __restrict__ Cadd, long ldAdd,
           float* __restrict__ C, long ldc, long sliceStride,
           __nv_bfloat16* __restrict__ Chi, __nv_bfloat16* __restrict__ Clo, long ldS,
           __nv_bfloat16* __restrict__ Th, __nv_bfloat16* __restrict__ Tl, long ldT,
           __nv_bfloat16* __restrict__ Tph, __nv_bfloat16* __restrict__ Tpl, long ldTp,
           float* __restrict__ rowpart, float* __restrict__ colpart,
           int reshapeRow,
           int M, int N, int K, int kPerSlice, int relu) {
    extern __shared__ __align__(16) char smraw[];
    const int tid = threadIdx.x, lane = tid & 31, wid = tid >> 5;
    const int wm = wid >> 1, wn = wid & 1;
    const int m0 = blockIdx.y * 128, n0 = blockIdx.x * 64;
    const int zz = blockIdx.z;
    if (A2gh && zz >= zSecond) { Agh = A2gh; Agl = A2gl; Bgh = B2gh; Bgl = B2gl; }
    const int kbeg = (zz % zSecond) * kPerSlice;
    const int kend = min(K, kbeg + kPerSlice);
    const int nch = (kend - kbeg) >> 5;
    C += (long)zz * sliceStride;

    const uint32_t sb = smem_u32(smraw);

    float acc[2][4][4];
    #pragma unroll
    for (int i = 0; i < 2; i++)
        #pragma unroll
        for (int j = 0; j < 4; j++)
            #pragma unroll
            for (int e = 0; e < 4; e++) acc[i][j][e] = 0.f;

    const int lrow = (((lane >> 3) & 1) << 3) + (lane & 7);
    const int lcol = (lane >> 4) << 4;

    auto load_stage = [&](int st, int k0) {
        uint32_t sbase = sb + st * STAGE_BYTES;
        #pragma unroll
        for (int i = 0; i < 2; i++) {
            int c = tid + i * 256;
            int r = c >> 2, kq = c & 3;
            uint32_t dso = (uint32_t)(r * 80 + kq * 16);
            long ao = (long)(m0 + r) * ldA + k0 + kq * 8;
            cp16(sbase + dso,         Agh + ao);
            cp16(sbase + 10240 + dso, Agl + ao);
        }
        {
            int r = tid >> 2, kq = tid & 3;
            uint32_t dso = (uint32_t)(r * 80 + kq * 16);
            long bo = (long)(n0 + r) * ldB + k0 + kq * 8;
            cp16(sbase + 20480 + dso, Bgh + bo);
            cp16(sbase + 25600 + dso, Bgl + bo);
        }
    };

    load_stage(0, kbeg);
    cp_commit();

    int stage = 0;
    for (int i = 0; i < nch; i++) {
        cp_wait<0>();
        __syncthreads();
        if (i + 1 < nch) {
            load_stage(stage ^ 1, kbeg + (i + 1) * 32);
            cp_commit();
        }

        const uint32_t aAh = sb + stage * STAGE_BYTES;
        const uint32_t aAl = aAh + 10240;
        const uint32_t aBh = aAh + 20480;
        const uint32_t aBl = aAh + 25600;

        #pragma unroll
        for (int s = 0; s < 2; s++) {
            const int sbyte = s * 32;
            uint32_t ah[2][4], al[2][4], bh[2][4];
            #pragma unroll
            for (int mf = 0; mf < 2; mf++) {
                int row = wm * 32 + mf * 16 + lrow;
                ldsm4(ah[mf][0], ah[mf][1], ah[mf][2], ah[mf][3],
                      aAh + row * 80 + lcol + sbyte);
                ldsm4(al[mf][0], al[mf][1], al[mf][2], al[mf][3],
                      aAl + row * 80 + lcol + sbyte);
            }
            #pragma unroll
            for (int nf = 0; nf < 2; nf++) {
                int row = wn * 32 + nf * 16 + lrow;
                ldsm4(bh[nf][0], bh[nf][1], bh[nf][2], bh[nf][3],
                      aBh + row * 80 + lcol + sbyte);
            }
            #pragma unroll
            for (int nf = 0; nf < 2; nf++)
                #pragma unroll
                for (int j = 0; j < 2; j++)
                    #pragma unroll
                    for (int mf = 0; mf < 2; mf++)
                        mma16816(acc[mf][nf * 2 + j], ah[mf], bh[nf][j], bh[nf][j + 2]);
            #pragma unroll
            for (int nf = 0; nf < 2; nf++)
                #pragma unroll
                for (int j = 0; j < 2; j++)
                    #pragma unroll
                    for (int mf = 0; mf < 2; mf++)
                        mma16816(acc[mf][nf * 2 + j], al[mf], bh[nf][j], bh[nf][j + 2]);
            #pragma unroll
            for (int nf = 0; nf < 2; nf++) {
                int row = wn * 32 + nf * 16 + lrow;
                uint32_t bl[4];
                ldsm4(bl[0], bl[1], bl[2], bl[3], aBl + row * 80 + lcol + sbyte);
                #pragma unroll
                for (int j = 0; j < 2; j++)
                    #pragma unroll
                    for (int mf = 0; mf < 2; mf++)
                        mma16816(acc[mf][nf * 2 + j], ah[mf], bl[j], bl[j + 2]);
            }
        }
        stage ^= 1;
    }
    __syncthreads();

    // ---- Cadd/bias/relu in-place ----
    const int tg = lane >> 2;
    const int tn = (lane & 3) << 1;
    if (Cadd || bias || relu) {
        #pragma unroll
        for (int mf = 0; mf < 2; mf++)
            #pragma unroll
            for (int h2 = 0; h2 < 2; h2++) {
                int m = m0 + wm * 32 + mf * 16 + h2 * 8 + tg;
                #pragma unroll
                for (int nfj = 0; nfj < 4; nfj++) {
                    int n = n0 + (wn * 32 + nfj * 8 + tn);
                    float vx = acc[mf][nfj][h2 * 2 + 0];
                    float vy = acc[mf][nfj][h2 * 2 + 1];
                    if (n < N) {
                        if (Cadd) {
                            float2 adv = *(const float2*)(Cadd + (long)m * ldAdd + n);
                            vx += adv.x; vy += adv.y;
                        }
                        if (bias) { vx += bias[n]; vy += bias[n + 1]; }
                    }
                    if (relu) { vx = fmaxf(vx, 0.f); vy = fmaxf(vy, 0.f); }
                    acc[mf][nfj][h2 * 2 + 0] = vx;
                    acc[mf][nfj][h2 * 2 + 1] = vy;
                }
            }
    }

    const bool rsh = (reshapeRow >= 0);
    const bool isH = rsh && (m0 >= reshapeRow);

    if (C || Chi) {
        #pragma unroll
        for (int mf = 0; mf < 2; mf++) {
            #pragma unroll
            for (int h2 = 0; h2 < 2; h2++) {
                int m = m0 + wm * 32 + mf * 16 + h2 * 8 + tg;
                #pragma unroll
                for (int nfj = 0; nfj < 4; nfj++) {
                    int n = n0 + wn * 32 + nfj * 8 + tn;
                    if (n >= N) continue;
                    float2 v;
                    v.x = acc[mf][nfj][h2 * 2 + 0];
                    v.y = acc[mf][nfj][h2 * 2 + 1];
                    if (C) *(float2*)(C + (long)m * ldc + n) = v;
                    if (Chi) {
                        __nv_bfloat16 h0, l0, h1, l1;
                        cvt_split(v.x, h0, l0);
                        cvt_split(v.y, h1, l1);
                        long o = (long)m * ldS + n;
                        *(uint32_t*)(Chi + o) = pack_bf2(h0, h1);
                        *(uint32_t*)(Clo + o) = pack_bf2(l0, l1);
                    }
                }
            }
        }
    }

    const bool doResh = Th && rsh && isH;
    const bool doReg  = Tph && rsh && !isH;
    if (doResh || doReg || rowpart || colpart) {
        float* ts = (float*)smraw;             // [64][129]
        #pragma unroll
        for (int mf = 0; mf < 2; mf++) {
            #pragma unroll
            for (int h2 = 0; h2 < 2; h2++) {
                int ml = wm * 32 + mf * 16 + h2 * 8 + tg;
                #pragma unroll
                for (int nfj = 0; nfj < 4; nfj++) {
                    int nl = wn * 32 + nfj * 8 + tn;
                    ts[(nl + 0) * 129 + ml] = acc[mf][nfj][h2 * 2 + 0];
                    ts[(nl + 1) * 129 + ml] = acc[mf][nfj][h2 * 2 + 1];
                }
            }
        }
        __syncthreads();
        if (tid < 128 && rowpart) {
            float s = 0.f;
            #pragma unroll 8
            for (int n = 0; n < 64; n++) s += ts[n * 129 + tid];
            rowpart[(long)blockIdx.x * M + m0 + tid] = s;
        }
        if (tid < 64 && colpart) {
            float s2 = 0.f;
            #pragma unroll 8
            for (int m = 0; m < 128; m++) s2 += ts[tid * 129 + m];
            colpart[(long)blockIdx.y * N + n0 + tid] = s2;
        }
        if (doResh) {
            long kb = (long)(m0 - reshapeRow) >> 3;
            for (int idx = tid; idx < 512; idx += 256) {
                int r8 = idx >> 6, nl = idx & 63;
                long j = (long)r8 * HN + n0 + nl;
                __align__(16) __nv_bfloat16 hb[16], lb[16];
                #pragma unroll
                for (int q = 0; q < 16; q++) {
                    __nv_bfloat16 hi, lo;
                    cvt_split(ts[nl * 129 + r8 + 8 * q], hi, lo);
                    hb[q] = hi; lb[q] = lo;
                }
                long o = j * ldT + kb;
                *(uint4*)(Th + o)     = *(uint4*)(hb);
                *(uint4*)(Th + o + 8) = *(uint4*)(hb + 8);
                *(uint4*)(Tl + o)     = *(uint4*)(lb);
                *(uint4*)(Tl + o + 8) = *(uint4*)(lb + 8);
            }
        }
        if (doReg) {
            for (int idx = tid; idx < 4096; idx += 256) {
                int n = idx >> 6, m2 = (idx & 63) << 1;
                __nv_bfloat16 h0, l0, h1, l1;
                cvt_split(ts[n * 129 + m2], h0, l0);
                cvt_split(ts[n * 129 + m2 + 1], h1, l1);
                long o = (long)(n0 + n) * ldTp + m0 + m2;
                *(uint32_t*)(Tph + o) = pack_bf2(h0, h1);
                *(uint32_t*)(Tpl + o) = pack_bf2(l0, l1);
            }
        }
    }
}

static const int BGEMM_SMEM = 2 * STAGE_BYTES;

// ---------------- weight splits (5 segments incl. Wc1 halves) -----------------
__global__ void split_weights_kernel(const float* __restrict__ Wa1, const float* __restrict__ Wa2,
                                     const float* __restrict__ Wc1, const float* __restrict__ Wc2,
                                     __nv_bfloat16* __restrict__ a1h, __nv_bfloat16* __restrict__ a1l,
                                     __nv_bfloat16* __restrict__ a2h, __nv_bfloat16* __restrict__ a2l,
                                     __nv_bfloat16* __restrict__ c1ah, __nv_bfloat16* __restrict__ c1al,
                                     __nv_bfloat16* __restrict__ c1bh, __nv_bfloat16* __restrict__ c1bl,
                                     __nv_bfloat16* __restrict__ c2h, __nv_bfloat16* __restrict__ c2l) {
    const long s1 = (long)HN * DP, s2 = (long)HN * HN;
    const long s3 = (long)HN * XK, s4 = (long)HN * XK, s5 = (long)HN * HN;
    long i = (long)blockIdx.x * blockDim.x + threadIdx.x;
    float v; __nv_bfloat16 *dh, *dl; long li;
    if (i < s1) {
        li = i; int m = (int)(li / DP), k = (int)(li % DP);
        v = (k < DN) ? Wa1[(long)m * DN + k] : 0.f; dh = a1h; dl = a1l;
    } else if (i < s1 + s2) {
        li = i - s1; int m = (int)(li / HN), k = (int)(li % HN);
        v = Wa2[(long)m * HN + k]; dh = a2h; dl = a2l;
    } else if (i < s1 + s2 + s3) {
        li = i - s1 - s2; int m = (int)(li / XK), k = (int)(li % XK);
        v = (k < DN) ? Wc1[(long)m * (2 * DN) + k] : 0.f; dh = c1ah; dl = c1al;
    } else if (i < s1 + s2 + s3 + s4) {
        li = i - s1 - s2 - s3; int m = (int)(li / XK), k = (int)(li % XK);
        v = (k < DN) ? Wc1[(long)m * (2 * DN) + DN + k] : 0.f; dh = c1bh; dl = c1bl;
    } else if (i < s1 + s2 + s3 + s4 + s5) {
        li = i - s1 - s2 - s3 - s4; int m = (int)(li / HN), k = (int)(li % HN);
        v = Wc2[(long)m * HN + k]; dh = c2h; dl = c2l;
    } else return;
    __nv_bfloat16 hi, lo;
    cvt_split(v, hi, lo);
    dh[li] = hi; dl[li] = lo;
}

// ---------------- fused gather + split-pad + xb pad zero ----------------------
__global__ void gather_split_kernel(const float* __restrict__ emb,
                                    const int* __restrict__ p_idx,
                                    const int* __restrict__ h_idx,
                                    __nv_bfloat16* __restrict__ e_h,
                                    __nv_bfloat16* __restrict__ e_l,
                                    __nv_bfloat16* __restrict__ xb_h,
                                    __nv_bfloat16* __restrict__ xb_l) {
    int r = blockIdx.x;
    long src = (r < LPN) ? p_idx[r] : h_idx[r - LPN];
    const float* s = emb + src * (long)DN;
    for (int c = threadIdx.x; c < DP; c += blockDim.x) {
        float v = (c < DN) ? s[c] : 0.f;
        __nv_bfloat16 hi, lo;
        cvt_split(v, hi, lo);
        long eo = (long)r * DP + c;
        e_h[eo] = hi; e_l[eo] = lo;
    }
    // zero xb pad columns [DN, XK)
    for (int c = DN + threadIdx.x; c < XK; c += blockDim.x) {
        long xo = (long)r * XK + c;
        xb_h[xo] = __float2bfloat16(0.f);
        xb_l[xo] = __float2bfloat16(0.f);
    }
}

// ---------------- gathered transpose + split -----------------------------------
__global__ void gtranspose_split2_kernel(const float* __restrict__ emb,
                                         const int* __restrict__ p_idx,
                                         __nv_bfloat16* __restrict__ dhA, __nv_bfloat16* __restrict__ dlA,
                                         const int* __restrict__ h_idx,
                                         __nv_bfloat16* __restrict__ dhB, __nv_bfloat16* __restrict__ dlB,
                                         int R, int C, int dR) {
    const int* idx = blockIdx.z ? h_idx : p_idx;
    __nv_bfloat16* dh = blockIdx.z ? dhB : dhA;
    __nv_bfloat16* dl = blockIdx.z ? dlB : dlA;
    __shared__ float tile[32][33];
    int c0 = blockIdx.x * 32, r0 = blockIdx.y * 32;
    int x = threadIdx.x, y = threadIdx.y;
    #pragma unroll
    for (int i = y; i < 32; i += 8) {
        int r = r0 + i, c = c0 + x;
        tile[i][x] = (r < R && c < C) ? emb[(long)idx[r] * DN + c] : 0.f;
    }
    __syncthreads();
    #pragma unroll
    for (int i = y; i < 32; i += 8) {
        int dr = c0 + i, dc = r0 + x;
        if (dr < dR && dc < R) {
            __nv_bfloat16 hi, lo;
            cvt_split(tile[x][i], hi, lo);
            dh[(long)dr * R + dc] = hi;
            dl[(long)dr * R + dc] = lo;
        }
    }
}

// ---------------- W slice reduce + split ----------------------------------------
__global__ void wreduce_kernel(const float* __restrict__ slices,
                               __nv_bfloat16* __restrict__ w1h, __nv_bfloat16* __restrict__ w1l,
                               __nv_bfloat16* __restrict__ w2h, __nv_bfloat16* __restrict__ w2l) {
    int i = blockIdx.x * blockDim.x + threadIdx.x;
    if (i >= WELEMS) return;
    int which = blockIdx.y;
    const float* base = slices + (long)which * 8 * WELEMS + i;
    float s = 0.f;
    #pragma unroll
    for (int p = 0; p < 8; p++) s += base[(long)p * WELEMS];
    __nv_bfloat16 hi, lo;
    cvt_split(s, hi, lo);
    if (which) { w2h[i] = hi; w2l[i] = lo; }
    else       { w1h[i] = hi; w1l[i] = lo; }
}

// ---------------- rowdiv + fused concat into xb (dual) --------------------------
__global__ void splitk_concat2_kernel(const float* __restrict__ partA, const float* __restrict__ rdA,
                                      float* __restrict__ CA,
                                      const float* __restrict__ partB, const float* __restrict__ rdB,
                                      float* __restrict__ CB,
                                      __nv_bfloat16* __restrict__ xbh, __nv_bfloat16* __restrict__ xbl,
                                      int M, int N, int S) {
    const float* part = blockIdx.y ? partB : partA;
    const float* rowdiv = blockIdx.y ? rdB : rdA;
    float* C = blockIdx.y ? CB : CA;
    long xRowOff = blockIdx.y ? (long)M : 0;
    long i = (long)blockIdx.x * blockDim.x + threadIdx.x;
    long total = (long)M * N;
    if (i >= total) return;
    int m = (int)(i / N), n = (int)(i % N);
    float s = 0.f;
    for (int p = 0; p < S; p++) s += part[(long)p * total + i];
    float v = s / rowdiv[m];
    C[(long)m * N + n] = v;
    __nv_bfloat16 hi, lo;
    cvt_split(v, hi, lo);
    long o = (xRowOff + m) * (long)XK + n;
    xbh[o] = hi; xbl[o] = lo;
}

// ---------------- dual column reduce --------------------------------------------
__global__ void colsum_reduce2_kernel(const float* __restrict__ partA, float* __restrict__ outA, int PA,
                                      const float* __restrict__ partB, float* __restrict__ outB, int PB,
                                      int C) {
    const float* part = blockIdx.y ? partB : partA;
    float* out = blockIdx.y ? outB : outA;
    int P = blockIdx.y ? PB : PA;
    int c = blockIdx.x * blockDim.x + threadIdx.x;
    if (c >= C) return;
    float s = 0.f;
    for (int p = 0; p < P; p++) s += part[(long)p * C + c];
    out[c] = s;
}

// ---------------- final head -----------------------------------------------------
__global__ void head_kernel(const float* __restrict__ v,
                            const float* __restrict__ Wg1, const float* __restrict__ bg1,
                            const float* __restrict__ Wg2, const float* __restrict__ bg2,
                            const float* __restrict__ Wg3, const float* __restrict__ bg3,
                            float* __restrict__ y) {
    __shared__ float sv[2 * HN];
    __shared__ float y1[HN];
    __shared__ float y2[HN];
    __shared__ float logit[3];
    int t = threadIdx.x;
    sv[t] = v[t];
    sv[t + HN] = v[t + HN];
    __syncthreads();
    {
        float acc = bg1[t];
        const float* w = Wg1 + (long)t * (2 * HN);
        for (int k = 0; k < 2 * HN; k++) acc += sv[k] * w[k];
        y1[t] = fmaxf(acc, 0.f);
    }
    __syncthreads();
    {
        float acc = bg2[t];
        const float* w = Wg2 + (long)t * HN;
        for (int k = 0; k < HN; k++) acc += y1[k] * w[k];
        y2[t] = fmaxf(acc, 0.f);
    }
    __syncthreads();
    if (t < 3) {
        float a = bg3[t];
        const float* w = Wg3 + (long)t * HN;
        for (int k = 0; k < HN; k++) a += y2[k] * w[k];
        logit[t] = a;
    }
    __syncthreads();
    if (t == 0) {
        float m = fmaxf(logit[0], fmaxf(logit[1], logit[2]));
        float e0 = expf(logit[0] - m), e1 = expf(logit[1] - m), e2 = expf(logit[2] - m);
        float s = e0 + e1 + e2;
        y[0] = e0 / s; y[1] = e1 / s; y[2] = e2 / s;
    }
}

// ---------------- host dispatch ---------------------------------------------------
struct BArgs {
    const __nv_bfloat16 *Ah, *Al; long ldA;
    const __nv_bfloat16 *Bh, *Bl; long ldB;
    const __nv_bfloat16 *A2h = nullptr, *A2l = nullptr, *B2h = nullptr, *B2l = nullptr;
    const float* bias = nullptr;
    const float* Cadd = nullptr; long ldAdd = 0;
    float* C = nullptr; long ldc = 0; long sliceStride = 0;
    __nv_bfloat16 *Chi = nullptr, *Clo = nullptr; long ldS = 0;
    __nv_bfloat16 *Th = nullptr, *Tl = nullptr; long ldT = 0;
    __nv_bfloat16 *Tph = nullptr, *Tpl = nullptr; long ldTp = 0;
    float *rowpart = nullptr, *colpart = nullptr;
    int reshapeRow = -1;
    int M, N, K, splits = 1, zTotal = 0, relu = 0;
};

static void launch_bgemm(const BArgs& a, cudaStream_t st) {
    cudaFuncSetAttribute(bgemm, cudaFuncAttributeMaxDynamicSharedMemorySize, BGEMM_SMEM);
    int kps = (a.K + a.splits - 1) / a.splits;
    kps = ((kps + 31) / 32) * 32;
    int zt = a.zTotal ? a.zTotal : a.splits;
    dim3 grid((a.N + 63) / 64, a.M / 128, zt);
    bgemm<<<grid, 256, BGEMM_SMEM, st>>>(a.Ah, a.Al, a.ldA, a.Bh, a.Bl, a.ldB,
                                         a.A2h, a.A2l, a.B2h, a.B2l, a.splits,
                                         a.bias, a.Cadd, a.ldAdd,
                                         a.C, a.ldc, a.sliceStride,
                                         a.Chi, a.Clo, a.ldS,
                                         a.Th, a.Tl, a.ldT,
                                         a.Tph, a.Tpl, a.ldTp,
                                         a.rowpart, a.colpart, a.reshapeRow,
                                         a.M, a.N, a.K, kps, a.relu);
}

#define GETSYM(var, sym) cudaGetSymbolAddress((void**)&var, sym)

extern "C" void kernel_launch(void* const* d_in, const int* in_sizes, int n_in,
                              void* d_out, int out_size) {
    static cudaStream_t s2 = nullptr;
    static cudaEvent_t evGather = nullptr, evFork = nullptr, evJoin = nullptr;
    if (!s2) {
        cudaStreamCreateWithFlags(&s2, cudaStreamNonBlocking);
        cudaEventCreateWithFlags(&evGather, cudaEventDisableTiming);
        cudaEventCreateWithFlags(&evFork, cudaEventDisableTiming);
        cudaEventCreateWithFlags(&evJoin, cudaEventDisableTiming);
    }

    const int*   p_idx = (const int*)  d_in[0];
    const int*   h_idx = (const int*)  d_in[1];
    const float* emb   = (const float*)d_in[2];
    const float* W_a1  = (const float*)d_in[3];
    const float* b_a1  = (const float*)d_in[4];
    const float* W_a2  = (const float*)d_in[5];
    const float* b_a2  = (const float*)d_in[6];
    const float* W_c1  = (const float*)d_in[7];
    const float* b_c1  = (const float*)d_in[8];
    const float* W_c2  = (const float*)d_in[9];
    const float* b_c2  = (const float*)d_in[10];
    const float* W_g1  = (const float*)d_in[11];
    const float* b_g1  = (const float*)d_in[12];
    const float* W_g2  = (const float*)d_in[13];
    const float* b_g2  = (const float*)d_in[14];
    const float* W_g3  = (const float*)d_in[15];
    const float* b_g3  = (const float*)d_in[16];

    float* out = (float*)d_out;
    const long E_OFF    = 0;
    const long BETA_OFF = (long)LPN * LHN;
    const long ALPHA_OFF= BETA_OFF + (long)LPN * DN;
    const long V1_OFF   = ALPHA_OFF + (long)LHN * DN;
    const long V2_OFF   = V1_OFF + HN;
    const long Y_OFF    = V2_OFF + HN;

    float *eik, *ekj, *part, *part2, *split, *csl;
    GETSYM(eik, g_eik); GETSYM(ekj, g_ekj);
    GETSYM(part, g_part); GETSYM(part2, g_part2); GETSYM(split, g_split);
    GETSYM(csl, g_csl);

    __nv_bfloat16 *emb2s_h, *emb2s_l, *xb_h, *xb_l, *ths_h, *ths_l, *fs_h, *fs_l;
    __nv_bfloat16 *fpTs_h, *fpTs_l, *fhTs_h, *fhTs_l;
    __nv_bfloat16 *hTs_h, *hTs_l, *pTs_h, *pTs_l;
    __nv_bfloat16 *W1Ts_h, *W1Ts_l, *W2Ts_h, *W2Ts_l;
    __nv_bfloat16 *Wa1s_h, *Wa1s_l, *Wa2s_h, *Wa2s_l;
    __nv_bfloat16 *Wc1a_h, *Wc1a_l, *Wc1b_h, *Wc1b_l, *Wc2s_h, *Wc2s_l;
    GETSYM(emb2s_h, g_emb2s_h); GETSYM(emb2s_l, g_emb2s_l);
    GETSYM(xb_h, g_xb_h);       GETSYM(xb_l, g_xb_l);
    GETSYM(ths_h, g_ths_h);     GETSYM(ths_l, g_ths_l);
    GETSYM(fs_h, g_fs_h);       GETSYM(fs_l, g_fs_l);
    GETSYM(fpTs_h, g_fpTs_h);   GETSYM(fpTs_l, g_fpTs_l);
    GETSYM(fhTs_h, g_fhTs_h);   GETSYM(fhTs_l, g_fhTs_l);
    GETSYM(hTs_h, g_hTs_h);     GETSYM(hTs_l, g_hTs_l);
    GETSYM(pTs_h, g_pTs_h);     GETSYM(pTs_l, g_pTs_l);
    GETSYM(W1Ts_h, g_W1Ts_h);   GETSYM(W1Ts_l, g_W1Ts_l);
    GETSYM(W2Ts_h, g_W2Ts_h);   GETSYM(W2Ts_l, g_W2Ts_l);
    GETSYM(Wa1s_h, g_Wa1s_h);   GETSYM(Wa1s_l, g_Wa1s_l);
    GETSYM(Wa2s_h, g_Wa2s_h);   GETSYM(Wa2s_l, g_Wa2s_l);
    GETSYM(Wc1a_h, g_Wc1a_h);   GETSYM(Wc1a_l, g_Wc1a_l);
    GETSYM(Wc1b_h, g_Wc1b_h);   GETSYM(Wc1b_l, g_Wc1b_l);
    GETSYM(Wc2s_h, g_Wc2s_h);   GETSYM(Wc2s_l, g_Wc2s_l);

    // 0) weight splits + gather + embedding transposes
    {
        long total = (long)HN * (DP + HN + XK + XK + HN);
        split_weights_kernel<<<(int)((total + 255) / 256), 256>>>(
            W_a1, W_a2, W_c1, W_c2,
            Wa1s_h, Wa1s_l, Wa2s_h, Wa2s_l,
            Wc1a_h, Wc1a_l, Wc1b_h, Wc1b_l, Wc2s_h, Wc2s_l);
    }
    gather_split_kernel<<<M2, 128>>>(emb, p_idx, h_idx, emb2s_h, emb2s_l, xb_h, xb_l);
    {
        dim3 b(32, 8);
        dim3 g((NROWS_PAD + 31) / 32, (LPN + 31) / 32, 2);
        gtranspose_split2_kernel<<<g, b>>>(emb, p_idx, pTs_h, pTs_l,
                                           h_idx, hTs_h, hTs_l, LPN, DN, NROWS_PAD);
    }
    cudaEventRecord(evGather, 0);
    cudaStreamWaitEvent(s2, evGather, 0);

    // [s2] comp1 emb-half: csl0 = emb2s @ Wc1a (fp32, no epilogue)
    {
        BArgs a{emb2s_h, emb2s_l, DP, Wc1a_h, Wc1a_l, XK};
        a.C = csl; a.ldc = HN;
        a.M = M2; a.N = HN; a.K = XK;
        launch_bgemm(a, s2);
    }

    // 1) attend1
    {
        BArgs a{emb2s_h, emb2s_l, DP, Wa1s_h, Wa1s_l, DP};
        a.bias = b_a1; a.Chi = ths_h; a.Clo = ths_l; a.ldS = HN;
        a.M = M2; a.N = HN; a.K = DP; a.relu = 1;
        launch_bgemm(a, 0);
    }
    // 2) attend2: Chi=fs, h-tiles -> fhTs (reshape T), p-tiles -> fpTs (regular T)
    {
        BArgs a{ths_h, ths_l, HN, Wa2s_h, Wa2s_l, HN};
        a.bias = b_a2;
        a.Chi = fs_h; a.Clo = fs_l; a.ldS = HN;
        a.Th = fhTs_h; a.Tl = fhTs_l; a.ldT = HN;
        a.Tph = fpTs_h; a.Tpl = fpTs_l; a.ldTp = LPN;
        a.reshapeRow = LPN;
        a.M = M2; a.N = HN; a.K = HN; a.relu = 1;
        launch_bgemm(a, 0);
    }

    // ---- FORK for W-chain ----
    cudaEventRecord(evFork, 0);
    cudaStreamWaitEvent(s2, evFork, 0);

    // [s2] W1T = hT @ fhR^T ; W2T = pT @ fpT^T  (dual, split-K x8)
    {
        BArgs a{hTs_h, hTs_l, LHN, fs_h + (long)LPN * HN, fs_l + (long)LPN * HN, LHN};
        a.A2h = pTs_h; a.A2l = pTs_l; a.B2h = fpTs_h; a.B2l = fpTs_l;
        a.C = split; a.ldc = HN; a.sliceStride = WELEMS;
        a.M = WROWS; a.N = HN; a.K = LHN; a.splits = 8; a.zTotal = 16;
        launch_bgemm(a, s2);
    }
    {
        dim3 g((WELEMS + 255) / 256, 2);
        wreduce_kernel<<<g, 256, 0, s2>>>(split, W1Ts_h, W1Ts_l, W2Ts_h, W2Ts_l);
    }
    cudaEventRecord(evJoin, s2);

    // 3) [main] E = fp @ fhR with fused row/col partials
    {
        BArgs a{fs_h, fs_l, HN, fhTs_h, fhTs_l, HN};
        a.C = out + E_OFF; a.ldc = LHN;
        a.rowpart = part; a.colpart = part2;
        a.M = LPN; a.N = LHN; a.K = HN;
        launch_bgemm(a, 0);
    }
    {
        dim3 g((LPN + 255) / 256, 2);
        colsum_reduce2_kernel<<<g, 256>>>(part, eik, 64, part2, ekj, 32, LPN);
    }

    // ---- JOIN ----
    cudaStreamWaitEvent(0, evJoin, 0);

    // 4) beta_raw = fp @ W1 ; alpha_raw = fhT @ W2
    float* baRaw = split + 16L * WELEMS;
    {
        BArgs a{fs_h, fs_l, HN, W1Ts_h, W1Ts_l, HN};
        a.A2h = fhTs_h; a.A2l = fhTs_l; a.B2h = W2Ts_h; a.B2l = W2Ts_l;
        a.C = baRaw; a.ldc = DN; a.sliceStride = (long)LPN * DN;
        a.M = LPN; a.N = DN; a.K = HN; a.splits = 1; a.zTotal = 2;
        launch_bgemm(a, 0);
    }
    {
        dim3 g((int)(((long)LPN * DN + 255) / 256), 2);
        splitk_concat2_kernel<<<g, 256>>>(baRaw, eik, out + BETA_OFF,
                                          baRaw + (long)LPN * DN, ekj, out + ALPHA_OFF,
                                          xb_h, xb_l, LPN, DN, 1);
    }

    // 5) comp1 beta-half with fused add of emb-half partial; then comp2
    {
        BArgs a{xb_h, xb_l, XK, Wc1b_h, Wc1b_l, XK};
        a.bias = b_c1; a.Cadd = csl; a.ldAdd = HN;
        a.Chi = ths_h; a.Clo = ths_l; a.ldS = HN;
        a.M = M2; a.N = HN; a.K = XK; a.relu = 1;
        launch_bgemm(a, 0);
    }
    {
        BArgs a{ths_h, ths_l, HN, Wc2s_h, Wc2s_l, HN};
        a.bias = b_c2; a.colpart = part;
        a.M = M2; a.N = HN; a.K = HN; a.relu = 1;
        launch_bgemm(a, 0);
    }
    {
        dim3 g((HN + 255) / 256, 2);
        colsum_reduce2_kernel<<<g, 256>>>(part, out + V1_OFF, 32,
                                          part + 32 * HN, out + V2_OFF, 32, HN);
    }

    // 6) head
    head_kernel<<<1, HN>>>(out + V1_OFF, W_g1, b_g1, W_g2, b_g2, W_g3, b_g3, out + Y_OFF);

    (void)in_sizes; (void)n_in; (void)out_size;
}

// round 16
// speedup vs baseline: 1.3320x; 1.0073x over previous
#include <cuda_runtime.h>
#include <cuda_bf16.h>
#include <cstdint>
#include <cmath>

#define LPN 4096
#define LHN 4096
#define DN  300
#define HN  512
#define DP  320
#define XK  320
#define NROWS_PAD 384
#define M2  8192
#define WROWS 384
#define WELEMS (WROWS * HN)

// ---------------- scratch ----------------------------------------------------
__device__ float g_eik [LPN];
__device__ float g_ekj [LHN];
__device__ float g_rs  [HN];
__device__ float g_fpcol[HN];
__device__ float g_part [64 * 4096];
__device__ float g_part2[64 * 4096];
__device__ float g_split[16 * WELEMS + 2 * LPN * DN];
__device__ float g_csl  [(long)M2 * HN];

__device__ __nv_bfloat16 g_emb2s_h[M2 * DP],  g_emb2s_l[M2 * DP];
__device__ __nv_bfloat16 g_xb_h  [M2 * XK],   g_xb_l  [M2 * XK];
__device__ __nv_bfloat16 g_ths_h [M2 * HN],   g_ths_l [M2 * HN];
__device__ __nv_bfloat16 g_fs_h  [M2 * HN],   g_fs_l  [M2 * HN];
__device__ __nv_bfloat16 g_fpTs_h[HN * LPN],  g_fpTs_l[HN * LPN];
__device__ __nv_bfloat16 g_fhTs_h[LHN * HN],  g_fhTs_l[LHN * HN];
__device__ __nv_bfloat16 g_hTs_h[NROWS_PAD * LHN], g_hTs_l[NROWS_PAD * LHN];
__device__ __nv_bfloat16 g_pTs_h[NROWS_PAD * LPN], g_pTs_l[NROWS_PAD * LPN];
__device__ __nv_bfloat16 g_W1Ts_h[WELEMS], g_W1Ts_l[WELEMS];
__device__ __nv_bfloat16 g_W2Ts_h[WELEMS], g_W2Ts_l[WELEMS];
__device__ __nv_bfloat16 g_Wa1s_h[HN * DP],   g_Wa1s_l[HN * DP];
__device__ __nv_bfloat16 g_Wa2s_h[HN * HN],   g_Wa2s_l[HN * HN];
__device__ __nv_bfloat16 g_Wc1a_h[HN * XK],   g_Wc1a_l[HN * XK];
__device__ __nv_bfloat16 g_Wc1b_h[HN * XK],   g_Wc1b_l[HN * XK];
__device__ __nv_bfloat16 g_Wc2s_h[HN * HN],   g_Wc2s_l[HN * HN];

// ---------------- PTX helpers ------------------------------------------------
__device__ __forceinline__ uint32_t smem_u32(const void* p) {
    uint32_t a;
    asm("{ .reg .u64 t; cvta.to.shared.u64 t, %1; cvt.u32.u64 %0, t; }" : "=r"(a) : "l"(p));
    return a;
}
__device__ __forceinline__ void ldsm4(uint32_t& r0, uint32_t& r1, uint32_t& r2,
                                      uint32_t& r3, uint32_t addr) {
    asm volatile("ldmatrix.sync.aligned.m8n8.x4.shared.b16 {%0,%1,%2,%3}, [%4];"
                 : "=r"(r0), "=r"(r1), "=r"(r2), "=r"(r3) : "r"(addr));
}
__device__ __forceinline__ void mma16816(float* c, const uint32_t* a,
                                         const uint32_t b0, const uint32_t b1) {
    asm volatile(
        "mma.sync.aligned.m16n8k16.row.col.f32.bf16.bf16.f32 "
        "{%0,%1,%2,%3}, {%4,%5,%6,%7}, {%8,%9}, {%0,%1,%2,%3};"
        : "+f"(c[0]), "+f"(c[1]), "+f"(c[2]), "+f"(c[3])
        : "r"(a[0]), "r"(a[1]), "r"(a[2]), "r"(a[3]), "r"(b0), "r"(b1));
}
__device__ __forceinline__ void cvt_split(float x, __nv_bfloat16& hi, __nv_bfloat16& lo) {
    hi = __float2bfloat16(x);
    lo = __float2bfloat16(x - __bfloat162float(hi));
}
__device__ __forceinline__ uint32_t pack_bf2(__nv_bfloat16 a, __nv_bfloat16 b) {
    return (uint32_t)__bfloat16_as_ushort(a) | ((uint32_t)__bfloat16_as_ushort(b) << 16);
}
__device__ __forceinline__ void cp16(uint32_t dst, const void* src) {
    asm volatile("cp.async.cg.shared.global [%0], [%1], 16;"
                 :: "r"(dst), "l"(__cvta_generic_to_global(src)));
}
__device__ __forceinline__ void cp_commit() {
    asm volatile("cp.async.commit_group;");
}
template <int NN> __device__ __forceinline__ void cp_wait() {
    asm volatile("cp.async.wait_group %0;" :: "n"(NN));
}

#define STAGE_BYTES 30720

// ---------------- bf16x3 mma.sync SGEMM, 128x64 tile, 2-stage, 1 bar/chunk ---
__global__ __launch_bounds__(256, 3)
void bgemm(const __nv_bfloat16* __restrict__ Agh, const __nv_bfloat16* __restrict__ Agl, long ldA,
           const __nv_bfloat16* __restrict__ Bgh, const __nv_bfloat16* __restrict__ Bgl, long ldB,
           const __nv_bfloat16* __restrict__ A2gh, const __nv_bfloat16* __restrict__ A2gl,
           const __nv_bfloat16* __restrict__ B2gh, const __nv_bfloat16* __restrict__ B2gl,
           int zSecond,
           const float* __restrict__ bias,
           const float* __restrict__ Cadd, long ldAdd,
           float* __restrict__ C, long ldc, long sliceStride,
           __nv_bfloat16* __restrict__ Chi, __nv_bfloat16* __restrict__ Clo, long ldS,
           __nv_bfloat16* __restrict__ Th, __nv_bfloat16* __restrict__ Tl, long ldT,
           __nv_bfloat16* __restrict__ Tph, __nv_bfloat16* __restrict__ Tpl, long ldTp,
           float* __restrict__ rowpart, float* __restrict__ colpart,
           int reshapeRow,
           int M, int N, int K, int kPerSlice, int relu) {
    extern __shared__ __align__(16) char smraw[];
    const int tid = threadIdx.x, lane = tid & 31, wid = tid >> 5;
    const int wm = wid >> 1, wn = wid & 1;
    const int m0 = blockIdx.y * 128, n0 = blockIdx.x * 64;
    const int zz = blockIdx.z;
    if (A2gh && zz >= zSecond) { Agh = A2gh; Agl = A2gl; Bgh = B2gh; Bgl = B2gl; }
    const int kbeg = (zz % zSecond) * kPerSlice;
    const int kend = min(K, kbeg + kPerSlice);
    const int nch = (kend - kbeg) >> 5;
    C += (long)zz * sliceStride;

    const uint32_t sb = smem_u32(smraw);

    float acc[2][4][4];
    #pragma unroll
    for (int i = 0; i < 2; i++)
        #pragma unroll
        for (int j = 0; j < 4; j++)
            #pragma unroll
            for (int e = 0; e < 4; e++) acc[i][j][e] = 0.f;

    const int lrow = (((lane >> 3) & 1) << 3) + (lane & 7);
    const int lcol = (lane >> 4) << 4;

    auto load_stage = [&](int st, int k0) {
        uint32_t sbase = sb + st * STAGE_BYTES;
        #pragma unroll
        for (int i = 0; i < 2; i++) {
            int c = tid + i * 256;
            int r = c >> 2, kq = c & 3;
            uint32_t dso = (uint32_t)(r * 80 + kq * 16);
            long ao = (long)(m0 + r) * ldA + k0 + kq * 8;
            cp16(sbase + dso,         Agh + ao);
            cp16(sbase + 10240 + dso, Agl + ao);
        }
        {
            int r = tid >> 2, kq = tid & 3;
            uint32_t dso = (uint32_t)(r * 80 + kq * 16);
            long bo = (long)(n0 + r) * ldB + k0 + kq * 8;
            cp16(sbase + 20480 + dso, Bgh + bo);
            cp16(sbase + 25600 + dso, Bgl + bo);
        }
    };

    load_stage(0, kbeg);
    cp_commit();

    int stage = 0;
    for (int i = 0; i < nch; i++) {
        cp_wait<0>();
        __syncthreads();
        if (i + 1 < nch) {
            load_stage(stage ^ 1, kbeg + (i + 1) * 32);
            cp_commit();
        }

        const uint32_t aAh = sb + stage * STAGE_BYTES;
        const uint32_t aAl = aAh + 10240;
        const uint32_t aBh = aAh + 20480;
        const uint32_t aBl = aAh + 25600;

        #pragma unroll
        for (int s = 0; s < 2; s++) {
            const int sbyte = s * 32;
            uint32_t ah[2][4], al[2][4], bh[2][4];
            #pragma unroll
            for (int mf = 0; mf < 2; mf++) {
                int row = wm * 32 + mf * 16 + lrow;
                ldsm4(ah[mf][0], ah[mf][1], ah[mf][2], ah[mf][3],
                      aAh + row * 80 + lcol + sbyte);
                ldsm4(al[mf][0], al[mf][1], al[mf][2], al[mf][3],
                      aAl + row * 80 + lcol + sbyte);
            }
            #pragma unroll
            for (int nf = 0; nf < 2; nf++) {
                int row = wn * 32 + nf * 16 + lrow;
                ldsm4(bh[nf][0], bh[nf][1], bh[nf][2], bh[nf][3],
                      aBh + row * 80 + lcol + sbyte);
            }
            #pragma unroll
            for (int nf = 0; nf < 2; nf++)
                #pragma unroll
                for (int j = 0; j < 2; j++)
                    #pragma unroll
                    for (int mf = 0; mf < 2; mf++)
                        mma16816(acc[mf][nf * 2 + j], ah[mf], bh[nf][j], bh[nf][j + 2]);
            #pragma unroll
            for (int nf = 0; nf < 2; nf++)
                #pragma unroll
                for (int j = 0; j < 2; j++)
                    #pragma unroll
                    for (int mf = 0; mf < 2; mf++)
                        mma16816(acc[mf][nf * 2 + j], al[mf], bh[nf][j], bh[nf][j + 2]);
            #pragma unroll
            for (int nf = 0; nf < 2; nf++) {
                int row = wn * 32 + nf * 16 + lrow;
                uint32_t bl[4];
                ldsm4(bl[0], bl[1], bl[2], bl[3], aBl + row * 80 + lcol + sbyte);
                #pragma unroll
                for (int j = 0; j < 2; j++)
                    #pragma unroll
                    for (int mf = 0; mf < 2; mf++)
                        mma16816(acc[mf][nf * 2 + j], ah[mf], bl[j], bl[j + 2]);
            }
        }
        stage ^= 1;
    }
    __syncthreads();

    // ---- Cadd/bias/relu in-place ----
    const int tg = lane >> 2;
    const int tn = (lane & 3) << 1;
    if (Cadd || bias || relu) {
        #pragma unroll
        for (int mf = 0; mf < 2; mf++)
            #pragma unroll
            for (int h2 = 0; h2 < 2; h2++) {
                int m = m0 + wm * 32 + mf * 16 + h2 * 8 + tg;
                #pragma unroll
                for (int nfj = 0; nfj < 4; nfj++) {
                    int n = n0 + (wn * 32 + nfj * 8 + tn);
                    float vx = acc[mf][nfj][h2 * 2 + 0];
                    float vy = acc[mf][nfj][h2 * 2 + 1];
                    if (n < N) {
                        if (Cadd) {
                            float2 adv = *(const float2*)(Cadd + (long)m * ldAdd + n);
                            vx += adv.x; vy += adv.y;
                        }
                        if (bias) { vx += bias[n]; vy += bias[n + 1]; }
                    }
                    if (relu) { vx = fmaxf(vx, 0.f); vy = fmaxf(vy, 0.f); }
                    acc[mf][nfj][h2 * 2 + 0] = vx;
                    acc[mf][nfj][h2 * 2 + 1] = vy;
                }
            }
    }

    const bool rsh = (reshapeRow >= 0);
    const bool isH = rsh && (m0 >= reshapeRow);

    if (C || Chi) {
        #pragma unroll
        for (int mf = 0; mf < 2; mf++) {
            #pragma unroll
            for (int h2 = 0; h2 < 2; h2++) {
                int m = m0 + wm * 32 + mf * 16 + h2 * 8 + tg;
                #pragma unroll
                for (int nfj = 0; nfj < 4; nfj++) {
                    int n = n0 + wn * 32 + nfj * 8 + tn;
                    if (n >= N) continue;
                    float2 v;
                    v.x = acc[mf][nfj][h2 * 2 + 0];
                    v.y = acc[mf][nfj][h2 * 2 + 1];
                    if (C) *(float2*)(C + (long)m * ldc + n) = v;
                    if (Chi) {
                        __nv_bfloat16 h0, l0, h1, l1;
                        cvt_split(v.x, h0, l0);
                        cvt_split(v.y, h1, l1);
                        long o = (long)m * ldS + n;
                        *(uint32_t*)(Chi + o) = pack_bf2(h0, h1);
                        *(uint32_t*)(Clo + o) = pack_bf2(l0, l1);
                    }
                }
            }
        }
    }

    const bool doResh = Th && rsh && isH;
    const bool doReg  = Tph && rsh && !isH;
    if (doResh || doReg || rowpart || colpart) {
        float* ts = (float*)smraw;             // [64][129]
        #pragma unroll
        for (int mf = 0; mf < 2; mf++) {
            #pragma unroll
            for (int h2 = 0; h2 < 2; h2++) {
                int ml = wm * 32 + mf * 16 + h2 * 8 + tg;
                #pragma unroll
                for (int nfj = 0; nfj < 4; nfj++) {
                    int nl = wn * 32 + nfj * 8 + tn;
                    ts[(nl + 0) * 129 + ml] = acc[mf][nfj][h2 * 2 + 0];
                    ts[(nl + 1) * 129 + ml] = acc[mf][nfj][h2 * 2 + 1];
                }
            }
        }
        __syncthreads();
        if (tid < 128 && rowpart) {
            float s = 0.f;
            #pragma unroll 8
            for (int n = 0; n < 64; n++) s += ts[n * 129 + tid];
            rowpart[(long)blockIdx.x * M + m0 + tid] = s;
        }
        if (tid < 64 && colpart) {
            float s2 = 0.f;
            #pragma unroll 8
            for (int m = 0; m < 128; m++) s2 += ts[tid * 129 + m];
            colpart[(long)blockIdx.y * N + n0 + tid] = s2;
        }
        if (doResh) {
            long kb = (long)(m0 - reshapeRow) >> 3;
            for (int idx = tid; idx < 512; idx += 256) {
                int r8 = idx >> 6, nl = idx & 63;
                long j = (long)r8 * HN + n0 + nl;
                __align__(16) __nv_bfloat16 hb[16], lb[16];
                #pragma unroll
                for (int q = 0; q < 16; q++) {
                    __nv_bfloat16 hi, lo;
                    cvt_split(ts[nl * 129 + r8 + 8 * q], hi, lo);
                    hb[q] = hi; lb[q] = lo;
                }
                long o = j * ldT + kb;
                *(uint4*)(Th + o)     = *(uint4*)(hb);
                *(uint4*)(Th + o + 8) = *(uint4*)(hb + 8);
                *(uint4*)(Tl + o)     = *(uint4*)(lb);
                *(uint4*)(Tl + o + 8) = *(uint4*)(lb + 8);
            }
        }
        if (doReg) {
            for (int idx = tid; idx < 4096; idx += 256) {
                int n = idx >> 6, m2 = (idx & 63) << 1;
                __nv_bfloat16 h0, l0, h1, l1;
                cvt_split(ts[n * 129 + m2], h0, l0);
                cvt_split(ts[n * 129 + m2 + 1], h1, l1);
                long o = (long)(n0 + n) * ldTp + m0 + m2;
                *(uint32_t*)(Tph + o) = pack_bf2(h0, h1);
                *(uint32_t*)(Tpl + o) = pack_bf2(l0, l1);
            }
        }
    }
}

static const int BGEMM_SMEM = 2 * STAGE_BYTES;

// ---------------- weight splits -----------------------------------------------
__global__ void split_weights_kernel(const float* __restrict__ Wa1, const float* __restrict__ Wa2,
                                     const float* __restrict__ Wc1, const float* __restrict__ Wc2,
                                     __nv_bfloat16* __restrict__ a1h, __nv_bfloat16* __restrict__ a1l,
                                     __nv_bfloat16* __restrict__ a2h, __nv_bfloat16* __restrict__ a2l,
                                     __nv_bfloat16* __restrict__ c1ah, __nv_bfloat16* __restrict__ c1al,
                                     __nv_bfloat16* __restrict__ c1bh, __nv_bfloat16* __restrict__ c1bl,
                                     __nv_bfloat16* __restrict__ c2h, __nv_bfloat16* __restrict__ c2l) {
    const long s1 = (long)HN * DP, s2 = (long)HN * HN;
    const long s3 = (long)HN * XK, s4 = (long)HN * XK, s5 = (long)HN * HN;
    long i = (long)blockIdx.x * blockDim.x + threadIdx.x;
    float v; __nv_bfloat16 *dh, *dl; long li;
    if (i < s1) {
        li = i; int m = (int)(li / DP), k = (int)(li % DP);
        v = (k < DN) ? Wa1[(long)m * DN + k] : 0.f; dh = a1h; dl = a1l;
    } else if (i < s1 + s2) {
        li = i - s1; int m = (int)(li / HN), k = (int)(li % HN);
        v = Wa2[(long)m * HN + k]; dh = a2h; dl = a2l;
    } else if (i < s1 + s2 + s3) {
        li = i - s1 - s2; int m = (int)(li / XK), k = (int)(li % XK);
        v = (k < DN) ? Wc1[(long)m * (2 * DN) + k] : 0.f; dh = c1ah; dl = c1al;
    } else if (i < s1 + s2 + s3 + s4) {
        li = i - s1 - s2 - s3; int m = (int)(li / XK), k = (int)(li % XK);
        v = (k < DN) ? Wc1[(long)m * (2 * DN) + DN + k] : 0.f; dh = c1bh; dl = c1bl;
    } else if (i < s1 + s2 + s3 + s4 + s5) {
        li = i - s1 - s2 - s3 - s4; int m = (int)(li / HN), k = (int)(li % HN);
        v = Wc2[(long)m * HN + k]; dh = c2h; dl = c2l;
    } else return;
    __nv_bfloat16 hi, lo;
    cvt_split(v, hi, lo);
    dh[li] = hi; dl[li] = lo;
}

// ---------------- fused gather + split-pad + xb pad zero ----------------------
__global__ void gather_split_kernel(const float* __restrict__ emb,
                                    const int* __restrict__ p_idx,
                                    const int* __restrict__ h_idx,
                                    __nv_bfloat16* __restrict__ e_h,
                                    __nv_bfloat16* __restrict__ e_l,
                                    __nv_bfloat16* __restrict__ xb_h,
                                    __nv_bfloat16* __restrict__ xb_l) {
    int r = blockIdx.x;
    long src = (r < LPN) ? p_idx[r] : h_idx[r - LPN];
    const float* s = emb + src * (long)DN;
    for (int c = threadIdx.x; c < DP; c += blockDim.x) {
        float v = (c < DN) ? s[c] : 0.f;
        __nv_bfloat16 hi, lo;
        cvt_split(v, hi, lo);
        long eo = (long)r * DP + c;
        e_h[eo] = hi; e_l[eo] = lo;
    }
    for (int c = DN + threadIdx.x; c < XK; c += blockDim.x) {
        long xo = (long)r * XK + c;
        xb_h[xo] = __float2bfloat16(0.f);
        xb_l[xo] = __float2bfloat16(0.f);
    }
}

// ---------------- gathered transpose + split -----------------------------------
__global__ void gtranspose_split2_kernel(const float* __restrict__ emb,
                                         const int* __restrict__ p_idx,
                                         __nv_bfloat16* __restrict__ dhA, __nv_bfloat16* __restrict__ dlA,
                                         const int* __restrict__ h_idx,
                                         __nv_bfloat16* __restrict__ dhB, __nv_bfloat16* __restrict__ dlB,
                                         int R, int C, int dR) {
    const int* idx = blockIdx.z ? h_idx : p_idx;
    __nv_bfloat16* dh = blockIdx.z ? dhB : dhA;
    __nv_bfloat16* dl = blockIdx.z ? dlB : dlA;
    __shared__ float tile[32][33];
    int c0 = blockIdx.x * 32, r0 = blockIdx.y * 32;
    int x = threadIdx.x, y = threadIdx.y;
    #pragma unroll
    for (int i = y; i < 32; i += 8) {
        int r = r0 + i, c = c0 + x;
        tile[i][x] = (r < R && c < C) ? emb[(long)idx[r] * DN + c] : 0.f;
    }
    __syncthreads();
    #pragma unroll
    for (int i = y; i < 32; i += 8) {
        int dr = c0 + i, dc = r0 + x;
        if (dr < dR && dc < R) {
            __nv_bfloat16 hi, lo;
            cvt_split(tile[x][i], hi, lo);
            dh[(long)dr * R + dc] = hi;
            dl[(long)dr * R + dc] = lo;
        }
    }
}

// ---------------- W slice reduce + split ----------------------------------------
__global__ void wreduce_kernel(const float* __restrict__ slices,
                               __nv_bfloat16* __restrict__ w1h, __nv_bfloat16* __restrict__ w1l,
                               __nv_bfloat16* __restrict__ w2h, __nv_bfloat16* __restrict__ w2l) {
    int i = blockIdx.x * blockDim.x + threadIdx.x;
    if (i >= WELEMS) return;
    int which = blockIdx.y;
    const float* base = slices + (long)which * 8 * WELEMS + i;
    float s = 0.f;
    #pragma unroll
    for (int p = 0; p < 8; p++) s += base[(long)p * WELEMS];
    __nv_bfloat16 hi, lo;
    cvt_split(s, hi, lo);
    if (which) { w2h[i] = hi; w2l[i] = lo; }
    else       { w1h[i] = hi; w1l[i] = lo; }
}

// ---------------- rs / fpcol from attend2 partials ------------------------------
// rs[k] = sum over fh rows 8k..8k+7 of their rowsums; fpcol[n] = colsum of fp.
__global__ void rs_fpcol_kernel(const float* __restrict__ rowpart,
                                const float* __restrict__ colpart,
                                float* __restrict__ rs, float* __restrict__ fpcol) {
    int t = blockIdx.x * blockDim.x + threadIdx.x;
    if (t < HN) {
        float s = 0.f;
        #pragma unroll
        for (int bx = 0; bx < 8; bx++)
            #pragma unroll
            for (int r = 0; r < 8; r++)
                s += rowpart[(long)bx * M2 + LPN + 8 * t + r];
        rs[t] = s;
    } else if (t < 2 * HN) {
        int n = t - HN;
        float s = 0.f;
        #pragma unroll
        for (int by = 0; by < 32; by++) s += colpart[(long)by * HN + n];
        fpcol[n] = s;
    }
}

// ---------------- GEMV: out[i] = sum_k (Ah[i,k]+Al[i,k]) * v[k], warp per row ---
__global__ void gemv_rows_kernel(const __nv_bfloat16* __restrict__ Ah,
                                 const __nv_bfloat16* __restrict__ Al,
                                 const float* __restrict__ v,
                                 float* __restrict__ outv, int M) {
    int row = blockIdx.x * 8 + (threadIdx.x >> 5);
    int lane = threadIdx.x & 31;
    if (row >= M) return;
    const __nv_bfloat16* ah = Ah + (long)row * HN;
    const __nv_bfloat16* al = Al + (long)row * HN;
    float s = 0.f;
    for (int k = lane; k < HN; k += 32)
        s += (__bfloat162float(ah[k]) + __bfloat162float(al[k])) * v[k];
    #pragma unroll
    for (int o = 16; o > 0; o >>= 1) s += __shfl_down_sync(0xffffffff, s, o);
    if (lane == 0) outv[row] = s;
}

// ---------------- rowdiv + fused concat into xb (dual) --------------------------
__global__ void splitk_concat2_kernel(const float* __restrict__ partA, const float* __restrict__ rdA,
                                      float* __restrict__ CA,
                                      const float* __restrict__ partB, const float* __restrict__ rdB,
                                      float* __restrict__ CB,
                                      __nv_bfloat16* __restrict__ xbh, __nv_bfloat16* __restrict__ xbl,
                                      int M, int N, int S) {
    const float* part = blockIdx.y ? partB : partA;
    const float* rowdiv = blockIdx.y ? rdB : rdA;
    float* C = blockIdx.y ? CB : CA;
    long xRowOff = blockIdx.y ? (long)M : 0;
    long i = (long)blockIdx.x * blockDim.x + threadIdx.x;
    long total = (long)M * N;
    if (i >= total) return;
    int m = (int)(i / N), n = (int)(i % N);
    float s = 0.f;
    for (int p = 0; p < S; p++) s += part[(long)p * total + i];
    float v = s / rowdiv[m];
    C[(long)m * N + n] = v;
    __nv_bfloat16 hi, lo;
    cvt_split(v, hi, lo);
    long o = (xRowOff + m) * (long)XK + n;
    xbh[o] = hi; xbl[o] = lo;
}

// ---------------- dual column reduce --------------------------------------------
__global__ void colsum_reduce2_kernel(const float* __restrict__ partA, float* __restrict__ outA, int PA,
                                      const float* __restrict__ partB, float* __restrict__ outB, int PB,
                                      int C) {
    const float* part = blockIdx.y ? partB : partA;
    float* out = blockIdx.y ? outB : outA;
    int P = blockIdx.y ? PB : PA;
    int c = blockIdx.x * blockDim.x + threadIdx.x;
    if (c >= C) return;
    float s = 0.f;
    for (int p = 0; p < P; p++) s += part[(long)p * C + c];
    out[c] = s;
}

// ---------------- final head -----------------------------------------------------
__global__ void head_kernel(const float* __restrict__ v,
                            const float* __restrict__ Wg1, const float* __restrict__ bg1,
                            const float* __restrict__ Wg2, const float* __restrict__ bg2,
                            const float* __restrict__ Wg3, const float* __restrict__ bg3,
                            float* __restrict__ y) {
    __shared__ float sv[2 * HN];
    __shared__ float y1[HN];
    __shared__ float y2[HN];
    __shared__ float logit[3];
    int t = threadIdx.x;
    sv[t] = v[t];
    sv[t + HN] = v[t + HN];
    __syncthreads();
    {
        float acc = bg1[t];
        const float* w = Wg1 + (long)t * (2 * HN);
        for (int k = 0; k < 2 * HN; k++) acc += sv[k] * w[k];
        y1[t] = fmaxf(acc, 0.f);
    }
    __syncthreads();
    {
        float acc = bg2[t];
        const float* w = Wg2 + (long)t * HN;
        for (int k = 0; k < HN; k++) acc += y1[k] * w[k];
        y2[t] = fmaxf(acc, 0.f);
    }
    __syncthreads();
    if (t < 3) {
        float a = bg3[t];
        const float* w = Wg3 + (long)t * HN;
        for (int k = 0; k < HN; k++) a += y2[k] * w[k];
        logit[t] = a;
    }
    __syncthreads();
    if (t == 0) {
        float m = fmaxf(logit[0], fmaxf(logit[1], logit[2]));
        float e0 = expf(logit[0] - m), e1 = expf(logit[1] - m), e2 = expf(logit[2] - m);
        float s = e0 + e1 + e2;
        y[0] = e0 / s; y[1] = e1 / s; y[2] = e2 / s;
    }
}

// ---------------- host dispatch ---------------------------------------------------
struct BArgs {
    const __nv_bfloat16 *Ah, *Al; long ldA;
    const __nv_bfloat16 *Bh, *Bl; long ldB;
    const __nv_bfloat16 *A2h = nullptr, *A2l = nullptr, *B2h = nullptr, *B2l = nullptr;
    const float* bias = nullptr;
    const float* Cadd = nullptr; long ldAdd = 0;
    float* C = nullptr; long ldc = 0; long sliceStride = 0;
    __nv_bfloat16 *Chi = nullptr, *Clo = nullptr; long ldS = 0;
    __nv_bfloat16 *Th = nullptr, *Tl = nullptr; long ldT = 0;
    __nv_bfloat16 *Tph = nullptr, *Tpl = nullptr; long ldTp = 0;
    float *rowpart = nullptr, *colpart = nullptr;
    int reshapeRow = -1;
    int M, N, K, splits = 1, zTotal = 0, relu = 0;
};

static void launch_bgemm(const BArgs& a, cudaStream_t st) {
    cudaFuncSetAttribute(bgemm, cudaFuncAttributeMaxDynamicSharedMemorySize, BGEMM_SMEM);
    int kps = (a.K + a.splits - 1) / a.splits;
    kps = ((kps + 31) / 32) * 32;
    int zt = a.zTotal ? a.zTotal : a.splits;
    dim3 grid((a.N + 63) / 64, a.M / 128, zt);
    bgemm<<<grid, 256, BGEMM_SMEM, st>>>(a.Ah, a.Al, a.ldA, a.Bh, a.Bl, a.ldB,
                                         a.A2h, a.A2l, a.B2h, a.B2l, a.splits,
                                         a.bias, a.Cadd, a.ldAdd,
                                         a.C, a.ldc, a.sliceStride,
                                         a.Chi, a.Clo, a.ldS,
                                         a.Th, a.Tl, a.ldT,
                                         a.Tph, a.Tpl, a.ldTp,
                                         a.rowpart, a.colpart, a.reshapeRow,
                                         a.M, a.N, a.K, kps, a.relu);
}

#define GETSYM(var, sym) cudaGetSymbolAddress((void**)&var, sym)

extern "C" void kernel_launch(void* const* d_in, const int* in_sizes, int n_in,
                              void* d_out, int out_size) {
    static cudaStream_t s2 = nullptr;
    static cudaEvent_t evGather = nullptr, evFork = nullptr, evJoin = nullptr;
    if (!s2) {
        cudaStreamCreateWithFlags(&s2, cudaStreamNonBlocking);
        cudaEventCreateWithFlags(&evGather, cudaEventDisableTiming);
        cudaEventCreateWithFlags(&evFork, cudaEventDisableTiming);
        cudaEventCreateWithFlags(&evJoin, cudaEventDisableTiming);
    }

    const int*   p_idx = (const int*)  d_in[0];
    const int*   h_idx = (const int*)  d_in[1];
    const float* emb   = (const float*)d_in[2];
    const float* W_a1  = (const float*)d_in[3];
    const float* b_a1  = (const float*)d_in[4];
    const float* W_a2  = (const float*)d_in[5];
    const float* b_a2  = (const float*)d_in[6];
    const float* W_c1  = (const float*)d_in[7];
    const float* b_c1  = (const float*)d_in[8];
    const float* W_c2  = (const float*)d_in[9];
    const float* b_c2  = (const float*)d_in[10];
    const float* W_g1  = (const float*)d_in[11];
    const float* b_g1  = (const float*)d_in[12];
    const float* W_g2  = (const float*)d_in[13];
    const float* b_g2  = (const float*)d_in[14];
    const float* W_g3  = (const float*)d_in[15];
    const float* b_g3  = (const float*)d_in[16];

    float* out = (float*)d_out;
    const long E_OFF    = 0;
    const long BETA_OFF = (long)LPN * LHN;
    const long ALPHA_OFF= BETA_OFF + (long)LPN * DN;
    const long V1_OFF   = ALPHA_OFF + (long)LHN * DN;
    const long V2_OFF   = V1_OFF + HN;
    const long Y_OFF    = V2_OFF + HN;

    float *eik, *ekj, *rs, *fpcol, *part, *part2, *split, *csl;
    GETSYM(eik, g_eik); GETSYM(ekj, g_ekj);
    GETSYM(rs, g_rs);   GETSYM(fpcol, g_fpcol);
    GETSYM(part, g_part); GETSYM(part2, g_part2); GETSYM(split, g_split);
    GETSYM(csl, g_csl);

    __nv_bfloat16 *emb2s_h, *emb2s_l, *xb_h, *xb_l, *ths_h, *ths_l, *fs_h, *fs_l;
    __nv_bfloat16 *fpTs_h, *fpTs_l, *fhTs_h, *fhTs_l;
    __nv_bfloat16 *hTs_h, *hTs_l, *pTs_h, *pTs_l;
    __nv_bfloat16 *W1Ts_h, *W1Ts_l, *W2Ts_h, *W2Ts_l;
    __nv_bfloat16 *Wa1s_h, *Wa1s_l, *Wa2s_h, *Wa2s_l;
    __nv_bfloat16 *Wc1a_h, *Wc1a_l, *Wc1b_h, *Wc1b_l, *Wc2s_h, *Wc2s_l;
    GETSYM(emb2s_h, g_emb2s_h); GETSYM(emb2s_l, g_emb2s_l);
    GETSYM(xb_h, g_xb_h);       GETSYM(xb_l, g_xb_l);
    GETSYM(ths_h, g_ths_h);     GETSYM(ths_l, g_ths_l);
    GETSYM(fs_h, g_fs_h);       GETSYM(fs_l, g_fs_l);
    GETSYM(fpTs_h, g_fpTs_h);   GETSYM(fpTs_l, g_fpTs_l);
    GETSYM(fhTs_h, g_fhTs_h);   GETSYM(fhTs_l, g_fhTs_l);
    GETSYM(hTs_h, g_hTs_h);     GETSYM(hTs_l, g_hTs_l);
    GETSYM(pTs_h, g_pTs_h);     GETSYM(pTs_l, g_pTs_l);
    GETSYM(W1Ts_h, g_W1Ts_h);   GETSYM(W1Ts_l, g_W1Ts_l);
    GETSYM(W2Ts_h, g_W2Ts_h);   GETSYM(W2Ts_l, g_W2Ts_l);
    GETSYM(Wa1s_h, g_Wa1s_h);   GETSYM(Wa1s_l, g_Wa1s_l);
    GETSYM(Wa2s_h, g_Wa2s_h);   GETSYM(Wa2s_l, g_Wa2s_l);
    GETSYM(Wc1a_h, g_Wc1a_h);   GETSYM(Wc1a_l, g_Wc1a_l);
    GETSYM(Wc1b_h, g_Wc1b_h);   GETSYM(Wc1b_l, g_Wc1b_l);
    GETSYM(Wc2s_h, g_Wc2s_h);   GETSYM(Wc2s_l, g_Wc2s_l);

    // 0) weight splits + gather + embedding transposes
    {
        long total = (long)HN * (DP + HN + XK + XK + HN);
        split_weights_kernel<<<(int)((total + 255) / 256), 256>>>(
            W_a1, W_a2, W_c1, W_c2,
            Wa1s_h, Wa1s_l, Wa2s_h, Wa2s_l,
            Wc1a_h, Wc1a_l, Wc1b_h, Wc1b_l, Wc2s_h, Wc2s_l);
    }
    gather_split_kernel<<<M2, 128>>>(emb, p_idx, h_idx, emb2s_h, emb2s_l, xb_h, xb_l);
    {
        dim3 b(32, 8);
        dim3 g((NROWS_PAD + 31) / 32, (LPN + 31) / 32, 2);
        gtranspose_split2_kernel<<<g, b>>>(emb, p_idx, pTs_h, pTs_l,
                                           h_idx, hTs_h, hTs_l, LPN, DN, NROWS_PAD);
    }
    cudaEventRecord(evGather, 0);
    cudaStreamWaitEvent(s2, evGather, 0);

    // [s2] comp1 emb-half
    {
        BArgs a{emb2s_h, emb2s_l, DP, Wc1a_h, Wc1a_l, XK};
        a.C = csl; a.ldc = HN;
        a.M = M2; a.N = HN; a.K = XK;
        launch_bgemm(a, s2);
    }

    // 1) attend1
    {
        BArgs a{emb2s_h, emb2s_l, DP, Wa1s_h, Wa1s_l, DP};
        a.bias = b_a1; a.Chi = ths_h; a.Clo = ths_l; a.ldS = HN;
        a.M = M2; a.N = HN; a.K = DP; a.relu = 1;
        launch_bgemm(a, 0);
    }
    // 2) attend2: splits + transposes + row/col partials (for rs/fpcol)
    {
        BArgs a{ths_h, ths_l, HN, Wa2s_h, Wa2s_l, HN};
        a.bias = b_a2;
        a.Chi = fs_h; a.Clo = fs_l; a.ldS = HN;
        a.Th = fhTs_h; a.Tl = fhTs_l; a.ldT = HN;
        a.Tph = fpTs_h; a.Tpl = fpTs_l; a.ldTp = LPN;
        a.rowpart = part; a.colpart = part2;
        a.reshapeRow = LPN;
        a.M = M2; a.N = HN; a.K = HN; a.relu = 1;
        launch_bgemm(a, 0);
    }

    // ---- FORK: s2 computes W chain + eik/ekj + beta/alpha; main computes E ----
    cudaEventRecord(evFork, 0);
    cudaStreamWaitEvent(s2, evFork, 0);

    // [s2] W1T / W2T (dual, split-K x8)
    {
        BArgs a{hTs_h, hTs_l, LHN, fs_h + (long)LPN * HN, fs_l + (long)LPN * HN, LHN};
        a.A2h = pTs_h; a.A2l = pTs_l; a.B2h = fpTs_h; a.B2l = fpTs_l;
        a.C = split; a.ldc = HN; a.sliceStride = WELEMS;
        a.M = WROWS; a.N = HN; a.K = LHN; a.splits = 8; a.zTotal = 16;
        launch_bgemm(a, s2);
    }
    {
        dim3 g((WELEMS + 255) / 256, 2);
        wreduce_kernel<<<g, 256, 0, s2>>>(split, W1Ts_h, W1Ts_l, W2Ts_h, W2Ts_l);
    }
    // [s2] rs/fpcol from attend2 partials, then eik = fp@rs, ekj = fhT@fpcol
    rs_fpcol_kernel<<<(2 * HN + 255) / 256, 256, 0, s2>>>(part, part2, rs, fpcol);
    gemv_rows_kernel<<<LPN / 8, 256, 0, s2>>>(fs_h, fs_l, rs, eik, LPN);
    gemv_rows_kernel<<<LHN / 8, 256, 0, s2>>>(fhTs_h, fhTs_l, fpcol, ekj, LHN);
    // [s2] beta_raw = fp @ W1 ; alpha_raw = fhT @ W2 (dual) — independent of E
    float* baRaw = split + 16L * WELEMS;
    {
        BArgs a{fs_h, fs_l, HN, W1Ts_h, W1Ts_l, HN};
        a.A2h = fhTs_h; a.A2l = fhTs_l; a.B2h = W2Ts_h; a.B2l = W2Ts_l;
        a.C = baRaw; a.ldc = DN; a.sliceStride = (long)LPN * DN;
        a.M = LPN; a.N = DN; a.K = HN; a.splits = 1; a.zTotal = 2;
        launch_bgemm(a, s2);
    }
    cudaEventRecord(evJoin, s2);

    // 3) [main] E = fp @ fhR  (pure GEMM)
    {
        BArgs a{fs_h, fs_l, HN, fhTs_h, fhTs_l, HN};
        a.C = out + E_OFF; a.ldc = LHN;
        a.M = LPN; a.N = LHN; a.K = HN;
        launch_bgemm(a, 0);
    }

    // ---- JOIN ----
    cudaStreamWaitEvent(0, evJoin, 0);

    // 4) divide + concat into xb
    {
        dim3 g((int)(((long)LPN * DN + 255) / 256), 2);
        splitk_concat2_kernel<<<g, 256>>>(baRaw, eik, out + BETA_OFF,
                                          baRaw + (long)LPN * DN, ekj, out + ALPHA_OFF,
                                          xb_h, xb_l, LPN, DN, 1);
    }

    // 5) comp1 beta-half (fused add of emb-half partial), comp2 with colsums
    {
        BArgs a{xb_h, xb_l, XK, Wc1b_h, Wc1b_l, XK};
        a.bias = b_c1; a.Cadd = csl; a.ldAdd = HN;
        a.Chi = ths_h; a.Clo = ths_l; a.ldS = HN;
        a.M = M2; a.N = HN; a.K = XK; a.relu = 1;
        launch_bgemm(a, 0);
    }
    {
        BArgs a{ths_h, ths_l, HN, Wc2s_h, Wc2s_l, HN};
        a.bias = b_c2; a.colpart = part;
        a.M = M2; a.N = HN; a.K = HN; a.relu = 1;
        launch_bgemm(a, 0);
    }
    {
        dim3 g((HN + 255) / 256, 2);
        colsum_reduce2_kernel<<<g, 256>>>(part, out + V1_OFF, 32,
                                          part + 32 * HN, out + V2_OFF, 32, HN);
    }

    // 6) head
    head_kernel<<<1, HN>>>(out + V1_OFF, W_g1, b_g1, W_g2, b_g2, W_g3, b_g3, out + Y_OFF);

    (void)in_sizes; (void)n_in; (void)out_size;
}

// round 17
// speedup vs baseline: 1.4373x; 1.0791x over previous
#include <cuda_runtime.h>
#include <cuda_bf16.h>
#include <cstdint>
#include <cmath>

#define LPN 4096
#define LHN 4096
#define DN  300
#define HN  512
#define DP  320
#define XK  320
#define NROWS_PAD 384
#define M2  8192
#define WROWS 384
#define WELEMS (WROWS * HN)

// ---------------- scratch ----------------------------------------------------
__device__ float g_eik [LPN];
__device__ float g_ekj [LHN];
__device__ float g_rs  [HN];
__device__ float g_fpcol[HN];
__device__ float g_part [64 * 4096];
__device__ float g_part2[64 * 4096];
__device__ float g_split[16 * WELEMS + 2 * LPN * DN];
__device__ float g_csl  [(long)M2 * HN];

__device__ __nv_bfloat16 g_emb2s_h[M2 * DP],  g_emb2s_l[M2 * DP];
__device__ __nv_bfloat16 g_xb_h  [M2 * XK],   g_xb_l  [M2 * XK];
__device__ __nv_bfloat16 g_ths_h [M2 * HN],   g_ths_l [M2 * HN];
__device__ __nv_bfloat16 g_fs_h  [M2 * HN],   g_fs_l  [M2 * HN];
__device__ __nv_bfloat16 g_fpTs_h[HN * LPN],  g_fpTs_l[HN * LPN];
__device__ __nv_bfloat16 g_fhTs_h[LHN * HN],  g_fhTs_l[LHN * HN];
__device__ __nv_bfloat16 g_hTs_h[NROWS_PAD * LHN], g_hTs_l[NROWS_PAD * LHN];
__device__ __nv_bfloat16 g_pTs_h[NROWS_PAD * LPN], g_pTs_l[NROWS_PAD * LPN];
__device__ __nv_bfloat16 g_W1Ts_h[WELEMS], g_W1Ts_l[WELEMS];
__device__ __nv_bfloat16 g_W2Ts_h[WELEMS], g_W2Ts_l[WELEMS];
__device__ __nv_bfloat16 g_Wa1s_h[HN * DP],   g_Wa1s_l[HN * DP];
__device__ __nv_bfloat16 g_Wa2s_h[HN * HN],   g_Wa2s_l[HN * HN];
__device__ __nv_bfloat16 g_Wc1a_h[HN * XK],   g_Wc1a_l[HN * XK];
__device__ __nv_bfloat16 g_Wc1b_h[HN * XK],   g_Wc1b_l[HN * XK];
__device__ __nv_bfloat16 g_Wc2s_h[HN * HN],   g_Wc2s_l[HN * HN];

// ---------------- PTX helpers ------------------------------------------------
__device__ __forceinline__ uint32_t smem_u32(const void* p) {
    uint32_t a;
    asm("{ .reg .u64 t; cvta.to.shared.u64 t, %1; cvt.u32.u64 %0, t; }" : "=r"(a) : "l"(p));
    return a;
}
__device__ __forceinline__ void ldsm4(uint32_t& r0, uint32_t& r1, uint32_t& r2,
                                      uint32_t& r3, uint32_t addr) {
    asm volatile("ldmatrix.sync.aligned.m8n8.x4.shared.b16 {%0,%1,%2,%3}, [%4];"
                 : "=r"(r0), "=r"(r1), "=r"(r2), "=r"(r3) : "r"(addr));
}
__device__ __forceinline__ void mma16816(float* c, const uint32_t* a,
                                         const uint32_t b0, const uint32_t b1) {
    asm volatile(
        "mma.sync.aligned.m16n8k16.row.col.f32.bf16.bf16.f32 "
        "{%0,%1,%2,%3}, {%4,%5,%6,%7}, {%8,%9}, {%0,%1,%2,%3};"
        : "+f"(c[0]), "+f"(c[1]), "+f"(c[2]), "+f"(c[3])
        : "r"(a[0]), "r"(a[1]), "r"(a[2]), "r"(a[3]), "r"(b0), "r"(b1));
}
__device__ __forceinline__ void cvt_split(float x, __nv_bfloat16& hi, __nv_bfloat16& lo) {
    hi = __float2bfloat16(x);
    lo = __float2bfloat16(x - __bfloat162float(hi));
}
__device__ __forceinline__ uint32_t pack_bf2(__nv_bfloat16 a, __nv_bfloat16 b) {
    return (uint32_t)__bfloat16_as_ushort(a) | ((uint32_t)__bfloat16_as_ushort(b) << 16);
}
__device__ __forceinline__ void cp16(uint32_t dst, const void* src) {
    asm volatile("cp.async.cg.shared.global [%0], [%1], 16;"
                 :: "r"(dst), "l"(__cvta_generic_to_global(src)));
}
__device__ __forceinline__ void cp_commit() {
    asm volatile("cp.async.commit_group;");
}
template <int NN> __device__ __forceinline__ void cp_wait() {
    asm volatile("cp.async.wait_group %0;" :: "n"(NN));
}

#define STAGE_BYTES 30720

// ---------------- bf16 mma.sync SGEMM, 128x64 tile, 2-stage, 1 bar/chunk -----
// npass: 3 = full bf16x3 split (hi*hi + lo*hi + hi*lo); 1 = hi*hi only
// (valid for non-cancelling / tolerance-bounded outputs).
__global__ __launch_bounds__(256, 3)
void bgemm(const __nv_bfloat16* __restrict__ Agh, const __nv_bfloat16* __restrict__ Agl, long ldA,
           const __nv_bfloat16* __restrict__ Bgh, const __nv_bfloat16* __restrict__ Bgl, long ldB,
           const __nv_bfloat16* __restrict__ A2gh, const __nv_bfloat16* __restrict__ A2gl,
           const __nv_bfloat16* __restrict__ B2gh, const __nv_bfloat16* __restrict__ B2gl,
           int zSecond,
           const float* __restrict__ bias,
           const float* __restrict__ Cadd, long ldAdd,
           float* __restrict__ C, long ldc, long sliceStride,
           __nv_bfloat16* __restrict__ Chi, __nv_bfloat16* __restrict__ Clo, long ldS,
           __nv_bfloat16* __restrict__ Th, __nv_bfloat16* __restrict__ Tl, long ldT,
           __nv_bfloat16* __restrict__ Tph, __nv_bfloat16* __restrict__ Tpl, long ldTp,
           float* __restrict__ rowpart, float* __restrict__ colpart,
           int reshapeRow, int npass,
           int M, int N, int K, int kPerSlice, int relu) {
    extern __shared__ __align__(16) char smraw[];
    const int tid = threadIdx.x, lane = tid & 31, wid = tid >> 5;
    const int wm = wid >> 1, wn = wid & 1;
    const int m0 = blockIdx.y * 128, n0 = blockIdx.x * 64;
    const int zz = blockIdx.z;
    if (A2gh && zz >= zSecond) { Agh = A2gh; Agl = A2gl; Bgh = B2gh; Bgl = B2gl; }
    const int kbeg = (zz % zSecond) * kPerSlice;
    const int kend = min(K, kbeg + kPerSlice);
    const int nch = (kend - kbeg) >> 5;
    C += (long)zz * sliceStride;

    const uint32_t sb = smem_u32(smraw);

    float acc[2][4][4];
    #pragma unroll
    for (int i = 0; i < 2; i++)
        #pragma unroll
        for (int j = 0; j < 4; j++)
            #pragma unroll
            for (int e = 0; e < 4; e++) acc[i][j][e] = 0.f;

    const int lrow = (((lane >> 3) & 1) << 3) + (lane & 7);
    const int lcol = (lane >> 4) << 4;

    auto load_stage = [&](int st, int k0) {
        uint32_t sbase = sb + st * STAGE_BYTES;
        #pragma unroll
        for (int i = 0; i < 2; i++) {
            int c = tid + i * 256;
            int r = c >> 2, kq = c & 3;
            uint32_t dso = (uint32_t)(r * 80 + kq * 16);
            long ao = (long)(m0 + r) * ldA + k0 + kq * 8;
            cp16(sbase + dso, Agh + ao);
            if (npass > 1) cp16(sbase + 10240 + dso, Agl + ao);
        }
        {
            int r = tid >> 2, kq = tid & 3;
            uint32_t dso = (uint32_t)(r * 80 + kq * 16);
            long bo = (long)(n0 + r) * ldB + k0 + kq * 8;
            cp16(sbase + 20480 + dso, Bgh + bo);
            if (npass > 2) cp16(sbase + 25600 + dso, Bgl + bo);
        }
    };

    load_stage(0, kbeg);
    cp_commit();

    int stage = 0;
    for (int i = 0; i < nch; i++) {
        cp_wait<0>();
        __syncthreads();
        if (i + 1 < nch) {
            load_stage(stage ^ 1, kbeg + (i + 1) * 32);
            cp_commit();
        }

        const uint32_t aAh = sb + stage * STAGE_BYTES;
        const uint32_t aAl = aAh + 10240;
        const uint32_t aBh = aAh + 20480;
        const uint32_t aBl = aAh + 25600;

        #pragma unroll
        for (int s = 0; s < 2; s++) {
            const int sbyte = s * 32;
            uint32_t ah[2][4], al[2][4], bh[2][4];
            #pragma unroll
            for (int mf = 0; mf < 2; mf++) {
                int row = wm * 32 + mf * 16 + lrow;
                ldsm4(ah[mf][0], ah[mf][1], ah[mf][2], ah[mf][3],
                      aAh + row * 80 + lcol + sbyte);
                if (npass > 1)
                    ldsm4(al[mf][0], al[mf][1], al[mf][2], al[mf][3],
                          aAl + row * 80 + lcol + sbyte);
            }
            #pragma unroll
            for (int nf = 0; nf < 2; nf++) {
                int row = wn * 32 + nf * 16 + lrow;
                ldsm4(bh[nf][0], bh[nf][1], bh[nf][2], bh[nf][3],
                      aBh + row * 80 + lcol + sbyte);
            }
            #pragma unroll
            for (int nf = 0; nf < 2; nf++)
                #pragma unroll
                for (int j = 0; j < 2; j++)
                    #pragma unroll
                    for (int mf = 0; mf < 2; mf++)
                        mma16816(acc[mf][nf * 2 + j], ah[mf], bh[nf][j], bh[nf][j + 2]);
            if (npass > 1) {
                #pragma unroll
                for (int nf = 0; nf < 2; nf++)
                    #pragma unroll
                    for (int j = 0; j < 2; j++)
                        #pragma unroll
                        for (int mf = 0; mf < 2; mf++)
                            mma16816(acc[mf][nf * 2 + j], al[mf], bh[nf][j], bh[nf][j + 2]);
            }
            if (npass > 2) {
                #pragma unroll
                for (int nf = 0; nf < 2; nf++) {
                    int row = wn * 32 + nf * 16 + lrow;
                    uint32_t bl[4];
                    ldsm4(bl[0], bl[1], bl[2], bl[3], aBl + row * 80 + lcol + sbyte);
                    #pragma unroll
                    for (int j = 0; j < 2; j++)
                        #pragma unroll
                        for (int mf = 0; mf < 2; mf++)
                            mma16816(acc[mf][nf * 2 + j], ah[mf], bl[j], bl[j + 2]);
                }
            }
        }
        stage ^= 1;
    }
    __syncthreads();

    // ---- Cadd/bias/relu in-place ----
    const int tg = lane >> 2;
    const int tn = (lane & 3) << 1;
    if (Cadd || bias || relu) {
        #pragma unroll
        for (int mf = 0; mf < 2; mf++)
            #pragma unroll
            for (int h2 = 0; h2 < 2; h2++) {
                int m = m0 + wm * 32 + mf * 16 + h2 * 8 + tg;
                #pragma unroll
                for (int nfj = 0; nfj < 4; nfj++) {
                    int n = n0 + (wn * 32 + nfj * 8 + tn);
                    float vx = acc[mf][nfj][h2 * 2 + 0];
                    float vy = acc[mf][nfj][h2 * 2 + 1];
                    if (n < N) {
                        if (Cadd) {
                            float2 adv = *(const float2*)(Cadd + (long)m * ldAdd + n);
                            vx += adv.x; vy += adv.y;
                        }
                        if (bias) { vx += bias[n]; vy += bias[n + 1]; }
                    }
                    if (relu) { vx = fmaxf(vx, 0.f); vy = fmaxf(vy, 0.f); }
                    acc[mf][nfj][h2 * 2 + 0] = vx;
                    acc[mf][nfj][h2 * 2 + 1] = vy;
                }
            }
    }

    const bool rsh = (reshapeRow >= 0);
    const bool isH = rsh && (m0 >= reshapeRow);

    if (C || Chi) {
        #pragma unroll
        for (int mf = 0; mf < 2; mf++) {
            #pragma unroll
            for (int h2 = 0; h2 < 2; h2++) {
                int m = m0 + wm * 32 + mf * 16 + h2 * 8 + tg;
                #pragma unroll
                for (int nfj = 0; nfj < 4; nfj++) {
                    int n = n0 + wn * 32 + nfj * 8 + tn;
                    if (n >= N) continue;
                    float2 v;
                    v.x = acc[mf][nfj][h2 * 2 + 0];
                    v.y = acc[mf][nfj][h2 * 2 + 1];
                    if (C) *(float2*)(C + (long)m * ldc + n) = v;
                    if (Chi) {
                        __nv_bfloat16 h0, l0, h1, l1;
                        cvt_split(v.x, h0, l0);
                        cvt_split(v.y, h1, l1);
                        long o = (long)m * ldS + n;
                        *(uint32_t*)(Chi + o) = pack_bf2(h0, h1);
                        *(uint32_t*)(Clo + o) = pack_bf2(l0, l1);
                    }
                }
            }
        }
    }

    const bool doResh = Th && rsh && isH;
    const bool doReg  = Tph && rsh && !isH;
    if (doResh || doReg || rowpart || colpart) {
        float* ts = (float*)smraw;             // [64][129]
        #pragma unroll
        for (int mf = 0; mf < 2; mf++) {
            #pragma unroll
            for (int h2 = 0; h2 < 2; h2++) {
                int ml = wm * 32 + mf * 16 + h2 * 8 + tg;
                #pragma unroll
                for (int nfj = 0; nfj < 4; nfj++) {
                    int nl = wn * 32 + nfj * 8 + tn;
                    ts[(nl + 0) * 129 + ml] = acc[mf][nfj][h2 * 2 + 0];
                    ts[(nl + 1) * 129 + ml] = acc[mf][nfj][h2 * 2 + 1];
                }
            }
        }
        __syncthreads();
        if (tid < 128 && rowpart) {
            float s = 0.f;
            #pragma unroll 8
            for (int n = 0; n < 64; n++) s += ts[n * 129 + tid];
            rowpart[(long)blockIdx.x * M + m0 + tid] = s;
        }
        if (tid < 64 && colpart) {
            float s2 = 0.f;
            #pragma unroll 8
            for (int m = 0; m < 128; m++) s2 += ts[tid * 129 + m];
            colpart[(long)blockIdx.y * N + n0 + tid] = s2;
        }
        if (doResh) {
            long kb = (long)(m0 - reshapeRow) >> 3;
            for (int idx = tid; idx < 512; idx += 256) {
                int r8 = idx >> 6, nl = idx & 63;
                long j = (long)r8 * HN + n0 + nl;
                __align__(16) __nv_bfloat16 hb[16], lb[16];
                #pragma unroll
                for (int q = 0; q < 16; q++) {
                    __nv_bfloat16 hi, lo;
                    cvt_split(ts[nl * 129 + r8 + 8 * q], hi, lo);
                    hb[q] = hi; lb[q] = lo;
                }
                long o = j * ldT + kb;
                *(uint4*)(Th + o)     = *(uint4*)(hb);
                *(uint4*)(Th + o + 8) = *(uint4*)(hb + 8);
                *(uint4*)(Tl + o)     = *(uint4*)(lb);
                *(uint4*)(Tl + o + 8) = *(uint4*)(lb + 8);
            }
        }
        if (doReg) {
            for (int idx = tid; idx < 4096; idx += 256) {
                int n = idx >> 6, m2 = (idx & 63) << 1;
                __nv_bfloat16 h0, l0, h1, l1;
                cvt_split(ts[n * 129 + m2], h0, l0);
                cvt_split(ts[n * 129 + m2 + 1], h1, l1);
                long o = (long)(n0 + n) * ldTp + m0 + m2;
                *(uint32_t*)(Tph + o) = pack_bf2(h0, h1);
                *(uint32_t*)(Tpl + o) = pack_bf2(l0, l1);
            }
        }
    }
}

static const int BGEMM_SMEM = 2 * STAGE_BYTES;

// ---------------- weight splits -----------------------------------------------
__global__ void split_weights_kernel(const float* __restrict__ Wa1, const float* __restrict__ Wa2,
                                     const float* __restrict__ Wc1, const float* __restrict__ Wc2,
                                     __nv_bfloat16* __restrict__ a1h, __nv_bfloat16* __restrict__ a1l,
                                     __nv_bfloat16* __restrict__ a2h, __nv_bfloat16* __restrict__ a2l,
                                     __nv_bfloat16* __restrict__ c1ah, __nv_bfloat16* __restrict__ c1al,
                                     __nv_bfloat16* __restrict__ c1bh, __nv_bfloat16* __restrict__ c1bl,
                                     __nv_bfloat16* __restrict__ c2h, __nv_bfloat16* __restrict__ c2l) {
    const long s1 = (long)HN * DP, s2 = (long)HN * HN;
    const long s3 = (long)HN * XK, s4 = (long)HN * XK, s5 = (long)HN * HN;
    long i = (long)blockIdx.x * blockDim.x + threadIdx.x;
    float v; __nv_bfloat16 *dh, *dl; long li;
    if (i < s1) {
        li = i; int m = (int)(li / DP), k = (int)(li % DP);
        v = (k < DN) ? Wa1[(long)m * DN + k] : 0.f; dh = a1h; dl = a1l;
    } else if (i < s1 + s2) {
        li = i - s1; int m = (int)(li / HN), k = (int)(li % HN);
        v = Wa2[(long)m * HN + k]; dh = a2h; dl = a2l;
    } else if (i < s1 + s2 + s3) {
        li = i - s1 - s2; int m = (int)(li / XK), k = (int)(li % XK);
        v = (k < DN) ? Wc1[(long)m * (2 * DN) + k] : 0.f; dh = c1ah; dl = c1al;
    } else if (i < s1 + s2 + s3 + s4) {
        li = i - s1 - s2 - s3; int m = (int)(li / XK), k = (int)(li % XK);
        v = (k < DN) ? Wc1[(long)m * (2 * DN) + DN + k] : 0.f; dh = c1bh; dl = c1bl;
    } else if (i < s1 + s2 + s3 + s4 + s5) {
        li = i - s1 - s2 - s3 - s4; int m = (int)(li / HN), k = (int)(li % HN);
        v = Wc2[(long)m * HN + k]; dh = c2h; dl = c2l;
    } else return;
    __nv_bfloat16 hi, lo;
    cvt_split(v, hi, lo);
    dh[li] = hi; dl[li] = lo;
}

// ---------------- fused gather + split-pad + xb pad zero ----------------------
__global__ void gather_split_kernel(const float* __restrict__ emb,
                                    const int* __restrict__ p_idx,
                                    const int* __restrict__ h_idx,
                                    __nv_bfloat16* __restrict__ e_h,
                                    __nv_bfloat16* __restrict__ e_l,
                                    __nv_bfloat16* __restrict__ xb_h,
                                    __nv_bfloat16* __restrict__ xb_l) {
    int r = blockIdx.x;
    long src = (r < LPN) ? p_idx[r] : h_idx[r - LPN];
    const float* s = emb + src * (long)DN;
    for (int c = threadIdx.x; c < DP; c += blockDim.x) {
        float v = (c < DN) ? s[c] : 0.f;
        __nv_bfloat16 hi, lo;
        cvt_split(v, hi, lo);
        long eo = (long)r * DP + c;
        e_h[eo] = hi; e_l[eo] = lo;
    }
    for (int c = DN + threadIdx.x; c < XK; c += blockDim.x) {
        long xo = (long)r * XK + c;
        xb_h[xo] = __float2bfloat16(0.f);
        xb_l[xo] = __float2bfloat16(0.f);
    }
}

// ---------------- gathered transpose + split -----------------------------------
__global__ void gtranspose_split2_kernel(const float* __restrict__ emb,
                                         const int* __restrict__ p_idx,
                                         __nv_bfloat16* __restrict__ dhA, __nv_bfloat16* __restrict__ dlA,
                                         const int* __restrict__ h_idx,
                                         __nv_bfloat16* __restrict__ dhB, __nv_bfloat16* __restrict__ dlB,
                                         int R, int C, int dR) {
    const int* idx = blockIdx.z ? h_idx : p_idx;
    __nv_bfloat16* dh = blockIdx.z ? dhB : dhA;
    __nv_bfloat16* dl = blockIdx.z ? dlB : dlA;
    __shared__ float tile[32][33];
    int c0 = blockIdx.x * 32, r0 = blockIdx.y * 32;
    int x = threadIdx.x, y = threadIdx.y;
    #pragma unroll
    for (int i = y; i < 32; i += 8) {
        int r = r0 + i, c = c0 + x;
        tile[i][x] = (r < R && c < C) ? emb[(long)idx[r] * DN + c] : 0.f;
    }
    __syncthreads();
    #pragma unroll
    for (int i = y; i < 32; i += 8) {
        int dr = c0 + i, dc = r0 + x;
        if (dr < dR && dc < R) {
            __nv_bfloat16 hi, lo;
            cvt_split(tile[x][i], hi, lo);
            dh[(long)dr * R + dc] = hi;
            dl[(long)dr * R + dc] = lo;
        }
    }
}

// ---------------- W slice reduce + split ----------------------------------------
__global__ void wreduce_kernel(const float* __restrict__ slices,
                               __nv_bfloat16* __restrict__ w1h, __nv_bfloat16* __restrict__ w1l,
                               __nv_bfloat16* __restrict__ w2h, __nv_bfloat16* __restrict__ w2l) {
    int i = blockIdx.x * blockDim.x + threadIdx.x;
    if (i >= WELEMS) return;
    int which = blockIdx.y;
    const float* base = slices + (long)which * 8 * WELEMS + i;
    float s = 0.f;
    #pragma unroll
    for (int p = 0; p < 8; p++) s += base[(long)p * WELEMS];
    __nv_bfloat16 hi, lo;
    cvt_split(s, hi, lo);
    if (which) { w2h[i] = hi; w2l[i] = lo; }
    else       { w1h[i] = hi; w1l[i] = lo; }
}

// ---------------- rs / fpcol from attend2 partials ------------------------------
__global__ void rs_fpcol_kernel(const float* __restrict__ rowpart,
                                const float* __restrict__ colpart,
                                float* __restrict__ rs, float* __restrict__ fpcol) {
    int t = blockIdx.x * blockDim.x + threadIdx.x;
    if (t < HN) {
        float s = 0.f;
        #pragma unroll
        for (int bx = 0; bx < 8; bx++)
            #pragma unroll
            for (int r = 0; r < 8; r++)
                s += rowpart[(long)bx * M2 + LPN + 8 * t + r];
        rs[t] = s;
    } else if (t < 2 * HN) {
        int n = t - HN;
        float s = 0.f;
        #pragma unroll
        for (int by = 0; by < 32; by++) s += colpart[(long)by * HN + n];
        fpcol[n] = s;
    }
}

// ---------------- GEMV: out[i] = sum_k (Ah+Al)[i,k] * v[k] ---------------------
__global__ void gemv_rows_kernel(const __nv_bfloat16* __restrict__ Ah,
                                 const __nv_bfloat16* __restrict__ Al,
                                 const float* __restrict__ v,
                                 float* __restrict__ outv, int M) {
    int row = blockIdx.x * 8 + (threadIdx.x >> 5);
    int lane = threadIdx.x & 31;
    if (row >= M) return;
    const __nv_bfloat16* ah = Ah + (long)row * HN;
    const __nv_bfloat16* al = Al + (long)row * HN;
    float s = 0.f;
    for (int k = lane; k < HN; k += 32)
        s += (__bfloat162float(ah[k]) + __bfloat162float(al[k])) * v[k];
    #pragma unroll
    for (int o = 16; o > 0; o >>= 1) s += __shfl_down_sync(0xffffffff, s, o);
    if (lane == 0) outv[row] = s;
}

// ---------------- rowdiv + fused concat into xb (dual) --------------------------
__global__ void splitk_concat2_kernel(const float* __restrict__ partA, const float* __restrict__ rdA,
                                      float* __restrict__ CA,
                                      const float* __restrict__ partB, const float* __restrict__ rdB,
                                      float* __restrict__ CB,
                                      __nv_bfloat16* __restrict__ xbh, __nv_bfloat16* __restrict__ xbl,
                                      int M, int N, int S) {
    const float* part = blockIdx.y ? partB : partA;
    const float* rowdiv = blockIdx.y ? rdB : rdA;
    float* C = blockIdx.y ? CB : CA;
    long xRowOff = blockIdx.y ? (long)M : 0;
    long i = (long)blockIdx.x * blockDim.x + threadIdx.x;
    long total = (long)M * N;
    if (i >= total) return;
    int m = (int)(i / N), n = (int)(i % N);
    float s = 0.f;
    for (int p = 0; p < S; p++) s += part[(long)p * total + i];
    float v = s / rowdiv[m];
    C[(long)m * N + n] = v;
    __nv_bfloat16 hi, lo;
    cvt_split(v, hi, lo);
    long o = (xRowOff + m) * (long)XK + n;
    xbh[o] = hi; xbl[o] = lo;
}

// ---------------- dual column reduce --------------------------------------------
__global__ void colsum_reduce2_kernel(const float* __restrict__ partA, float* __restrict__ outA, int PA,
                                      const float* __restrict__ partB, float* __restrict__ outB, int PB,
                                      int C) {
    const float* part = blockIdx.y ? partB : partA;
    float* out = blockIdx.y ? outB : outA;
    int P = blockIdx.y ? PB : PA;
    int c = blockIdx.x * blockDim.x + threadIdx.x;
    if (c >= C) return;
    float s = 0.f;
    for (int p = 0; p < P; p++) s += part[(long)p * C + c];
    out[c] = s;
}

// ---------------- final head -----------------------------------------------------
__global__ void head_kernel(const float* __restrict__ v,
                            const float* __restrict__ Wg1, const float* __restrict__ bg1,
                            const float* __restrict__ Wg2, const float* __restrict__ bg2,
                            const float* __restrict__ Wg3, const float* __restrict__ bg3,
                            float* __restrict__ y) {
    __shared__ float sv[2 * HN];
    __shared__ float y1[HN];
    __shared__ float y2[HN];
    __shared__ float logit[3];
    int t = threadIdx.x;
    sv[t] = v[t];
    sv[t + HN] = v[t + HN];
    __syncthreads();
    {
        float acc = bg1[t];
        const float* w = Wg1 + (long)t * (2 * HN);
        for (int k = 0; k < 2 * HN; k++) acc += sv[k] * w[k];
        y1[t] = fmaxf(acc, 0.f);
    }
    __syncthreads();
    {
        float acc = bg2[t];
        const float* w = Wg2 + (long)t * HN;
        for (int k = 0; k < HN; k++) acc += y1[k] * w[k];
        y2[t] = fmaxf(acc, 0.f);
    }
    __syncthreads();
    if (t < 3) {
        float a = bg3[t];
        const float* w = Wg3 + (long)t * HN;
        for (int k = 0; k < HN; k++) a += y2[k] * w[k];
        logit[t] = a;
    }
    __syncthreads();
    if (t == 0) {
        float m = fmaxf(logit[0], fmaxf(logit[1], logit[2]));
        float e0 = expf(logit[0] - m), e1 = expf(logit[1] - m), e2 = expf(logit[2] - m);
        float s = e0 + e1 + e2;
        y[0] = e0 / s; y[1] = e1 / s; y[2] = e2 / s;
    }
}

// ---------------- host dispatch ---------------------------------------------------
struct BArgs {
    const __nv_bfloat16 *Ah, *Al; long ldA;
    const __nv_bfloat16 *Bh, *Bl; long ldB;
    const __nv_bfloat16 *A2h = nullptr, *A2l = nullptr, *B2h = nullptr, *B2l = nullptr;
    const float* bias = nullptr;
    const float* Cadd = nullptr; long ldAdd = 0;
    float* C = nullptr; long ldc = 0; long sliceStride = 0;
    __nv_bfloat16 *Chi = nullptr, *Clo = nullptr; long ldS = 0;
    __nv_bfloat16 *Th = nullptr, *Tl = nullptr; long ldT = 0;
    __nv_bfloat16 *Tph = nullptr, *Tpl = nullptr; long ldTp = 0;
    float *rowpart = nullptr, *colpart = nullptr;
    int reshapeRow = -1;
    int npass = 3;
    int M, N, K, splits = 1, zTotal = 0, relu = 0;
};

static void launch_bgemm(const BArgs& a, cudaStream_t st) {
    cudaFuncSetAttribute(bgemm, cudaFuncAttributeMaxDynamicSharedMemorySize, BGEMM_SMEM);
    int kps = (a.K + a.splits - 1) / a.splits;
    kps = ((kps + 31) / 32) * 32;
    int zt = a.zTotal ? a.zTotal : a.splits;
    dim3 grid((a.N + 63) / 64, a.M / 128, zt);
    bgemm<<<grid, 256, BGEMM_SMEM, st>>>(a.Ah, a.Al, a.ldA, a.Bh, a.Bl, a.ldB,
                                         a.A2h, a.A2l, a.B2h, a.B2l, a.splits,
                                         a.bias, a.Cadd, a.ldAdd,
                                         a.C, a.ldc, a.sliceStride,
                                         a.Chi, a.Clo, a.ldS,
                                         a.Th, a.Tl, a.ldT,
                                         a.Tph, a.Tpl, a.ldTp,
                                         a.rowpart, a.colpart, a.reshapeRow, a.npass,
                                         a.M, a.N, a.K, kps, a.relu);
}

#define GETSYM(var, sym) cudaGetSymbolAddress((void**)&var, sym)

extern "C" void kernel_launch(void* const* d_in, const int* in_sizes, int n_in,
                              void* d_out, int out_size) {
    static cudaStream_t s2 = nullptr;
    static cudaEvent_t evGather = nullptr, evFork = nullptr, evJoin = nullptr;
    if (!s2) {
        cudaStreamCreateWithFlags(&s2, cudaStreamNonBlocking);
        cudaEventCreateWithFlags(&evGather, cudaEventDisableTiming);
        cudaEventCreateWithFlags(&evFork, cudaEventDisableTiming);
        cudaEventCreateWithFlags(&evJoin, cudaEventDisableTiming);
    }

    const int*   p_idx = (const int*)  d_in[0];
    const int*   h_idx = (const int*)  d_in[1];
    const float* emb   = (const float*)d_in[2];
    const float* W_a1  = (const float*)d_in[3];
    const float* b_a1  = (const float*)d_in[4];
    const float* W_a2  = (const float*)d_in[5];
    const float* b_a2  = (const float*)d_in[6];
    const float* W_c1  = (const float*)d_in[7];
    const float* b_c1  = (const float*)d_in[8];
    const float* W_c2  = (const float*)d_in[9];
    const float* b_c2  = (const float*)d_in[10];
    const float* W_g1  = (const float*)d_in[11];
    const float* b_g1  = (const float*)d_in[12];
    const float* W_g2  = (const float*)d_in[13];
    const float* b_g2  = (const float*)d_in[14];
    const float* W_g3  = (const float*)d_in[15];
    const float* b_g3  = (const float*)d_in[16];

    float* out = (float*)d_out;
    const long E_OFF    = 0;
    const long BETA_OFF = (long)LPN * LHN;
    const long ALPHA_OFF= BETA_OFF + (long)LPN * DN;
    const long V1_OFF   = ALPHA_OFF + (long)LHN * DN;
    const long V2_OFF   = V1_OFF + HN;
    const long Y_OFF    = V2_OFF + HN;

    float *eik, *ekj, *rs, *fpcol, *part, *part2, *split, *csl;
    GETSYM(eik, g_eik); GETSYM(ekj, g_ekj);
    GETSYM(rs, g_rs);   GETSYM(fpcol, g_fpcol);
    GETSYM(part, g_part); GETSYM(part2, g_part2); GETSYM(split, g_split);
    GETSYM(csl, g_csl);

    __nv_bfloat16 *emb2s_h, *emb2s_l, *xb_h, *xb_l, *ths_h, *ths_l, *fs_h, *fs_l;
    __nv_bfloat16 *fpTs_h, *fpTs_l, *fhTs_h, *fhTs_l;
    __nv_bfloat16 *hTs_h, *hTs_l, *pTs_h, *pTs_l;
    __nv_bfloat16 *W1Ts_h, *W1Ts_l, *W2Ts_h, *W2Ts_l;
    __nv_bfloat16 *Wa1s_h, *Wa1s_l, *Wa2s_h, *Wa2s_l;
    __nv_bfloat16 *Wc1a_h, *Wc1a_l, *Wc1b_h, *Wc1b_l, *Wc2s_h, *Wc2s_l;
    GETSYM(emb2s_h, g_emb2s_h); GETSYM(emb2s_l, g_emb2s_l);
    GETSYM(xb_h, g_xb_h);       GETSYM(xb_l, g_xb_l);
    GETSYM(ths_h, g_ths_h);     GETSYM(ths_l, g_ths_l);
    GETSYM(fs_h, g_fs_h);       GETSYM(fs_l, g_fs_l);
    GETSYM(fpTs_h, g_fpTs_h);   GETSYM(fpTs_l, g_fpTs_l);
    GETSYM(fhTs_h, g_fhTs_h);   GETSYM(fhTs_l, g_fhTs_l);
    GETSYM(hTs_h, g_hTs_h);     GETSYM(hTs_l, g_hTs_l);
    GETSYM(pTs_h, g_pTs_h);     GETSYM(pTs_l, g_pTs_l);
    GETSYM(W1Ts_h, g_W1Ts_h);   GETSYM(W1Ts_l, g_W1Ts_l);
    GETSYM(W2Ts_h, g_W2Ts_h);   GETSYM(W2Ts_l, g_W2Ts_l);
    GETSYM(Wa1s_h, g_Wa1s_h);   GETSYM(Wa1s_l, g_Wa1s_l);
    GETSYM(Wa2s_h, g_Wa2s_h);   GETSYM(Wa2s_l, g_Wa2s_l);
    GETSYM(Wc1a_h, g_Wc1a_h);   GETSYM(Wc1a_l, g_Wc1a_l);
    GETSYM(Wc1b_h, g_Wc1b_h);   GETSYM(Wc1b_l, g_Wc1b_l);
    GETSYM(Wc2s_h, g_Wc2s_h);   GETSYM(Wc2s_l, g_Wc2s_l);

    // 0) weight splits + gather + embedding transposes
    {
        long total = (long)HN * (DP + HN + XK + XK + HN);
        split_weights_kernel<<<(int)((total + 255) / 256), 256>>>(
            W_a1, W_a2, W_c1, W_c2,
            Wa1s_h, Wa1s_l, Wa2s_h, Wa2s_l,
            Wc1a_h, Wc1a_l, Wc1b_h, Wc1b_l, Wc2s_h, Wc2s_l);
    }
    gather_split_kernel<<<M2, 128>>>(emb, p_idx, h_idx, emb2s_h, emb2s_l, xb_h, xb_l);
    {
        dim3 b(32, 8);
        dim3 g((NROWS_PAD + 31) / 32, (LPN + 31) / 32, 2);
        gtranspose_split2_kernel<<<g, b>>>(emb, p_idx, pTs_h, pTs_l,
                                           h_idx, hTs_h, hTs_l, LPN, DN, NROWS_PAD);
    }
    cudaEventRecord(evGather, 0);
    cudaStreamWaitEvent(s2, evGather, 0);

    // [s2] comp1 emb-half
    {
        BArgs a{emb2s_h, emb2s_l, DP, Wc1a_h, Wc1a_l, XK};
        a.C = csl; a.ldc = HN;
        a.M = M2; a.N = HN; a.K = XK;
        launch_bgemm(a, s2);
    }

    // 1) attend1
    {
        BArgs a{emb2s_h, emb2s_l, DP, Wa1s_h, Wa1s_l, DP};
        a.bias = b_a1; a.Chi = ths_h; a.Clo = ths_l; a.ldS = HN;
        a.M = M2; a.N = HN; a.K = DP; a.relu = 1;
        launch_bgemm(a, 0);
    }
    // 2) attend2: splits + transposes + row/col partials
    {
        BArgs a{ths_h, ths_l, HN, Wa2s_h, Wa2s_l, HN};
        a.bias = b_a2;
        a.Chi = fs_h; a.Clo = fs_l; a.ldS = HN;
        a.Th = fhTs_h; a.Tl = fhTs_l; a.ldT = HN;
        a.Tph = fpTs_h; a.Tpl = fpTs_l; a.ldTp = LPN;
        a.rowpart = part; a.colpart = part2;
        a.reshapeRow = LPN;
        a.M = M2; a.N = HN; a.K = HN; a.relu = 1;
        launch_bgemm(a, 0);
    }

    // ---- FORK ----
    cudaEventRecord(evFork, 0);
    cudaStreamWaitEvent(s2, evFork, 0);

    // [s2] W1T / W2T (dual, split-K x8)
    {
        BArgs a{hTs_h, hTs_l, LHN, fs_h + (long)LPN * HN, fs_l + (long)LPN * HN, LHN};
        a.A2h = pTs_h; a.A2l = pTs_l; a.B2h = fpTs_h; a.B2l = fpTs_l;
        a.C = split; a.ldc = HN; a.sliceStride = WELEMS;
        a.M = WROWS; a.N = HN; a.K = LHN; a.splits = 8; a.zTotal = 16;
        launch_bgemm(a, s2);
    }
    {
        dim3 g((WELEMS + 255) / 256, 2);
        wreduce_kernel<<<g, 256, 0, s2>>>(split, W1Ts_h, W1Ts_l, W2Ts_h, W2Ts_l);
    }
    rs_fpcol_kernel<<<(2 * HN + 255) / 256, 256, 0, s2>>>(part, part2, rs, fpcol);
    gemv_rows_kernel<<<LPN / 8, 256, 0, s2>>>(fs_h, fs_l, rs, eik, LPN);
    gemv_rows_kernel<<<LHN / 8, 256, 0, s2>>>(fhTs_h, fhTs_l, fpcol, ekj, LHN);
    float* baRaw = split + 16L * WELEMS;
    {
        BArgs a{fs_h, fs_l, HN, W1Ts_h, W1Ts_l, HN};
        a.A2h = fhTs_h; a.A2l = fhTs_l; a.B2h = W2Ts_h; a.B2l = W2Ts_l;
        a.C = baRaw; a.ldc = DN; a.sliceStride = (long)LPN * DN;
        a.M = LPN; a.N = DN; a.K = HN; a.splits = 1; a.zTotal = 2;
        launch_bgemm(a, s2);
    }
    cudaEventRecord(evJoin, s2);

    // 3) [main] E = fp @ fhR — single-pass hi*hi (no cancellation; output-only)
    {
        BArgs a{fs_h, fs_l, HN, fhTs_h, fhTs_l, HN};
        a.C = out + E_OFF; a.ldc = LHN;
        a.npass = 1;
        a.M = LPN; a.N = LHN; a.K = HN;
        launch_bgemm(a, 0);
    }

    // ---- JOIN ----
    cudaStreamWaitEvent(0, evJoin, 0);

    // 4) divide + concat into xb
    {
        dim3 g((int)(((long)LPN * DN + 255) / 256), 2);
        splitk_concat2_kernel<<<g, 256>>>(baRaw, eik, out + BETA_OFF,
                                          baRaw + (long)LPN * DN, ekj, out + ALPHA_OFF,
                                          xb_h, xb_l, LPN, DN, 1);
    }

    // 5) comp1 beta-half (fused add), comp2 with colsums
    {
        BArgs a{xb_h, xb_l, XK, Wc1b_h, Wc1b_l, XK};
        a.bias = b_c1; a.Cadd = csl; a.ldAdd = HN;
        a.Chi = ths_h; a.Clo = ths_l; a.ldS = HN;
        a.M = M2; a.N = HN; a.K = XK; a.relu = 1;
        launch_bgemm(a, 0);
    }
    {
        BArgs a{ths_h, ths_l, HN, Wc2s_h, Wc2s_l, HN};
        a.bias = b_c2; a.colpart = part;
        a.M = M2; a.N = HN; a.K = HN; a.relu = 1;
        launch_bgemm(a, 0);
    }
    {
        dim3 g((HN + 255) / 256, 2);
        colsum_reduce2_kernel<<<g, 256>>>(part, out + V1_OFF, 32,
                                          part + 32 * HN, out + V2_OFF, 32, HN);
    }

    // 6) head
    head_kernel<<<1, HN>>>(out + V1_OFF, W_g1, b_g1, W_g2, b_g2, W_g3, b_g3, out + Y_OFF);

    (void)in_sizes; (void)n_in; (void)out_size;
}